// round 2
// baseline (speedup 1.0000x reference)
#include <cuda_runtime.h>
#include <math.h>

// ---------------------------------------------------------------------------
// Problem constants
//   B=4096, S=128, A=32, H=1024, N=256, beta=1, norm_smoothing=0.01, max_a=1
// Pipeline:
//   t1 = relu(s@Wv1+bv1); t2 = relu(t1@Wv2+bv2); t3 = relu(t2@Wv3+bv3)
//   values = t3@Wv4+bv4                       [B,256]
//   h  = relu(s@Wl1+bl1)                      [B,1024]
//   Z[b, n*32+a] = h@WexpT + bexp  -> cent=tanh(Z)
//   dist[b,n] = sqrt(sum_a (cent-a)^2 + 0.01) [B,256]   (fused in expert GEMM)
//   out[b] = softmax_n(-dist) . values        [B,1]
//
// NOTE: no host-side CUDA runtime calls besides kernel launches. Scratch
// buffers are __device__ globals selected DEVICE-SIDE by integer id, so we
// never need cudaGetSymbolAddress (which triggered "system not yet
// initialized" under the harness interposer in round 1).
// ---------------------------------------------------------------------------

#define BM 128
#define BN 128
#define BK 16

// Scratch (allocation-free rule: __device__ globals)
__device__ float g_buf0[4096 * 1024];
__device__ float g_buf1[4096 * 1024];
__device__ float g_values[4096 * 256];
__device__ float g_dist[4096 * 256];

__device__ __forceinline__ float* scratch_ptr(int id) {
    switch (id) {
        case 0:  return g_buf0;
        case 1:  return g_buf1;
        case 2:  return g_values;
        default: return g_dist;
    }
}

// ---------------------------------------------------------------------------
// Generic fp32 GEMM: C[M,N] = epi(A[M,K] @ B[K,N] + bias[N])
// A comes from a_ext (if non-null) else scratch id; C goes to c_ext or scratch.
// 256 threads, 128x128 tile, 8x8 microtile in split-tile layout.
// ---------------------------------------------------------------------------
template <bool RELU>
__global__ __launch_bounds__(256, 2) void gemm_kernel(
    const float* __restrict__ a_ext, int a_id,
    const float* __restrict__ B,
    const float* __restrict__ bias,
    int c_id,
    int M, int N, int K)
{
    const float* A = a_ext ? a_ext : scratch_ptr(a_id);
    float* C = scratch_ptr(c_id);

    __shared__ float As[BK][BM + 4];
    __shared__ float Bs[BK][BN + 4];

    const int tid = threadIdx.x;
    const int tx = tid & 15;
    const int ty = tid >> 4;
    const int m0 = blockIdx.y * BM;
    const int n0 = blockIdx.x * BN;

    float acc[8][8];
#pragma unroll
    for (int i = 0; i < 8; i++)
#pragma unroll
        for (int j = 0; j < 8; j++) acc[i][j] = 0.f;

    const int aRow = tid >> 2;         // 0..63 (+64)
    const int aCol = (tid & 3) * 4;    // 0,4,8,12
    const int bRow = tid >> 5;         // 0..7 (+8)
    const int bCol = (tid & 31) * 4;   // 0..124

    for (int k0 = 0; k0 < K; k0 += BK) {
#pragma unroll
        for (int r = 0; r < 2; r++) {
            int m = aRow + r * 64;
            float4 v = *(const float4*)(A + (size_t)(m0 + m) * K + k0 + aCol);
            As[aCol + 0][m] = v.x;
            As[aCol + 1][m] = v.y;
            As[aCol + 2][m] = v.z;
            As[aCol + 3][m] = v.w;
        }
#pragma unroll
        for (int r = 0; r < 2; r++) {
            int k = bRow + r * 8;
            float4 v = *(const float4*)(B + (size_t)(k0 + k) * N + n0 + bCol);
            *(float4*)&Bs[k][bCol] = v;
        }
        __syncthreads();

#pragma unroll
        for (int kk = 0; kk < BK; kk++) {
            float af[8], bf[8];
            *(float4*)&af[0] = *(const float4*)&As[kk][ty * 4];
            *(float4*)&af[4] = *(const float4*)&As[kk][64 + ty * 4];
            *(float4*)&bf[0] = *(const float4*)&Bs[kk][tx * 4];
            *(float4*)&bf[4] = *(const float4*)&Bs[kk][64 + tx * 4];
#pragma unroll
            for (int i = 0; i < 8; i++)
#pragma unroll
                for (int j = 0; j < 8; j++)
                    acc[i][j] += af[i] * bf[j];
        }
        __syncthreads();
    }

    // Epilogue: bias (+ optional relu), vectorized stores
#pragma unroll
    for (int ii = 0; ii < 2; ii++) {
#pragma unroll
        for (int i = 0; i < 4; i++) {
            int m = m0 + ii * 64 + ty * 4 + i;
            int ar = ii * 4 + i;
#pragma unroll
            for (int jg = 0; jg < 2; jg++) {
                int n = n0 + jg * 64 + tx * 4;
                float4 o;
                o.x = acc[ar][jg * 4 + 0] + bias[n + 0];
                o.y = acc[ar][jg * 4 + 1] + bias[n + 1];
                o.z = acc[ar][jg * 4 + 2] + bias[n + 2];
                o.w = acc[ar][jg * 4 + 3] + bias[n + 3];
                if (RELU) {
                    o.x = fmaxf(o.x, 0.f);
                    o.y = fmaxf(o.y, 0.f);
                    o.z = fmaxf(o.z, 0.f);
                    o.w = fmaxf(o.w, 0.f);
                }
                *(float4*)(C + (size_t)m * N + n) = o;
            }
        }
    }
}

// ---------------------------------------------------------------------------
// Expert GEMM fused with tanh + squared-distance + per-n reduction.
//   Logical: Z[b, j] = h[b,:] @ WexpT[:, j] + bexp[j],  j = n*32 + a
//   WexpT[k, j] = Wexp[n*H*A + k*A + a]   (coalesced: 32 consecutive a per n)
//   dist[b,n] = sqrt( sum_{a=0..31} (tanh(Z) - act[b,a])^2 + 0.01 )
// Hm comes from scratch id 1; dist written to scratch id 3.
// ---------------------------------------------------------------------------
__global__ __launch_bounds__(256, 2) void expert_kernel(
    const float* __restrict__ Wexp,  // [256,1024,32]
    const float* __restrict__ bexp,  // [256,32] == [8192]
    const float* __restrict__ act)   // [4096,32]
{
    const int K = 1024;
    const float* Hm = scratch_ptr(1);   // [4096,1024]
    float* dist = scratch_ptr(3);       // [4096,256]

    __shared__ float As[BK][BM + 4];
    __shared__ float Bs[BK][BN + 4];

    const int tid = threadIdx.x;
    const int tx = tid & 15;
    const int ty = tid >> 4;
    const int m0 = blockIdx.y * BM;
    const int j0 = blockIdx.x * BN;  // 128 cols = 4 centroids

    float acc[8][8];
#pragma unroll
    for (int i = 0; i < 8; i++)
#pragma unroll
        for (int j = 0; j < 8; j++) acc[i][j] = 0.f;

    const int aRow = tid >> 2;
    const int aCol = (tid & 3) * 4;
    const int bRow = tid >> 5;
    const int bCol = (tid & 31) * 4;

    for (int k0 = 0; k0 < K; k0 += BK) {
#pragma unroll
        for (int r = 0; r < 2; r++) {
            int m = aRow + r * 64;
            float4 v = *(const float4*)(Hm + (size_t)(m0 + m) * K + k0 + aCol);
            As[aCol + 0][m] = v.x;
            As[aCol + 1][m] = v.y;
            As[aCol + 2][m] = v.z;
            As[aCol + 3][m] = v.w;
        }
#pragma unroll
        for (int r = 0; r < 2; r++) {
            int k = bRow + r * 8;
            int j = j0 + bCol;
            int n = j >> 5;
            int ai = j & 31;  // multiple of 4, 4 consecutive a in same n
            float4 v = *(const float4*)(Wexp + ((size_t)n * K + (k0 + k)) * 32 + ai);
            *(float4*)&Bs[k][bCol] = v;
        }
        __syncthreads();

#pragma unroll
        for (int kk = 0; kk < BK; kk++) {
            float af[8], bf[8];
            *(float4*)&af[0] = *(const float4*)&As[kk][ty * 4];
            *(float4*)&af[4] = *(const float4*)&As[kk][64 + ty * 4];
            *(float4*)&bf[0] = *(const float4*)&Bs[kk][tx * 4];
            *(float4*)&bf[4] = *(const float4*)&Bs[kk][64 + tx * 4];
#pragma unroll
            for (int i = 0; i < 8; i++)
#pragma unroll
                for (int j = 0; j < 8; j++)
                    acc[i][j] += af[i] * bf[j];
        }
        __syncthreads();
    }

    // Fused epilogue: tanh, subtract action, square, reduce 32 a-dims
    // per (row, n) across the 8 lanes that share (ty, tx>>3).
    const int aBase = (tx & 7) * 4;  // this thread's a-offset (same for both jg)
#pragma unroll
    for (int ii = 0; ii < 2; ii++) {
#pragma unroll
        for (int i = 0; i < 4; i++) {
            int m = m0 + ii * 64 + ty * 4 + i;
            int ar = ii * 4 + i;
#pragma unroll
            for (int jg = 0; jg < 2; jg++) {
                float ssum = 0.f;
#pragma unroll
                for (int jj = 0; jj < 4; jj++) {
                    int jl = jg * 64 + tx * 4 + jj;
                    float c = tanhf(acc[ar][jg * 4 + jj] + bexp[j0 + jl]);
                    float d = c - act[(size_t)m * 32 + aBase + jj];
                    ssum += d * d;
                }
                // 8-lane xor reduction (lanes share same n and row set)
                ssum += __shfl_xor_sync(0xffffffffu, ssum, 1);
                ssum += __shfl_xor_sync(0xffffffffu, ssum, 2);
                ssum += __shfl_xor_sync(0xffffffffu, ssum, 4);
                if ((tx & 7) == 0) {
                    int n = (j0 >> 5) + jg * 2 + (tx >> 3);
                    dist[(size_t)m * 256 + n] = sqrtf(ssum + 0.01f);
                }
            }
        }
    }
}

// ---------------------------------------------------------------------------
// Finalize: per batch row, softmax over -dist (beta=1) and weighted sum.
// One block of 256 threads per row; fixed-order reductions (deterministic).
// ---------------------------------------------------------------------------
__global__ void finalize_kernel(float* __restrict__ out)
{
    const float* dist = scratch_ptr(3);
    const float* values = scratch_ptr(2);

    const int b = blockIdx.x;
    const int n = threadIdx.x;  // 0..255
    const int lane = n & 31, w = n >> 5;

    float logit = -dist[(size_t)b * 256 + n];
    float v = values[(size_t)b * 256 + n];

    __shared__ float smax[8], s_e[8], s_ev[8];

    float mx = logit;
#pragma unroll
    for (int off = 16; off; off >>= 1)
        mx = fmaxf(mx, __shfl_xor_sync(0xffffffffu, mx, off));
    if (lane == 0) smax[w] = mx;
    __syncthreads();
    float bm = smax[0];
#pragma unroll
    for (int i = 1; i < 8; i++) bm = fmaxf(bm, smax[i]);

    float e = expf(logit - bm);
    float se = e, sev = e * v;
#pragma unroll
    for (int off = 16; off; off >>= 1) {
        se += __shfl_xor_sync(0xffffffffu, se, off);
        sev += __shfl_xor_sync(0xffffffffu, sev, off);
    }
    if (lane == 0) { s_e[w] = se; s_ev[w] = sev; }
    __syncthreads();
    if (n == 0) {
        float te = 0.f, tev = 0.f;
#pragma unroll
        for (int i = 0; i < 8; i++) { te += s_e[i]; tev += s_ev[i]; }
        out[b] = tev / te;
    }
}

// ---------------------------------------------------------------------------
// Launch — kernel launches ONLY (graph-capture safe, no other runtime APIs)
// ---------------------------------------------------------------------------
extern "C" void kernel_launch(void* const* d_in, const int* in_sizes, int n_in,
                              void* d_out, int out_size)
{
    const float* s    = (const float*)d_in[0];
    const float* act  = (const float*)d_in[1];
    const float* Wv1  = (const float*)d_in[2];
    const float* bv1  = (const float*)d_in[3];
    const float* Wv2  = (const float*)d_in[4];
    const float* bv2  = (const float*)d_in[5];
    const float* Wv3  = (const float*)d_in[6];
    const float* bv3  = (const float*)d_in[7];
    const float* Wv4  = (const float*)d_in[8];
    const float* bv4  = (const float*)d_in[9];
    const float* Wl1  = (const float*)d_in[10];
    const float* bl1  = (const float*)d_in[11];
    const float* Wexp = (const float*)d_in[12];
    const float* bexp = (const float*)d_in[13];
    float* out = (float*)d_out;

    dim3 blk(256);

    // Value MLP: s -> buf0 -> buf1 -> buf0 -> values(id2)
    gemm_kernel<true ><<<dim3(1024 / BN, 4096 / BM), blk>>>(s,       -1, Wv1, bv1, 0, 4096, 1024, 128);
    gemm_kernel<true ><<<dim3(1024 / BN, 4096 / BM), blk>>>(nullptr,  0, Wv2, bv2, 1, 4096, 1024, 1024);
    gemm_kernel<true ><<<dim3(1024 / BN, 4096 / BM), blk>>>(nullptr,  1, Wv3, bv3, 0, 4096, 1024, 1024);
    gemm_kernel<false><<<dim3(256  / BN, 4096 / BM), blk>>>(nullptr,  0, Wv4, bv4, 2, 4096, 256, 1024);

    // Location hidden: s -> buf1
    gemm_kernel<true ><<<dim3(1024 / BN, 4096 / BM), blk>>>(s, -1, Wl1, bl1, 1, 4096, 1024, 128);

    // Expert GEMM fused with tanh + RBF distance: buf1 -> dist(id3)
    expert_kernel<<<dim3(8192 / BN, 4096 / BM), blk>>>(Wexp, bexp, act);

    // Softmax + weighted sum
    finalize_kernel<<<4096, 256>>>(out);
}

// round 4
// speedup vs baseline: 2.3757x; 2.3757x over previous
#include <cuda_runtime.h>
#include <cuda_fp16.h>
#include <math.h>
#include <stdint.h>

// ===========================================================================
// B=4096, S=128, A=32, H=1024, N=256.
// Legacy tensor-core path (base PTX, works under compute_103):
//   ldmatrix + mma.sync.m16n8k16.row.col.f32.f16.f16.f32 + cp.async
// fp16 hi/lo 3-term split:  D = Ah*Bh + Ah*Bl + Al*Bh  (fp32 accum, ~2^-22)
// CTA 128x128, 8 warps (2x4), warp tile 64x32, K-chunk 64, double buffer.
// ===========================================================================

#define SWZ(o) ((o) ^ (((o) >> 3) & 0x70))

// ---------------- device scratch (allocation-free rule) --------------------
__device__ __half g_a0h[4096 * 1024];
__device__ __half g_a0l[4096 * 1024];
__device__ __half g_a1h[4096 * 1024];
__device__ __half g_a1l[4096 * 1024];
__device__ __half g_sh[4096 * 128];
__device__ __half g_sl[4096 * 128];
__device__ __half g_w1h[1024 * 128];
__device__ __half g_w1l[1024 * 128];
__device__ __half g_w2h[1024 * 1024];
__device__ __half g_w2l[1024 * 1024];
__device__ __half g_w3h[1024 * 1024];
__device__ __half g_w3l[1024 * 1024];
__device__ __half g_w4h[256 * 1024];
__device__ __half g_w4l[256 * 1024];
__device__ __half g_wlh[1024 * 128];
__device__ __half g_wll[1024 * 128];
__device__ __half g_weh[8192 * 1024];
__device__ __half g_wel[8192 * 1024];
__device__ float g_values[4096 * 256];
__device__ float g_dist[4096 * 256];

__device__ __forceinline__ void* sp(int id) {
    switch (id) {
        case 0:  return g_a0h; case 1:  return g_a0l;
        case 2:  return g_a1h; case 3:  return g_a1l;
        case 4:  return g_sh;  case 5:  return g_sl;
        case 6:  return g_w1h; case 7:  return g_w1l;
        case 8:  return g_w2h; case 9:  return g_w2l;
        case 10: return g_w3h; case 11: return g_w3l;
        case 12: return g_w4h; case 13: return g_w4l;
        case 14: return g_wlh; case 15: return g_wll;
        case 16: return g_weh; case 17: return g_wel;
        case 18: return g_values; default: return g_dist;
    }
}

// ---------------- PTX helpers (base ISA only) ------------------------------
__device__ __forceinline__ uint32_t smem_u32(const void* p) {
    uint32_t a;
    asm("{ .reg .u64 t; cvta.to.shared.u64 t, %1; cvt.u32.u64 %0, t; }" : "=r"(a) : "l"(p));
    return a;
}
__device__ __forceinline__ void cp16(uint32_t dst, const void* src) {
    asm volatile("cp.async.cg.shared.global [%0], [%1], 16;" :: "r"(dst), "l"(src) : "memory");
}
__device__ __forceinline__ void cp_commit() {
    asm volatile("cp.async.commit_group;" ::: "memory");
}
__device__ __forceinline__ void cp_wait0() {
    asm volatile("cp.async.wait_group 0;" ::: "memory");
}
__device__ __forceinline__ void cp_wait1() {
    asm volatile("cp.async.wait_group 1;" ::: "memory");
}
__device__ __forceinline__ void ldm_x4(uint32_t* r, uint32_t addr) {
    asm volatile("ldmatrix.sync.aligned.m8n8.x4.shared.b16 {%0,%1,%2,%3}, [%4];"
                 : "=r"(r[0]), "=r"(r[1]), "=r"(r[2]), "=r"(r[3]) : "r"(addr));
}
__device__ __forceinline__ void mma16816(float* c, const uint32_t* a, const uint32_t* b) {
    asm volatile(
        "mma.sync.aligned.m16n8k16.row.col.f32.f16.f16.f32 "
        "{%0,%1,%2,%3}, {%4,%5,%6,%7}, {%8,%9}, {%0,%1,%2,%3};"
        : "+f"(c[0]), "+f"(c[1]), "+f"(c[2]), "+f"(c[3])
        : "r"(a[0]), "r"(a[1]), "r"(a[2]), "r"(a[3]), "r"(b[0]), "r"(b[1]));
}

__device__ __forceinline__ void split2(float x, __half& h, __half& l) {
    h = __float2half_rn(x);
    l = __float2half_rn(x - __half2float(h));
}
__device__ __forceinline__ float tanh_fast(float x) {
    return __fdividef(2.0f, __expf(-2.0f * x) + 1.0f) - 1.0f;
}

// ---------------- conversion kernels ---------------------------------------
__global__ void split_kernel(const float* __restrict__ src, int n, int hid, int lid) {
    __half* h = (__half*)sp(hid);
    __half* l = (__half*)sp(lid);
    int i = blockIdx.x * blockDim.x + threadIdx.x;
    if (i < n) split2(src[i], h[i], l[i]);
}

// W[K][N] fp32 -> out[N][K] fp16 hi/lo
__global__ void transpose_split(const float* __restrict__ W, int K, int N, int hid, int lid) {
    __shared__ float t[32][33];
    __half* oh = (__half*)sp(hid);
    __half* ol = (__half*)sp(lid);
    int n0 = blockIdx.x * 32, k0 = blockIdx.y * 32;
    t[threadIdx.y][threadIdx.x] = W[(size_t)(k0 + threadIdx.y) * N + n0 + threadIdx.x];
    __syncthreads();
    float v = t[threadIdx.x][threadIdx.y];
    size_t o = (size_t)(n0 + threadIdx.y) * K + k0 + threadIdx.x;
    split2(v, oh[o], ol[o]);
}

// Wexp[256][1024][32] fp32 -> out[n*32+a][1024] fp16 hi/lo
__global__ void wexp_split(const float* __restrict__ W, int hid, int lid) {
    __shared__ float t[32][33];
    __half* oh = (__half*)sp(hid);
    __half* ol = (__half*)sp(lid);
    int k0 = blockIdx.x * 32, n = blockIdx.y;
    t[threadIdx.y][threadIdx.x] =
        W[((size_t)n * 1024 + (k0 + threadIdx.y)) * 32 + threadIdx.x];
    __syncthreads();
    float v = t[threadIdx.x][threadIdx.y];  // a=threadIdx.y, k=k0+threadIdx.x
    size_t o = (size_t)(n * 32 + threadIdx.y) * 1024 + k0 + threadIdx.x;
    split2(v, oh[o], ol[o]);
}

// ---------------- warp-MMA GEMM ---------------------------------------------
// EPI: 0 = bias+relu -> hi/lo fp16 out (o1=hi id, o2=lo id)
//      1 = bias -> fp32 (o1 = id)
//      2 = expert: tanh + distance fused (o1 = dist id, bias=bexp)
static constexpr int STAGE = 65536;                  // Ah,Al,Bh,Bl @ 16KB each
static constexpr int SMEM_BYTES = 1024 + 2 * STAGE;  // align pad + 2 stages

template <int EPI>
__global__ void __launch_bounds__(256, 1)
mma_gemm(int ahi, int alo, int bhi, int blo,
         const float* __restrict__ bias, const float* __restrict__ act,
         int o1, int o2, int M, int N, int K)
{
    extern __shared__ char smem_raw[];
    const uint32_t sb = (smem_u32(smem_raw) + 1023) & ~1023u;

    const __half* Ah = (const __half*)sp(ahi);
    const __half* Al = (const __half*)sp(alo);
    const __half* Bh = (const __half*)sp(bhi);
    const __half* Bl = (const __half*)sp(blo);

    const int tid = threadIdx.x;
    const int lane = tid & 31;
    const int wid = tid >> 5;
    const int wm = wid >> 2;        // 0..1 : 64-row strip
    const int wn = wid & 3;         // 0..3 : 32-col strip
    const int m0 = blockIdx.y * 128;
    const int n0 = blockIdx.x * 128;

    float acc[4][4][4];
#pragma unroll
    for (int i = 0; i < 4; i++)
#pragma unroll
        for (int j = 0; j < 4; j++)
#pragma unroll
            for (int q = 0; q < 4; q++) acc[i][j][q] = 0.f;

    const int C = K >> 6;

    auto issue = [&](int c, int s) {
        const uint32_t st = sb + s * STAGE;
        const int k0 = c * 64;
#pragma unroll
        for (int i = tid; i < 1024; i += 256) {
            int r = i >> 3, seg = i & 7;
            uint32_t off = SWZ((uint32_t)(r * 128 + seg * 16));
            size_t ga = (size_t)(m0 + r) * K + k0 + seg * 8;
            size_t gb = (size_t)(n0 + r) * K + k0 + seg * 8;
            cp16(st + off,         Ah + ga);
            cp16(st + 16384 + off, Al + ga);
            cp16(st + 32768 + off, Bh + gb);
            cp16(st + 49152 + off, Bl + gb);
        }
        cp_commit();
    };

    const int quad = lane >> 3, qi = lane & 7;

    auto compute = [&](int s) {
        const uint32_t st = sb + s * STAGE;
#pragma unroll
        for (int kk = 0; kk < 4; kk++) {
            uint32_t ah[4][4], al[4][4];
#pragma unroll
            for (int mt = 0; mt < 4; mt++) {
                int row = wm * 64 + mt * 16 + (quad & 1) * 8 + qi;
                int colb = (kk * 16 + (quad >> 1) * 8) * 2;
                uint32_t ad = st + SWZ((uint32_t)(row * 128 + colb));
                ldm_x4(ah[mt], ad);
                ldm_x4(al[mt], ad + 16384);
            }
            uint32_t bh[4][2], bl[4][2];
#pragma unroll
            for (int p = 0; p < 2; p++) {
                int row = wn * 32 + p * 16 + (quad >> 1) * 8 + qi;
                int colb = (kk * 16 + (quad & 1) * 8) * 2;
                uint32_t bd = st + 32768 + SWZ((uint32_t)(row * 128 + colb));
                uint32_t r4[4];
                ldm_x4(r4, bd);
                bh[p * 2][0] = r4[0]; bh[p * 2][1] = r4[1];
                bh[p * 2 + 1][0] = r4[2]; bh[p * 2 + 1][1] = r4[3];
                ldm_x4(r4, bd + 16384);
                bl[p * 2][0] = r4[0]; bl[p * 2][1] = r4[1];
                bl[p * 2 + 1][0] = r4[2]; bl[p * 2 + 1][1] = r4[3];
            }
#pragma unroll
            for (int mt = 0; mt < 4; mt++)
#pragma unroll
                for (int nt = 0; nt < 4; nt++) {
                    mma16816(acc[mt][nt], ah[mt], bh[nt]);
                    mma16816(acc[mt][nt], ah[mt], bl[nt]);
                    mma16816(acc[mt][nt], al[mt], bh[nt]);
                }
        }
    };

    issue(0, 0);
    for (int c = 0; c < C; ++c) {
        if (c + 1 < C) { issue(c + 1, (c + 1) & 1); cp_wait1(); }
        else           { cp_wait0(); }
        __syncthreads();
        compute(c & 1);
        __syncthreads();
    }

    // ---- epilogue ----
    const int r4 = lane >> 2;       // 0..7
    const int cp2 = (lane & 3) * 2; // 0,2,4,6

    if constexpr (EPI == 2) {
        const float* dist_bias = bias;
        float* dist = (float*)sp(o1);
        const int nc = blockIdx.x * 4 + wn;  // centroid index
#pragma unroll
        for (int mt = 0; mt < 4; mt++) {
#pragma unroll
            for (int h = 0; h < 2; h++) {
                int row = m0 + wm * 64 + mt * 16 + r4 + h * 8;
                float ss = 0.f;
#pragma unroll
                for (int nt = 0; nt < 4; nt++) {
                    int col = n0 + wn * 32 + nt * 8 + cp2;
                    int ai = nt * 8 + cp2;
                    float z0 = acc[mt][nt][h * 2 + 0] + dist_bias[col];
                    float z1 = acc[mt][nt][h * 2 + 1] + dist_bias[col + 1];
                    float d0 = tanh_fast(z0) - act[(size_t)row * 32 + ai];
                    float d1 = tanh_fast(z1) - act[(size_t)row * 32 + ai + 1];
                    ss += d0 * d0 + d1 * d1;
                }
                ss += __shfl_xor_sync(0xffffffffu, ss, 1);
                ss += __shfl_xor_sync(0xffffffffu, ss, 2);
                if ((lane & 3) == 0)
                    dist[(size_t)row * 256 + nc] = sqrtf(ss + 0.01f);
            }
        }
    } else if constexpr (EPI == 1) {
        float* o = (float*)sp(o1);
#pragma unroll
        for (int mt = 0; mt < 4; mt++)
#pragma unroll
            for (int nt = 0; nt < 4; nt++) {
                int row = m0 + wm * 64 + mt * 16 + r4;
                int col = n0 + wn * 32 + nt * 8 + cp2;
                float2 v0 = {acc[mt][nt][0] + bias[col], acc[mt][nt][1] + bias[col + 1]};
                float2 v1 = {acc[mt][nt][2] + bias[col], acc[mt][nt][3] + bias[col + 1]};
                *(float2*)(o + (size_t)row * N + col) = v0;
                *(float2*)(o + (size_t)(row + 8) * N + col) = v1;
            }
    } else {
        __half* oh = (__half*)sp(o1);
        __half* ol = (__half*)sp(o2);
#pragma unroll
        for (int mt = 0; mt < 4; mt++)
#pragma unroll
            for (int nt = 0; nt < 4; nt++) {
                int row = m0 + wm * 64 + mt * 16 + r4;
                int col = n0 + wn * 32 + nt * 8 + cp2;
                float b0 = bias[col], b1 = bias[col + 1];
#pragma unroll
                for (int h = 0; h < 2; h++) {
                    int rr = row + h * 8;
                    float y0 = fmaxf(acc[mt][nt][h * 2 + 0] + b0, 0.f);
                    float y1 = fmaxf(acc[mt][nt][h * 2 + 1] + b1, 0.f);
                    __half h0, l0, h1, l1;
                    split2(y0, h0, l0);
                    split2(y1, h1, l1);
                    *(__half2*)(oh + (size_t)rr * N + col) = __halves2half2(h0, h1);
                    *(__half2*)(ol + (size_t)rr * N + col) = __halves2half2(l0, l1);
                }
            }
    }
}

// ---------------- finalize: softmax(-dist) . values ------------------------
__global__ void finalize_kernel(float* __restrict__ out) {
    const float* dist = (const float*)sp(19);
    const float* values = (const float*)sp(18);
    const int b = blockIdx.x;
    const int n = threadIdx.x;
    const int lane = n & 31, w = n >> 5;

    float logit = -dist[(size_t)b * 256 + n];
    float v = values[(size_t)b * 256 + n];

    __shared__ float smax[8], s_e[8], s_ev[8];
    float mx = logit;
#pragma unroll
    for (int off = 16; off; off >>= 1)
        mx = fmaxf(mx, __shfl_xor_sync(0xffffffffu, mx, off));
    if (lane == 0) smax[w] = mx;
    __syncthreads();
    float bm = smax[0];
#pragma unroll
    for (int i = 1; i < 8; i++) bm = fmaxf(bm, smax[i]);

    float e = expf(logit - bm);
    float se = e, sev = e * v;
#pragma unroll
    for (int off = 16; off; off >>= 1) {
        se += __shfl_xor_sync(0xffffffffu, se, off);
        sev += __shfl_xor_sync(0xffffffffu, sev, off);
    }
    if (lane == 0) { s_e[w] = se; s_ev[w] = sev; }
    __syncthreads();
    if (n == 0) {
        float te = 0.f, tev = 0.f;
#pragma unroll
        for (int i = 0; i < 8; i++) { te += s_e[i]; tev += s_ev[i]; }
        out[b] = tev / te;
    }
}

// ---------------- launch ----------------------------------------------------
extern "C" void kernel_launch(void* const* d_in, const int* in_sizes, int n_in,
                              void* d_out, int out_size)
{
    const float* s    = (const float*)d_in[0];
    const float* act  = (const float*)d_in[1];
    const float* Wv1  = (const float*)d_in[2];
    const float* bv1  = (const float*)d_in[3];
    const float* Wv2  = (const float*)d_in[4];
    const float* bv2  = (const float*)d_in[5];
    const float* Wv3  = (const float*)d_in[6];
    const float* bv3  = (const float*)d_in[7];
    const float* Wv4  = (const float*)d_in[8];
    const float* bv4  = (const float*)d_in[9];
    const float* Wl1  = (const float*)d_in[10];
    const float* bl1  = (const float*)d_in[11];
    const float* Wexp = (const float*)d_in[12];
    const float* bexp = (const float*)d_in[13];
    float* out = (float*)d_out;

    cudaFuncSetAttribute(mma_gemm<0>, cudaFuncAttributeMaxDynamicSharedMemorySize, SMEM_BYTES);
    cudaFuncSetAttribute(mma_gemm<1>, cudaFuncAttributeMaxDynamicSharedMemorySize, SMEM_BYTES);
    cudaFuncSetAttribute(mma_gemm<2>, cudaFuncAttributeMaxDynamicSharedMemorySize, SMEM_BYTES);

    dim3 t32(32, 32);

    // conversions
    split_kernel<<<(4096 * 128 + 255) / 256, 256>>>(s, 4096 * 128, 4, 5);
    transpose_split<<<dim3(1024 / 32, 128 / 32),  t32>>>(Wv1, 128, 1024, 6, 7);
    transpose_split<<<dim3(1024 / 32, 1024 / 32), t32>>>(Wv2, 1024, 1024, 8, 9);
    transpose_split<<<dim3(1024 / 32, 1024 / 32), t32>>>(Wv3, 1024, 1024, 10, 11);
    transpose_split<<<dim3(256 / 32, 1024 / 32),  t32>>>(Wv4, 1024, 256, 12, 13);
    transpose_split<<<dim3(1024 / 32, 128 / 32),  t32>>>(Wl1, 128, 1024, 14, 15);
    wexp_split<<<dim3(1024 / 32, 256), t32>>>(Wexp, 16, 17);

    // value MLP: s -> a0 -> a1 -> a0 -> values
    mma_gemm<0><<<dim3(8, 32), 256, SMEM_BYTES>>>(4, 5, 6, 7,   bv1, nullptr, 0, 1, 4096, 1024, 128);
    mma_gemm<0><<<dim3(8, 32), 256, SMEM_BYTES>>>(0, 1, 8, 9,   bv2, nullptr, 2, 3, 4096, 1024, 1024);
    mma_gemm<0><<<dim3(8, 32), 256, SMEM_BYTES>>>(2, 3, 10, 11, bv3, nullptr, 0, 1, 4096, 1024, 1024);
    mma_gemm<1><<<dim3(2, 32), 256, SMEM_BYTES>>>(0, 1, 12, 13, bv4, nullptr, 18, 0, 4096, 256, 1024);

    // location hidden: s -> a1
    mma_gemm<0><<<dim3(8, 32), 256, SMEM_BYTES>>>(4, 5, 14, 15, bl1, nullptr, 2, 3, 4096, 1024, 128);

    // expert GEMM + fused tanh/dist
    mma_gemm<2><<<dim3(64, 32), 256, SMEM_BYTES>>>(2, 3, 16, 17, bexp, act, 19, 0, 4096, 8192, 1024);

    finalize_kernel<<<4096, 256>>>(out);
}

// round 5
// speedup vs baseline: 2.8666x; 1.2066x over previous
#include <cuda_runtime.h>
#include <cuda_fp16.h>
#include <math.h>
#include <stdint.h>

// ===========================================================================
// B=4096, S=128, A=32, H=1024, N=256.
// Legacy tensor-core path (base PTX, works under compute_103):
//   ldmatrix + mma.sync.m16n8k16.row.col.f32.f16.f16.f32 + cp.async
// fp16 hi/lo split:
//   MLP GEMMs (3-term):  D = Ah*Bh + Ah*Bl + Al*Bh   (~2^-22 rel err)
//   Expert GEMM (2-term): D = Ah*Bh + Al*Bh          (B fp16-rounded, ~5e-4;
//     damped by tanh saturation + distance floor + softmax averaging)
// CTA 128x128, 8 warps (2x4), warp tile 64x32, K-chunk 64, double buffer.
// ===========================================================================

#define SWZ(o) ((o) ^ (((o) >> 3) & 0x70))

// ---------------- device scratch (allocation-free rule) --------------------
__device__ __half g_a0h[4096 * 1024];
__device__ __half g_a0l[4096 * 1024];
__device__ __half g_a1h[4096 * 1024];
__device__ __half g_a1l[4096 * 1024];
__device__ __half g_sh[4096 * 128];
__device__ __half g_sl[4096 * 128];
__device__ __half g_w1h[1024 * 128];
__device__ __half g_w1l[1024 * 128];
__device__ __half g_w2h[1024 * 1024];
__device__ __half g_w2l[1024 * 1024];
__device__ __half g_w3h[1024 * 1024];
__device__ __half g_w3l[1024 * 1024];
__device__ __half g_w4h[256 * 1024];
__device__ __half g_w4l[256 * 1024];
__device__ __half g_wlh[1024 * 128];
__device__ __half g_wll[1024 * 128];
__device__ __half g_weh[8192 * 1024];
__device__ __half g_wel[8192 * 1024];
__device__ float g_values[4096 * 256];
__device__ float g_dist[4096 * 256];

__device__ __forceinline__ void* sp(int id) {
    switch (id) {
        case 0:  return g_a0h; case 1:  return g_a0l;
        case 2:  return g_a1h; case 3:  return g_a1l;
        case 4:  return g_sh;  case 5:  return g_sl;
        case 6:  return g_w1h; case 7:  return g_w1l;
        case 8:  return g_w2h; case 9:  return g_w2l;
        case 10: return g_w3h; case 11: return g_w3l;
        case 12: return g_w4h; case 13: return g_w4l;
        case 14: return g_wlh; case 15: return g_wll;
        case 16: return g_weh; case 17: return g_wel;
        case 18: return g_values; default: return g_dist;
    }
}

// ---------------- PTX helpers (base ISA only) ------------------------------
__device__ __forceinline__ uint32_t smem_u32(const void* p) {
    uint32_t a;
    asm("{ .reg .u64 t; cvta.to.shared.u64 t, %1; cvt.u32.u64 %0, t; }" : "=r"(a) : "l"(p));
    return a;
}
__device__ __forceinline__ void cp16(uint32_t dst, const void* src) {
    asm volatile("cp.async.cg.shared.global [%0], [%1], 16;" :: "r"(dst), "l"(src) : "memory");
}
__device__ __forceinline__ void cp_commit() {
    asm volatile("cp.async.commit_group;" ::: "memory");
}
__device__ __forceinline__ void cp_wait0() {
    asm volatile("cp.async.wait_group 0;" ::: "memory");
}
__device__ __forceinline__ void cp_wait1() {
    asm volatile("cp.async.wait_group 1;" ::: "memory");
}
__device__ __forceinline__ void ldm_x4(uint32_t* r, uint32_t addr) {
    asm volatile("ldmatrix.sync.aligned.m8n8.x4.shared.b16 {%0,%1,%2,%3}, [%4];"
                 : "=r"(r[0]), "=r"(r[1]), "=r"(r[2]), "=r"(r[3]) : "r"(addr));
}
__device__ __forceinline__ void mma16816(float* c, const uint32_t* a, const uint32_t* b) {
    asm volatile(
        "mma.sync.aligned.m16n8k16.row.col.f32.f16.f16.f32 "
        "{%0,%1,%2,%3}, {%4,%5,%6,%7}, {%8,%9}, {%0,%1,%2,%3};"
        : "+f"(c[0]), "+f"(c[1]), "+f"(c[2]), "+f"(c[3])
        : "r"(a[0]), "r"(a[1]), "r"(a[2]), "r"(a[3]), "r"(b[0]), "r"(b[1]));
}

__device__ __forceinline__ void split2(float x, __half& h, __half& l) {
    h = __float2half_rn(x);
    l = __float2half_rn(x - __half2float(h));
}
__device__ __forceinline__ float tanh_fast(float x) {
    return __fdividef(2.0f, __expf(-2.0f * x) + 1.0f) - 1.0f;
}

// ---------------- conversion kernels ---------------------------------------
__global__ void split_kernel(const float* __restrict__ src, int n, int hid, int lid) {
    __half* h = (__half*)sp(hid);
    __half* l = (__half*)sp(lid);
    int i = blockIdx.x * blockDim.x + threadIdx.x;
    if (i < n) split2(src[i], h[i], l[i]);
}

// W[K][N] fp32 -> out[N][K] fp16 hi/lo
__global__ void transpose_split(const float* __restrict__ W, int K, int N, int hid, int lid) {
    __shared__ float t[32][33];
    __half* oh = (__half*)sp(hid);
    __half* ol = (__half*)sp(lid);
    int n0 = blockIdx.x * 32, k0 = blockIdx.y * 32;
    t[threadIdx.y][threadIdx.x] = W[(size_t)(k0 + threadIdx.y) * N + n0 + threadIdx.x];
    __syncthreads();
    float v = t[threadIdx.x][threadIdx.y];
    size_t o = (size_t)(n0 + threadIdx.y) * K + k0 + threadIdx.x;
    split2(v, oh[o], ol[o]);
}

// Wexp[256][1024][32] fp32 -> out[n*32+a][1024] fp16 hi/lo
__global__ void wexp_split(const float* __restrict__ W, int hid, int lid) {
    __shared__ float t[32][33];
    __half* oh = (__half*)sp(hid);
    __half* ol = (__half*)sp(lid);
    int k0 = blockIdx.x * 32, n = blockIdx.y;
    t[threadIdx.y][threadIdx.x] =
        W[((size_t)n * 1024 + (k0 + threadIdx.y)) * 32 + threadIdx.x];
    __syncthreads();
    float v = t[threadIdx.x][threadIdx.y];  // a=threadIdx.y, k=k0+threadIdx.x
    size_t o = (size_t)(n * 32 + threadIdx.y) * 1024 + k0 + threadIdx.x;
    split2(v, oh[o], ol[o]);
}

// ---------------- warp-MMA GEMM ---------------------------------------------
// EPI: 0 = bias+relu -> hi/lo fp16 out (o1=hi id, o2=lo id)
//      1 = bias -> fp32 (o1 = id)
//      2 = expert: tanh + distance fused (o1 = dist id, bias=bexp)
// TERMS: 3 = Ah*Bh + Ah*Bl + Al*Bh ; 2 = Ah*Bh + Al*Bh (no Bl traffic/MMAs)
static constexpr int STAGE = 65536;                  // Ah,Al,Bh,(Bl) @ 16KB each
static constexpr int SMEM_BYTES = 1024 + 2 * STAGE;  // align pad + 2 stages

template <int EPI, int TERMS>
__global__ void __launch_bounds__(256, 1)
mma_gemm(int ahi, int alo, int bhi, int blo,
         const float* __restrict__ bias, const float* __restrict__ act,
         int o1, int o2, int M, int N, int K)
{
    extern __shared__ char smem_raw[];
    const uint32_t sb = (smem_u32(smem_raw) + 1023) & ~1023u;

    const __half* Ah = (const __half*)sp(ahi);
    const __half* Al = (const __half*)sp(alo);
    const __half* Bh = (const __half*)sp(bhi);
    const __half* Bl = (const __half*)sp(blo);

    const int tid = threadIdx.x;
    const int lane = tid & 31;
    const int wid = tid >> 5;
    const int wm = wid >> 2;        // 0..1 : 64-row strip
    const int wn = wid & 3;         // 0..3 : 32-col strip
    const int m0 = blockIdx.y * 128;
    const int n0 = blockIdx.x * 128;

    float acc[4][4][4];
#pragma unroll
    for (int i = 0; i < 4; i++)
#pragma unroll
        for (int j = 0; j < 4; j++)
#pragma unroll
            for (int q = 0; q < 4; q++) acc[i][j][q] = 0.f;

    const int C = K >> 6;

    auto issue = [&](int c, int s) {
        const uint32_t st = sb + s * STAGE;
        const int k0 = c * 64;
#pragma unroll
        for (int i = tid; i < 1024; i += 256) {
            int r = i >> 3, seg = i & 7;
            uint32_t off = SWZ((uint32_t)(r * 128 + seg * 16));
            size_t ga = (size_t)(m0 + r) * K + k0 + seg * 8;
            size_t gb = (size_t)(n0 + r) * K + k0 + seg * 8;
            cp16(st + off,         Ah + ga);
            cp16(st + 16384 + off, Al + ga);
            cp16(st + 32768 + off, Bh + gb);
            if (TERMS == 3) cp16(st + 49152 + off, Bl + gb);
        }
        cp_commit();
    };

    const int quad = lane >> 3, qi = lane & 7;

    auto compute = [&](int s) {
        const uint32_t st = sb + s * STAGE;
#pragma unroll
        for (int kk = 0; kk < 4; kk++) {
            uint32_t ah[4][4], al[4][4];
#pragma unroll
            for (int mt = 0; mt < 4; mt++) {
                int row = wm * 64 + mt * 16 + (quad & 1) * 8 + qi;
                int colb = (kk * 16 + (quad >> 1) * 8) * 2;
                uint32_t ad = st + SWZ((uint32_t)(row * 128 + colb));
                ldm_x4(ah[mt], ad);
                ldm_x4(al[mt], ad + 16384);
            }
            uint32_t bh[4][2], bl[4][2];
#pragma unroll
            for (int p = 0; p < 2; p++) {
                int row = wn * 32 + p * 16 + (quad >> 1) * 8 + qi;
                int colb = (kk * 16 + (quad & 1) * 8) * 2;
                uint32_t bd = st + 32768 + SWZ((uint32_t)(row * 128 + colb));
                uint32_t r4[4];
                ldm_x4(r4, bd);
                bh[p * 2][0] = r4[0]; bh[p * 2][1] = r4[1];
                bh[p * 2 + 1][0] = r4[2]; bh[p * 2 + 1][1] = r4[3];
                if (TERMS == 3) {
                    ldm_x4(r4, bd + 16384);
                    bl[p * 2][0] = r4[0]; bl[p * 2][1] = r4[1];
                    bl[p * 2 + 1][0] = r4[2]; bl[p * 2 + 1][1] = r4[3];
                }
            }
#pragma unroll
            for (int mt = 0; mt < 4; mt++)
#pragma unroll
                for (int nt = 0; nt < 4; nt++) {
                    mma16816(acc[mt][nt], ah[mt], bh[nt]);
                    if (TERMS == 3) mma16816(acc[mt][nt], ah[mt], bl[nt]);
                    mma16816(acc[mt][nt], al[mt], bh[nt]);
                }
        }
    };

    issue(0, 0);
    for (int c = 0; c < C; ++c) {
        if (c + 1 < C) { issue(c + 1, (c + 1) & 1); cp_wait1(); }
        else           { cp_wait0(); }
        __syncthreads();
        compute(c & 1);
        __syncthreads();
    }

    // ---- epilogue ----
    const int r4 = lane >> 2;       // 0..7
    const int cp2 = (lane & 3) * 2; // 0,2,4,6

    if constexpr (EPI == 2) {
        const float* dist_bias = bias;
        float* dist = (float*)sp(o1);
        const int nc = blockIdx.x * 4 + wn;  // centroid index
#pragma unroll
        for (int mt = 0; mt < 4; mt++) {
#pragma unroll
            for (int h = 0; h < 2; h++) {
                int row = m0 + wm * 64 + mt * 16 + r4 + h * 8;
                float ss = 0.f;
#pragma unroll
                for (int nt = 0; nt < 4; nt++) {
                    int col = n0 + wn * 32 + nt * 8 + cp2;
                    int ai = nt * 8 + cp2;
                    float z0 = acc[mt][nt][h * 2 + 0] + dist_bias[col];
                    float z1 = acc[mt][nt][h * 2 + 1] + dist_bias[col + 1];
                    float d0 = tanh_fast(z0) - act[(size_t)row * 32 + ai];
                    float d1 = tanh_fast(z1) - act[(size_t)row * 32 + ai + 1];
                    ss += d0 * d0 + d1 * d1;
                }
                ss += __shfl_xor_sync(0xffffffffu, ss, 1);
                ss += __shfl_xor_sync(0xffffffffu, ss, 2);
                if ((lane & 3) == 0)
                    dist[(size_t)row * 256 + nc] = sqrtf(ss + 0.01f);
            }
        }
    } else if constexpr (EPI == 1) {
        float* o = (float*)sp(o1);
#pragma unroll
        for (int mt = 0; mt < 4; mt++)
#pragma unroll
            for (int nt = 0; nt < 4; nt++) {
                int row = m0 + wm * 64 + mt * 16 + r4;
                int col = n0 + wn * 32 + nt * 8 + cp2;
                float2 v0 = {acc[mt][nt][0] + bias[col], acc[mt][nt][1] + bias[col + 1]};
                float2 v1 = {acc[mt][nt][2] + bias[col], acc[mt][nt][3] + bias[col + 1]};
                *(float2*)(o + (size_t)row * N + col) = v0;
                *(float2*)(o + (size_t)(row + 8) * N + col) = v1;
            }
    } else {
        __half* oh = (__half*)sp(o1);
        __half* ol = (__half*)sp(o2);
#pragma unroll
        for (int mt = 0; mt < 4; mt++)
#pragma unroll
            for (int nt = 0; nt < 4; nt++) {
                int row = m0 + wm * 64 + mt * 16 + r4;
                int col = n0 + wn * 32 + nt * 8 + cp2;
                float b0 = bias[col], b1 = bias[col + 1];
#pragma unroll
                for (int h = 0; h < 2; h++) {
                    int rr = row + h * 8;
                    float y0 = fmaxf(acc[mt][nt][h * 2 + 0] + b0, 0.f);
                    float y1 = fmaxf(acc[mt][nt][h * 2 + 1] + b1, 0.f);
                    __half h0, l0, h1, l1;
                    split2(y0, h0, l0);
                    split2(y1, h1, l1);
                    *(__half2*)(oh + (size_t)rr * N + col) = __halves2half2(h0, h1);
                    *(__half2*)(ol + (size_t)rr * N + col) = __halves2half2(l0, l1);
                }
            }
    }
}

// ---------------- finalize: softmax(-dist) . values ------------------------
__global__ void finalize_kernel(float* __restrict__ out) {
    const float* dist = (const float*)sp(19);
    const float* values = (const float*)sp(18);
    const int b = blockIdx.x;
    const int n = threadIdx.x;
    const int lane = n & 31, w = n >> 5;

    float logit = -dist[(size_t)b * 256 + n];
    float v = values[(size_t)b * 256 + n];

    __shared__ float smax[8], s_e[8], s_ev[8];
    float mx = logit;
#pragma unroll
    for (int off = 16; off; off >>= 1)
        mx = fmaxf(mx, __shfl_xor_sync(0xffffffffu, mx, off));
    if (lane == 0) smax[w] = mx;
    __syncthreads();
    float bm = smax[0];
#pragma unroll
    for (int i = 1; i < 8; i++) bm = fmaxf(bm, smax[i]);

    float e = expf(logit - bm);
    float se = e, sev = e * v;
#pragma unroll
    for (int off = 16; off; off >>= 1) {
        se += __shfl_xor_sync(0xffffffffu, se, off);
        sev += __shfl_xor_sync(0xffffffffu, sev, off);
    }
    if (lane == 0) { s_e[w] = se; s_ev[w] = sev; }
    __syncthreads();
    if (n == 0) {
        float te = 0.f, tev = 0.f;
#pragma unroll
        for (int i = 0; i < 8; i++) { te += s_e[i]; tev += s_ev[i]; }
        out[b] = tev / te;
    }
}

// ---------------- launch ----------------------------------------------------
extern "C" void kernel_launch(void* const* d_in, const int* in_sizes, int n_in,
                              void* d_out, int out_size)
{
    const float* s    = (const float*)d_in[0];
    const float* act  = (const float*)d_in[1];
    const float* Wv1  = (const float*)d_in[2];
    const float* bv1  = (const float*)d_in[3];
    const float* Wv2  = (const float*)d_in[4];
    const float* bv2  = (const float*)d_in[5];
    const float* Wv3  = (const float*)d_in[6];
    const float* bv3  = (const float*)d_in[7];
    const float* Wv4  = (const float*)d_in[8];
    const float* bv4  = (const float*)d_in[9];
    const float* Wl1  = (const float*)d_in[10];
    const float* bl1  = (const float*)d_in[11];
    const float* Wexp = (const float*)d_in[12];
    const float* bexp = (const float*)d_in[13];
    float* out = (float*)d_out;

    cudaFuncSetAttribute(mma_gemm<0,3>, cudaFuncAttributeMaxDynamicSharedMemorySize, SMEM_BYTES);
    cudaFuncSetAttribute(mma_gemm<1,3>, cudaFuncAttributeMaxDynamicSharedMemorySize, SMEM_BYTES);
    cudaFuncSetAttribute(mma_gemm<2,2>, cudaFuncAttributeMaxDynamicSharedMemorySize, SMEM_BYTES);

    dim3 t32(32, 32);

    // conversions
    split_kernel<<<(4096 * 128 + 255) / 256, 256>>>(s, 4096 * 128, 4, 5);
    transpose_split<<<dim3(1024 / 32, 128 / 32),  t32>>>(Wv1, 128, 1024, 6, 7);
    transpose_split<<<dim3(1024 / 32, 1024 / 32), t32>>>(Wv2, 1024, 1024, 8, 9);
    transpose_split<<<dim3(1024 / 32, 1024 / 32), t32>>>(Wv3, 1024, 1024, 10, 11);
    transpose_split<<<dim3(256 / 32, 1024 / 32),  t32>>>(Wv4, 1024, 256, 12, 13);
    transpose_split<<<dim3(1024 / 32, 128 / 32),  t32>>>(Wl1, 128, 1024, 14, 15);
    wexp_split<<<dim3(1024 / 32, 256), t32>>>(Wexp, 16, 17);

    // value MLP: s -> a0 -> a1 -> a0 -> values   (3-term, full precision)
    mma_gemm<0,3><<<dim3(8, 32), 256, SMEM_BYTES>>>(4, 5, 6, 7,   bv1, nullptr, 0, 1, 4096, 1024, 128);
    mma_gemm<0,3><<<dim3(8, 32), 256, SMEM_BYTES>>>(0, 1, 8, 9,   bv2, nullptr, 2, 3, 4096, 1024, 1024);
    mma_gemm<0,3><<<dim3(8, 32), 256, SMEM_BYTES>>>(2, 3, 10, 11, bv3, nullptr, 0, 1, 4096, 1024, 1024);
    mma_gemm<1,3><<<dim3(2, 32), 256, SMEM_BYTES>>>(0, 1, 12, 13, bv4, nullptr, 18, 0, 4096, 256, 1024);

    // location hidden: s -> a1   (3-term)
    mma_gemm<0,3><<<dim3(8, 32), 256, SMEM_BYTES>>>(4, 5, 14, 15, bl1, nullptr, 2, 3, 4096, 1024, 128);

    // expert GEMM + fused tanh/dist   (2-term: B fp16-rounded)
    mma_gemm<2,2><<<dim3(64, 32), 256, SMEM_BYTES>>>(2, 3, 16, 17, bexp, act, 19, 0, 4096, 8192, 1024);

    finalize_kernel<<<4096, 256>>>(out);
}

// round 9
// speedup vs baseline: 4.1074x; 1.4328x over previous
#include <cuda_runtime.h>
#include <cuda_fp16.h>
#include <math.h>
#include <stdint.h>

// ===========================================================================
// B=4096, S=128, A=32, H=1024, N=256.
// Legacy tensor-core path (base PTX, works under compute_103):
//   ldmatrix + mma.sync.m16n8k16.row.col.f32.f16.f16.f32 + cp.async
// fp16 hi/lo split:
//   MLP GEMMs (3-term):  D = Ah*Bh + Ah*Bl + Al*Bh   (~2^-22 rel err)
//   Expert GEMM (1-term): D = Ah*Bh  (both fp16-rounded, zero-mean ~3e-4,
//     damped by tanh saturation + distance floor + softmax averaging)
// CTA 128x128, 8 warps (2x4), warp tile 64x32, K-chunk 64, double buffer.
// Expert variant: 32KB/stage -> 2 CTAs/SM for latency hiding.
// ===========================================================================

#define SWZ(o) ((o) ^ (((o) >> 3) & 0x70))

// ---------------- device scratch (allocation-free rule) --------------------
__device__ __half g_a0h[4096 * 1024];
__device__ __half g_a0l[4096 * 1024];
__device__ __half g_a1h[4096 * 1024];
__device__ __half g_a1l[4096 * 1024];
__device__ __half g_sh[4096 * 128];
__device__ __half g_sl[4096 * 128];
__device__ __half g_w1h[1024 * 128];
__device__ __half g_w1l[1024 * 128];
__device__ __half g_w2h[1024 * 1024];
__device__ __half g_w2l[1024 * 1024];
__device__ __half g_w3h[1024 * 1024];
__device__ __half g_w3l[1024 * 1024];
__device__ __half g_w4h[256 * 1024];
__device__ __half g_w4l[256 * 1024];
__device__ __half g_wlh[1024 * 128];
__device__ __half g_wll[1024 * 128];
__device__ __half g_weh[8192 * 1024];
__device__ __half g_wel[8192 * 1024];
__device__ float g_values[4096 * 256];
__device__ float g_dist[4096 * 256];

__device__ __forceinline__ void* sp(int id) {
    switch (id) {
        case 0:  return g_a0h; case 1:  return g_a0l;
        case 2:  return g_a1h; case 3:  return g_a1l;
        case 4:  return g_sh;  case 5:  return g_sl;
        case 6:  return g_w1h; case 7:  return g_w1l;
        case 8:  return g_w2h; case 9:  return g_w2l;
        case 10: return g_w3h; case 11: return g_w3l;
        case 12: return g_w4h; case 13: return g_w4l;
        case 14: return g_wlh; case 15: return g_wll;
        case 16: return g_weh; case 17: return g_wel;
        case 18: return g_values; default: return g_dist;
    }
}

// ---------------- PTX helpers (base ISA only) ------------------------------
__device__ __forceinline__ uint32_t smem_u32(const void* p) {
    uint32_t a;
    asm("{ .reg .u64 t; cvta.to.shared.u64 t, %1; cvt.u32.u64 %0, t; }" : "=r"(a) : "l"(p));
    return a;
}
__device__ __forceinline__ void cp16(uint32_t dst, const void* src) {
    asm volatile("cp.async.cg.shared.global [%0], [%1], 16;" :: "r"(dst), "l"(src) : "memory");
}
__device__ __forceinline__ void cp_commit() {
    asm volatile("cp.async.commit_group;" ::: "memory");
}
__device__ __forceinline__ void cp_wait0() {
    asm volatile("cp.async.wait_group 0;" ::: "memory");
}
__device__ __forceinline__ void cp_wait1() {
    asm volatile("cp.async.wait_group 1;" ::: "memory");
}
__device__ __forceinline__ void ldm_x4(uint32_t* r, uint32_t addr) {
    asm volatile("ldmatrix.sync.aligned.m8n8.x4.shared.b16 {%0,%1,%2,%3}, [%4];"
                 : "=r"(r[0]), "=r"(r[1]), "=r"(r[2]), "=r"(r[3]) : "r"(addr));
}
__device__ __forceinline__ void mma16816(float* c, const uint32_t* a, const uint32_t* b) {
    asm volatile(
        "mma.sync.aligned.m16n8k16.row.col.f32.f16.f16.f32 "
        "{%0,%1,%2,%3}, {%4,%5,%6,%7}, {%8,%9}, {%0,%1,%2,%3};"
        : "+f"(c[0]), "+f"(c[1]), "+f"(c[2]), "+f"(c[3])
        : "r"(a[0]), "r"(a[1]), "r"(a[2]), "r"(a[3]), "r"(b[0]), "r"(b[1]));
}

__device__ __forceinline__ void split2(float x, __half& h, __half& l) {
    h = __float2half_rn(x);
    l = __float2half_rn(x - __half2float(h));
}
__device__ __forceinline__ float tanh_fast(float x) {
    return __fdividef(2.0f, __expf(-2.0f * x) + 1.0f) - 1.0f;
}

// ---------------- conversion kernels ---------------------------------------
__global__ void split_kernel(const float* __restrict__ src, int n, int hid, int lid) {
    __half* h = (__half*)sp(hid);
    __half* l = (__half*)sp(lid);
    int i = blockIdx.x * blockDim.x + threadIdx.x;
    if (i < n) split2(src[i], h[i], l[i]);
}

// W[K][N] fp32 -> out[N][K] fp16 hi/lo
__global__ void transpose_split(const float* __restrict__ W, int K, int N, int hid, int lid) {
    __shared__ float t[32][33];
    __half* oh = (__half*)sp(hid);
    __half* ol = (__half*)sp(lid);
    int n0 = blockIdx.x * 32, k0 = blockIdx.y * 32;
    t[threadIdx.y][threadIdx.x] = W[(size_t)(k0 + threadIdx.y) * N + n0 + threadIdx.x];
    __syncthreads();
    float v = t[threadIdx.x][threadIdx.y];
    size_t o = (size_t)(n0 + threadIdx.y) * K + k0 + threadIdx.x;
    split2(v, oh[o], ol[o]);
}

// Wexp[256][1024][32] fp32 -> out[n*32+a][1024] fp16 (hi only; expert is 1-term)
__global__ void wexp_split(const float* __restrict__ W, int hid) {
    __shared__ float t[32][33];
    __half* oh = (__half*)sp(hid);
    int k0 = blockIdx.x * 32, n = blockIdx.y;
    t[threadIdx.y][threadIdx.x] =
        W[((size_t)n * 1024 + (k0 + threadIdx.y)) * 32 + threadIdx.x];
    __syncthreads();
    float v = t[threadIdx.x][threadIdx.y];  // a=threadIdx.y, k=k0+threadIdx.x
    size_t o = (size_t)(n * 32 + threadIdx.y) * 1024 + k0 + threadIdx.x;
    oh[o] = __float2half_rn(v);
}

// ---------------- warp-MMA GEMM ---------------------------------------------
// EPI: 0 = bias+relu -> hi/lo fp16 out (o1=hi id, o2=lo id)
//      1 = bias -> fp32 (o1 = id)
//      2 = expert: tanh + distance fused (o1 = dist id, bias=bexp)
// TA/TB: number of fp16 planes per operand (1 = hi only, 2 = hi+lo).
// MMA terms: Ah*Bh always; Ah*Bl if TB==2; Al*Bh if TA==2.
template <int TA, int TB>
struct GemmCfg {
    static constexpr int STAGE = (TA + TB) * 16384;
    static constexpr int SMEM = 1024 + 2 * STAGE;
    static constexpr int MINB = (TA + TB <= 2) ? 2 : 1;
};

template <int EPI, int TA, int TB>
__global__ void __launch_bounds__(256, GemmCfg<TA, TB>::MINB)
mma_gemm(int ahi, int alo, int bhi, int blo,
         const float* __restrict__ bias, const float* __restrict__ act,
         int o1, int o2, int M, int N, int K)
{
    constexpr int STAGE = GemmCfg<TA, TB>::STAGE;
    constexpr uint32_t AL_OFF = 16384;               // only if TA==2
    constexpr uint32_t BH_OFF = TA * 16384;
    constexpr uint32_t BL_OFF = BH_OFF + 16384;      // only if TB==2

    extern __shared__ char smem_raw[];
    const uint32_t sb = (smem_u32(smem_raw) + 1023) & ~1023u;

    const __half* Ah = (const __half*)sp(ahi);
    const __half* Al = (const __half*)sp(alo);
    const __half* Bh = (const __half*)sp(bhi);
    const __half* Bl = (const __half*)sp(blo);

    const int tid = threadIdx.x;
    const int lane = tid & 31;
    const int wid = tid >> 5;
    const int wm = wid >> 2;        // 0..1 : 64-row strip
    const int wn = wid & 3;         // 0..3 : 32-col strip
    const int m0 = blockIdx.y * 128;
    const int n0 = blockIdx.x * 128;

    float acc[4][4][4];
#pragma unroll
    for (int i = 0; i < 4; i++)
#pragma unroll
        for (int j = 0; j < 4; j++)
#pragma unroll
            for (int q = 0; q < 4; q++) acc[i][j][q] = 0.f;

    const int C = K >> 6;

    auto issue = [&](int c, int s) {
        const uint32_t st = sb + s * STAGE;
        const int k0 = c * 64;
#pragma unroll
        for (int i = tid; i < 1024; i += 256) {
            int r = i >> 3, seg = i & 7;
            uint32_t off = SWZ((uint32_t)(r * 128 + seg * 16));
            size_t ga = (size_t)(m0 + r) * K + k0 + seg * 8;
            size_t gb = (size_t)(n0 + r) * K + k0 + seg * 8;
            cp16(st + off, Ah + ga);
            if (TA == 2) cp16(st + AL_OFF + off, Al + ga);
            cp16(st + BH_OFF + off, Bh + gb);
            if (TB == 2) cp16(st + BL_OFF + off, Bl + gb);
        }
        cp_commit();
    };

    const int quad = lane >> 3, qi = lane & 7;

    auto compute = [&](int s) {
        const uint32_t st = sb + s * STAGE;
#pragma unroll
        for (int kk = 0; kk < 4; kk++) {
            uint32_t ah[4][4], al[4][4];
#pragma unroll
            for (int mt = 0; mt < 4; mt++) {
                int row = wm * 64 + mt * 16 + (quad & 1) * 8 + qi;
                int colb = (kk * 16 + (quad >> 1) * 8) * 2;
                uint32_t ad = st + SWZ((uint32_t)(row * 128 + colb));
                ldm_x4(ah[mt], ad);
                if (TA == 2) ldm_x4(al[mt], ad + AL_OFF);
            }
            uint32_t bh[4][2], bl[4][2];
#pragma unroll
            for (int p = 0; p < 2; p++) {
                int row = wn * 32 + p * 16 + (quad >> 1) * 8 + qi;
                int colb = (kk * 16 + (quad & 1) * 8) * 2;
                uint32_t bd = st + BH_OFF + SWZ((uint32_t)(row * 128 + colb));
                uint32_t r4[4];
                ldm_x4(r4, bd);
                bh[p * 2][0] = r4[0]; bh[p * 2][1] = r4[1];
                bh[p * 2 + 1][0] = r4[2]; bh[p * 2 + 1][1] = r4[3];
                if (TB == 2) {
                    ldm_x4(r4, bd + 16384);
                    bl[p * 2][0] = r4[0]; bl[p * 2][1] = r4[1];
                    bl[p * 2 + 1][0] = r4[2]; bl[p * 2 + 1][1] = r4[3];
                }
            }
#pragma unroll
            for (int mt = 0; mt < 4; mt++)
#pragma unroll
                for (int nt = 0; nt < 4; nt++) {
                    mma16816(acc[mt][nt], ah[mt], bh[nt]);
                    if (TB == 2) mma16816(acc[mt][nt], ah[mt], bl[nt]);
                    if (TA == 2) mma16816(acc[mt][nt], al[mt], bh[nt]);
                }
        }
    };

    issue(0, 0);
    for (int c = 0; c < C; ++c) {
        if (c + 1 < C) { issue(c + 1, (c + 1) & 1); cp_wait1(); }
        else           { cp_wait0(); }
        __syncthreads();
        compute(c & 1);
        __syncthreads();
    }

    // ---- epilogue ----
    const int r4 = lane >> 2;       // 0..7
    const int cp2 = (lane & 3) * 2; // 0,2,4,6

    if constexpr (EPI == 2) {
        const float* dist_bias = bias;
        float* dist = (float*)sp(o1);
        const int nc = blockIdx.x * 4 + wn;  // centroid index
#pragma unroll
        for (int mt = 0; mt < 4; mt++) {
#pragma unroll
            for (int h = 0; h < 2; h++) {
                int row = m0 + wm * 64 + mt * 16 + r4 + h * 8;
                float ss = 0.f;
#pragma unroll
                for (int nt = 0; nt < 4; nt++) {
                    int col = n0 + wn * 32 + nt * 8 + cp2;
                    int ai = nt * 8 + cp2;
                    float z0 = acc[mt][nt][h * 2 + 0] + dist_bias[col];
                    float z1 = acc[mt][nt][h * 2 + 1] + dist_bias[col + 1];
                    float d0 = tanh_fast(z0) - act[(size_t)row * 32 + ai];
                    float d1 = tanh_fast(z1) - act[(size_t)row * 32 + ai + 1];
                    ss += d0 * d0 + d1 * d1;
                }
                ss += __shfl_xor_sync(0xffffffffu, ss, 1);
                ss += __shfl_xor_sync(0xffffffffu, ss, 2);
                if ((lane & 3) == 0)
                    dist[(size_t)row * 256 + nc] = sqrtf(ss + 0.01f);
            }
        }
    } else if constexpr (EPI == 1) {
        float* o = (float*)sp(o1);
#pragma unroll
        for (int mt = 0; mt < 4; mt++)
#pragma unroll
            for (int nt = 0; nt < 4; nt++) {
                int row = m0 + wm * 64 + mt * 16 + r4;
                int col = n0 + wn * 32 + nt * 8 + cp2;
                float2 v0 = {acc[mt][nt][0] + bias[col], acc[mt][nt][1] + bias[col + 1]};
                float2 v1 = {acc[mt][nt][2] + bias[col], acc[mt][nt][3] + bias[col + 1]};
                *(float2*)(o + (size_t)row * N + col) = v0;
                *(float2*)(o + (size_t)(row + 8) * N + col) = v1;
            }
    } else {
        __half* oh = (__half*)sp(o1);
        __half* ol = (__half*)sp(o2);
#pragma unroll
        for (int mt = 0; mt < 4; mt++)
#pragma unroll
            for (int nt = 0; nt < 4; nt++) {
                int row = m0 + wm * 64 + mt * 16 + r4;
                int col = n0 + wn * 32 + nt * 8 + cp2;
                float b0 = bias[col], b1 = bias[col + 1];
#pragma unroll
                for (int h = 0; h < 2; h++) {
                    int rr = row + h * 8;
                    float y0 = fmaxf(acc[mt][nt][h * 2 + 0] + b0, 0.f);
                    float y1 = fmaxf(acc[mt][nt][h * 2 + 1] + b1, 0.f);
                    __half h0, l0, h1, l1;
                    split2(y0, h0, l0);
                    split2(y1, h1, l1);
                    *(__half2*)(oh + (size_t)rr * N + col) = __halves2half2(h0, h1);
                    *(__half2*)(ol + (size_t)rr * N + col) = __halves2half2(l0, l1);
                }
            }
    }
}

// ---------------- finalize: softmax(-dist) . values ------------------------
__global__ void finalize_kernel(float* __restrict__ out) {
    const float* dist = (const float*)sp(19);
    const float* values = (const float*)sp(18);
    const int b = blockIdx.x;
    const int n = threadIdx.x;
    const int lane = n & 31, w = n >> 5;

    float logit = -dist[(size_t)b * 256 + n];
    float v = values[(size_t)b * 256 + n];

    __shared__ float smax[8], s_e[8], s_ev[8];
    float mx = logit;
#pragma unroll
    for (int off = 16; off; off >>= 1)
        mx = fmaxf(mx, __shfl_xor_sync(0xffffffffu, mx, off));
    if (lane == 0) smax[w] = mx;
    __syncthreads();
    float bm = smax[0];
#pragma unroll
    for (int i = 1; i < 8; i++) bm = fmaxf(bm, smax[i]);

    float e = expf(logit - bm);
    float se = e, sev = e * v;
#pragma unroll
    for (int off = 16; off; off >>= 1) {
        se += __shfl_xor_sync(0xffffffffu, se, off);
        sev += __shfl_xor_sync(0xffffffffu, sev, off);
    }
    if (lane == 0) { s_e[w] = se; s_ev[w] = sev; }
    __syncthreads();
    if (n == 0) {
        float te = 0.f, tev = 0.f;
#pragma unroll
        for (int i = 0; i < 8; i++) { te += s_e[i]; tev += s_ev[i]; }
        out[b] = tev / te;
    }
}

// ---------------- launch ----------------------------------------------------
extern "C" void kernel_launch(void* const* d_in, const int* in_sizes, int n_in,
                              void* d_out, int out_size)
{
    const float* s    = (const float*)d_in[0];
    const float* act  = (const float*)d_in[1];
    const float* Wv1  = (const float*)d_in[2];
    const float* bv1  = (const float*)d_in[3];
    const float* Wv2  = (const float*)d_in[4];
    const float* bv2  = (const float*)d_in[5];
    const float* Wv3  = (const float*)d_in[6];
    const float* bv3  = (const float*)d_in[7];
    const float* Wv4  = (const float*)d_in[8];
    const float* bv4  = (const float*)d_in[9];
    const float* Wl1  = (const float*)d_in[10];
    const float* bl1  = (const float*)d_in[11];
    const float* Wexp = (const float*)d_in[12];
    const float* bexp = (const float*)d_in[13];
    float* out = (float*)d_out;

    constexpr int S3 = GemmCfg<2, 2>::SMEM;  // 3-term MLP: 132KB
    constexpr int S1 = GemmCfg<1, 1>::SMEM;  // 1-term expert: 66KB

    cudaFuncSetAttribute(mma_gemm<0,2,2>, cudaFuncAttributeMaxDynamicSharedMemorySize, S3);
    cudaFuncSetAttribute(mma_gemm<1,2,2>, cudaFuncAttributeMaxDynamicSharedMemorySize, S3);
    cudaFuncSetAttribute(mma_gemm<2,1,1>, cudaFuncAttributeMaxDynamicSharedMemorySize, S1);

    dim3 t32(32, 32);

    // conversions
    split_kernel<<<(4096 * 128 + 255) / 256, 256>>>(s, 4096 * 128, 4, 5);
    transpose_split<<<dim3(1024 / 32, 128 / 32),  t32>>>(Wv1, 128, 1024, 6, 7);
    transpose_split<<<dim3(1024 / 32, 1024 / 32), t32>>>(Wv2, 1024, 1024, 8, 9);
    transpose_split<<<dim3(1024 / 32, 1024 / 32), t32>>>(Wv3, 1024, 1024, 10, 11);
    transpose_split<<<dim3(256 / 32, 1024 / 32),  t32>>>(Wv4, 1024, 256, 12, 13);
    transpose_split<<<dim3(1024 / 32, 128 / 32),  t32>>>(Wl1, 128, 1024, 14, 15);
    wexp_split<<<dim3(1024 / 32, 256), t32>>>(Wexp, 16);

    // value MLP: s -> a0 -> a1 -> a0 -> values   (3-term, full precision)
    mma_gemm<0,2,2><<<dim3(8, 32), 256, S3>>>(4, 5, 6, 7,   bv1, nullptr, 0, 1, 4096, 1024, 128);
    mma_gemm<0,2,2><<<dim3(8, 32), 256, S3>>>(0, 1, 8, 9,   bv2, nullptr, 2, 3, 4096, 1024, 1024);
    mma_gemm<0,2,2><<<dim3(8, 32), 256, S3>>>(2, 3, 10, 11, bv3, nullptr, 0, 1, 4096, 1024, 1024);
    mma_gemm<1,2,2><<<dim3(2, 32), 256, S3>>>(0, 1, 12, 13, bv4, nullptr, 18, 0, 4096, 256, 1024);

    // location hidden: s -> a1   (3-term)
    mma_gemm<0,2,2><<<dim3(8, 32), 256, S3>>>(4, 5, 14, 15, bl1, nullptr, 2, 3, 4096, 1024, 128);

    // expert GEMM + fused tanh/dist   (1-term fp16, 2 CTAs/SM)
    mma_gemm<2,1,1><<<dim3(64, 32), 256, S1>>>(2, 3, 16, 17, bexp, act, 19, 0, 4096, 8192, 1024);

    finalize_kernel<<<4096, 256>>>(out);
}

// round 11
// speedup vs baseline: 4.5032x; 1.0964x over previous
#include <cuda_runtime.h>
#include <cuda_fp16.h>
#include <math.h>
#include <stdint.h>

// ===========================================================================
// B=4096, S=128, A=32, H=1024, N=256.
// Legacy tensor-core path (base PTX, works under compute_103):
//   ldmatrix + mma.sync.m16n8k16.row.col.f32.f16.f16.f32 + cp.async
// fp16 hi/lo split, per-GEMM term count tuned to error budget:
//   L1 / L4 / loc (3-term):  D = Ah*Bh + Ah*Bl + Al*Bh    (~2^-22)
//   L2 / L3 (2-term):        D = (Ah+Al)*Bh               (W fp16, ~2.8e-4 zm)
//   Expert (1-term):         D = Ah*Bh                    (damped by tanh/dist/softmax)
// CTA 128x128, 8 warps (2x4), warp tile 64x32, K-chunk 64, double buffer.
// 2-term (97KB) and 1-term (66KB) variants run 2 CTAs/SM -> single wave + hiding.
// ===========================================================================

#define SWZ(o) ((o) ^ (((o) >> 3) & 0x70))

// ---------------- device scratch (allocation-free rule) --------------------
__device__ __half g_a0h[4096 * 1024];
__device__ __half g_a0l[4096 * 1024];
__device__ __half g_a1h[4096 * 1024];
__device__ __half g_a1l[4096 * 1024];
__device__ __half g_sh[4096 * 128];
__device__ __half g_sl[4096 * 128];
__device__ __half g_w1h[1024 * 128];
__device__ __half g_w1l[1024 * 128];
__device__ __half g_w2h[1024 * 1024];
__device__ __half g_w2l[1024 * 1024];
__device__ __half g_w3h[1024 * 1024];
__device__ __half g_w3l[1024 * 1024];
__device__ __half g_w4h[256 * 1024];
__device__ __half g_w4l[256 * 1024];
__device__ __half g_wlh[1024 * 128];
__device__ __half g_wll[1024 * 128];
__device__ __half g_weh[8192 * 1024];
__device__ __half g_wel[8192 * 1024];
__device__ float g_values[4096 * 256];
__device__ float g_dist[4096 * 256];

__device__ __forceinline__ void* sp(int id) {
    switch (id) {
        case 0:  return g_a0h; case 1:  return g_a0l;
        case 2:  return g_a1h; case 3:  return g_a1l;
        case 4:  return g_sh;  case 5:  return g_sl;
        case 6:  return g_w1h; case 7:  return g_w1l;
        case 8:  return g_w2h; case 9:  return g_w2l;
        case 10: return g_w3h; case 11: return g_w3l;
        case 12: return g_w4h; case 13: return g_w4l;
        case 14: return g_wlh; case 15: return g_wll;
        case 16: return g_weh; case 17: return g_wel;
        case 18: return g_values; default: return g_dist;
    }
}

// ---------------- PTX helpers (base ISA only) ------------------------------
__device__ __forceinline__ uint32_t smem_u32(const void* p) {
    uint32_t a;
    asm("{ .reg .u64 t; cvta.to.shared.u64 t, %1; cvt.u32.u64 %0, t; }" : "=r"(a) : "l"(p));
    return a;
}
__device__ __forceinline__ void cp16(uint32_t dst, const void* src) {
    asm volatile("cp.async.cg.shared.global [%0], [%1], 16;" :: "r"(dst), "l"(src) : "memory");
}
__device__ __forceinline__ void cp_commit() {
    asm volatile("cp.async.commit_group;" ::: "memory");
}
__device__ __forceinline__ void cp_wait0() {
    asm volatile("cp.async.wait_group 0;" ::: "memory");
}
__device__ __forceinline__ void cp_wait1() {
    asm volatile("cp.async.wait_group 1;" ::: "memory");
}
__device__ __forceinline__ void ldm_x4(uint32_t* r, uint32_t addr) {
    asm volatile("ldmatrix.sync.aligned.m8n8.x4.shared.b16 {%0,%1,%2,%3}, [%4];"
                 : "=r"(r[0]), "=r"(r[1]), "=r"(r[2]), "=r"(r[3]) : "r"(addr));
}
__device__ __forceinline__ void mma16816(float* c, const uint32_t* a, const uint32_t* b) {
    asm volatile(
        "mma.sync.aligned.m16n8k16.row.col.f32.f16.f16.f32 "
        "{%0,%1,%2,%3}, {%4,%5,%6,%7}, {%8,%9}, {%0,%1,%2,%3};"
        : "+f"(c[0]), "+f"(c[1]), "+f"(c[2]), "+f"(c[3])
        : "r"(a[0]), "r"(a[1]), "r"(a[2]), "r"(a[3]), "r"(b[0]), "r"(b[1]));
}

__device__ __forceinline__ void split2(float x, __half& h, __half& l) {
    h = __float2half_rn(x);
    l = __float2half_rn(x - __half2float(h));
}
__device__ __forceinline__ float tanh_fast(float x) {
    return __fdividef(2.0f, __expf(-2.0f * x) + 1.0f) - 1.0f;
}

// ---------------- conversion kernels ---------------------------------------
__global__ void split_kernel(const float* __restrict__ src, int n, int hid, int lid) {
    __half* h = (__half*)sp(hid);
    __half* l = (__half*)sp(lid);
    int i = blockIdx.x * blockDim.x + threadIdx.x;
    if (i < n) split2(src[i], h[i], l[i]);
}

// W[K][N] fp32 -> out[N][K] fp16 hi (+lo if lid >= 0)
__global__ void transpose_split(const float* __restrict__ W, int K, int N, int hid, int lid) {
    __shared__ float t[32][33];
    __half* oh = (__half*)sp(hid);
    int n0 = blockIdx.x * 32, k0 = blockIdx.y * 32;
    t[threadIdx.y][threadIdx.x] = W[(size_t)(k0 + threadIdx.y) * N + n0 + threadIdx.x];
    __syncthreads();
    float v = t[threadIdx.x][threadIdx.y];
    size_t o = (size_t)(n0 + threadIdx.y) * K + k0 + threadIdx.x;
    if (lid >= 0) {
        __half* ol = (__half*)sp(lid);
        split2(v, oh[o], ol[o]);
    } else {
        oh[o] = __float2half_rn(v);
    }
}

// Wexp[256][1024][32] fp32 -> out[n*32+a][1024] fp16 (hi only; expert is 1-term)
__global__ void wexp_split(const float* __restrict__ W, int hid) {
    __shared__ float t[32][33];
    __half* oh = (__half*)sp(hid);
    int k0 = blockIdx.x * 32, n = blockIdx.y;
    t[threadIdx.y][threadIdx.x] =
        W[((size_t)n * 1024 + (k0 + threadIdx.y)) * 32 + threadIdx.x];
    __syncthreads();
    float v = t[threadIdx.x][threadIdx.y];  // a=threadIdx.y, k=k0+threadIdx.x
    size_t o = (size_t)(n * 32 + threadIdx.y) * 1024 + k0 + threadIdx.x;
    oh[o] = __float2half_rn(v);
}

// ---------------- warp-MMA GEMM ---------------------------------------------
// EPI: 0 = bias+relu -> hi/lo fp16 out (o1=hi id, o2=lo id)
//      1 = bias -> fp32 (o1 = id)
//      2 = expert: tanh + distance fused (o1 = dist id, bias=bexp)
// TA/TB: fp16 planes per operand (1 = hi only, 2 = hi+lo).
// MMA terms: Ah*Bh always; Ah*Bl if TB==2; Al*Bh if TA==2.
template <int TA, int TB>
struct GemmCfg {
    static constexpr int STAGE = (TA + TB) * 16384;
    static constexpr int SMEM = 1024 + 2 * STAGE;
    static constexpr int MINB = (TA + TB <= 3) ? 2 : 1;  // <=3 planes: 2 CTAs/SM
};

template <int EPI, int TA, int TB>
__global__ void __launch_bounds__(256, GemmCfg<TA, TB>::MINB)
mma_gemm(int ahi, int alo, int bhi, int blo,
         const float* __restrict__ bias, const float* __restrict__ act,
         int o1, int o2, int M, int N, int K)
{
    constexpr int STAGE = GemmCfg<TA, TB>::STAGE;
    constexpr uint32_t AL_OFF = 16384;               // only if TA==2
    constexpr uint32_t BH_OFF = TA * 16384;
    constexpr uint32_t BL_OFF = BH_OFF + 16384;      // only if TB==2

    extern __shared__ char smem_raw[];
    const uint32_t sb = (smem_u32(smem_raw) + 1023) & ~1023u;

    const __half* Ah = (const __half*)sp(ahi);
    const __half* Al = (const __half*)sp(alo);
    const __half* Bh = (const __half*)sp(bhi);
    const __half* Bl = (const __half*)sp(blo);

    const int tid = threadIdx.x;
    const int lane = tid & 31;
    const int wid = tid >> 5;
    const int wm = wid >> 2;        // 0..1 : 64-row strip
    const int wn = wid & 3;         // 0..3 : 32-col strip
    const int m0 = blockIdx.y * 128;
    const int n0 = blockIdx.x * 128;

    float acc[4][4][4];
#pragma unroll
    for (int i = 0; i < 4; i++)
#pragma unroll
        for (int j = 0; j < 4; j++)
#pragma unroll
            for (int q = 0; q < 4; q++) acc[i][j][q] = 0.f;

    const int C = K >> 6;

    auto issue = [&](int c, int s) {
        const uint32_t st = sb + s * STAGE;
        const int k0 = c * 64;
#pragma unroll
        for (int i = tid; i < 1024; i += 256) {
            int r = i >> 3, seg = i & 7;
            uint32_t off = SWZ((uint32_t)(r * 128 + seg * 16));
            size_t ga = (size_t)(m0 + r) * K + k0 + seg * 8;
            size_t gb = (size_t)(n0 + r) * K + k0 + seg * 8;
            cp16(st + off, Ah + ga);
            if (TA == 2) cp16(st + AL_OFF + off, Al + ga);
            cp16(st + BH_OFF + off, Bh + gb);
            if (TB == 2) cp16(st + BL_OFF + off, Bl + gb);
        }
        cp_commit();
    };

    const int quad = lane >> 3, qi = lane & 7;

    auto compute = [&](int s) {
        const uint32_t st = sb + s * STAGE;
#pragma unroll
        for (int kk = 0; kk < 4; kk++) {
            uint32_t ah[4][4], al[4][4];
#pragma unroll
            for (int mt = 0; mt < 4; mt++) {
                int row = wm * 64 + mt * 16 + (quad & 1) * 8 + qi;
                int colb = (kk * 16 + (quad >> 1) * 8) * 2;
                uint32_t ad = st + SWZ((uint32_t)(row * 128 + colb));
                ldm_x4(ah[mt], ad);
                if (TA == 2) ldm_x4(al[mt], ad + AL_OFF);
            }
            uint32_t bh[4][2], bl[4][2];
#pragma unroll
            for (int p = 0; p < 2; p++) {
                int row = wn * 32 + p * 16 + (quad >> 1) * 8 + qi;
                int colb = (kk * 16 + (quad & 1) * 8) * 2;
                uint32_t bd = st + BH_OFF + SWZ((uint32_t)(row * 128 + colb));
                uint32_t r4[4];
                ldm_x4(r4, bd);
                bh[p * 2][0] = r4[0]; bh[p * 2][1] = r4[1];
                bh[p * 2 + 1][0] = r4[2]; bh[p * 2 + 1][1] = r4[3];
                if (TB == 2) {
                    ldm_x4(r4, bd + 16384);
                    bl[p * 2][0] = r4[0]; bl[p * 2][1] = r4[1];
                    bl[p * 2 + 1][0] = r4[2]; bl[p * 2 + 1][1] = r4[3];
                }
            }
#pragma unroll
            for (int mt = 0; mt < 4; mt++)
#pragma unroll
                for (int nt = 0; nt < 4; nt++) {
                    mma16816(acc[mt][nt], ah[mt], bh[nt]);
                    if (TB == 2) mma16816(acc[mt][nt], ah[mt], bl[nt]);
                    if (TA == 2) mma16816(acc[mt][nt], al[mt], bh[nt]);
                }
        }
    };

    issue(0, 0);
    for (int c = 0; c < C; ++c) {
        if (c + 1 < C) { issue(c + 1, (c + 1) & 1); cp_wait1(); }
        else           { cp_wait0(); }
        __syncthreads();
        compute(c & 1);
        __syncthreads();
    }

    // ---- epilogue ----
    const int r4 = lane >> 2;       // 0..7
    const int cp2 = (lane & 3) * 2; // 0,2,4,6

    if constexpr (EPI == 2) {
        const float* dist_bias = bias;
        float* dist = (float*)sp(o1);
        const int nc = blockIdx.x * 4 + wn;  // centroid index
#pragma unroll
        for (int mt = 0; mt < 4; mt++) {
#pragma unroll
            for (int h = 0; h < 2; h++) {
                int row = m0 + wm * 64 + mt * 16 + r4 + h * 8;
                float ss = 0.f;
#pragma unroll
                for (int nt = 0; nt < 4; nt++) {
                    int col = n0 + wn * 32 + nt * 8 + cp2;
                    int ai = nt * 8 + cp2;
                    float z0 = acc[mt][nt][h * 2 + 0] + dist_bias[col];
                    float z1 = acc[mt][nt][h * 2 + 1] + dist_bias[col + 1];
                    float d0 = tanh_fast(z0) - act[(size_t)row * 32 + ai];
                    float d1 = tanh_fast(z1) - act[(size_t)row * 32 + ai + 1];
                    ss += d0 * d0 + d1 * d1;
                }
                ss += __shfl_xor_sync(0xffffffffu, ss, 1);
                ss += __shfl_xor_sync(0xffffffffu, ss, 2);
                if ((lane & 3) == 0)
                    dist[(size_t)row * 256 + nc] = sqrtf(ss + 0.01f);
            }
        }
    } else if constexpr (EPI == 1) {
        float* o = (float*)sp(o1);
#pragma unroll
        for (int mt = 0; mt < 4; mt++)
#pragma unroll
            for (int nt = 0; nt < 4; nt++) {
                int row = m0 + wm * 64 + mt * 16 + r4;
                int col = n0 + wn * 32 + nt * 8 + cp2;
                float2 v0 = {acc[mt][nt][0] + bias[col], acc[mt][nt][1] + bias[col + 1]};
                float2 v1 = {acc[mt][nt][2] + bias[col], acc[mt][nt][3] + bias[col + 1]};
                *(float2*)(o + (size_t)row * N + col) = v0;
                *(float2*)(o + (size_t)(row + 8) * N + col) = v1;
            }
    } else {
        __half* oh = (__half*)sp(o1);
        __half* ol = (__half*)sp(o2);
#pragma unroll
        for (int mt = 0; mt < 4; mt++)
#pragma unroll
            for (int nt = 0; nt < 4; nt++) {
                int row = m0 + wm * 64 + mt * 16 + r4;
                int col = n0 + wn * 32 + nt * 8 + cp2;
                float b0 = bias[col], b1 = bias[col + 1];
#pragma unroll
                for (int h = 0; h < 2; h++) {
                    int rr = row + h * 8;
                    float y0 = fmaxf(acc[mt][nt][h * 2 + 0] + b0, 0.f);
                    float y1 = fmaxf(acc[mt][nt][h * 2 + 1] + b1, 0.f);
                    __half h0, l0, h1, l1;
                    split2(y0, h0, l0);
                    split2(y1, h1, l1);
                    *(__half2*)(oh + (size_t)rr * N + col) = __halves2half2(h0, h1);
                    *(__half2*)(ol + (size_t)rr * N + col) = __halves2half2(l0, l1);
                }
            }
    }
}

// ---------------- finalize: softmax(-dist) . values ------------------------
__global__ void finalize_kernel(float* __restrict__ out) {
    const float* dist = (const float*)sp(19);
    const float* values = (const float*)sp(18);
    const int b = blockIdx.x;
    const int n = threadIdx.x;
    const int lane = n & 31, w = n >> 5;

    float logit = -dist[(size_t)b * 256 + n];
    float v = values[(size_t)b * 256 + n];

    __shared__ float smax[8], s_e[8], s_ev[8];
    float mx = logit;
#pragma unroll
    for (int off = 16; off; off >>= 1)
        mx = fmaxf(mx, __shfl_xor_sync(0xffffffffu, mx, off));
    if (lane == 0) smax[w] = mx;
    __syncthreads();
    float bm = smax[0];
#pragma unroll
    for (int i = 1; i < 8; i++) bm = fmaxf(bm, smax[i]);

    float e = expf(logit - bm);
    float se = e, sev = e * v;
#pragma unroll
    for (int off = 16; off; off >>= 1) {
        se += __shfl_xor_sync(0xffffffffu, se, off);
        sev += __shfl_xor_sync(0xffffffffu, sev, off);
    }
    if (lane == 0) { s_e[w] = se; s_ev[w] = sev; }
    __syncthreads();
    if (n == 0) {
        float te = 0.f, tev = 0.f;
#pragma unroll
        for (int i = 0; i < 8; i++) { te += s_e[i]; tev += s_ev[i]; }
        out[b] = tev / te;
    }
}

// ---------------- launch ----------------------------------------------------
extern "C" void kernel_launch(void* const* d_in, const int* in_sizes, int n_in,
                              void* d_out, int out_size)
{
    const float* s    = (const float*)d_in[0];
    const float* act  = (const float*)d_in[1];
    const float* Wv1  = (const float*)d_in[2];
    const float* bv1  = (const float*)d_in[3];
    const float* Wv2  = (const float*)d_in[4];
    const float* bv2  = (const float*)d_in[5];
    const float* Wv3  = (const float*)d_in[6];
    const float* bv3  = (const float*)d_in[7];
    const float* Wv4  = (const float*)d_in[8];
    const float* bv4  = (const float*)d_in[9];
    const float* Wl1  = (const float*)d_in[10];
    const float* bl1  = (const float*)d_in[11];
    const float* Wexp = (const float*)d_in[12];
    const float* bexp = (const float*)d_in[13];
    float* out = (float*)d_out;

    constexpr int S3 = GemmCfg<2, 2>::SMEM;  // 3-term: 132KB, 1 CTA/SM
    constexpr int S2 = GemmCfg<2, 1>::SMEM;  // 2-term: 97KB,  2 CTAs/SM
    constexpr int S1 = GemmCfg<1, 1>::SMEM;  // 1-term: 66KB,  2 CTAs/SM

    cudaFuncSetAttribute(mma_gemm<0,2,2>, cudaFuncAttributeMaxDynamicSharedMemorySize, S3);
    cudaFuncSetAttribute(mma_gemm<1,2,2>, cudaFuncAttributeMaxDynamicSharedMemorySize, S3);
    cudaFuncSetAttribute(mma_gemm<0,2,1>, cudaFuncAttributeMaxDynamicSharedMemorySize, S2);
    cudaFuncSetAttribute(mma_gemm<2,1,1>, cudaFuncAttributeMaxDynamicSharedMemorySize, S1);

    dim3 t32(32, 32);

    // conversions (W2/W3 hi-only: their lo planes are dead under 2-term)
    split_kernel<<<(4096 * 128 + 255) / 256, 256>>>(s, 4096 * 128, 4, 5);
    transpose_split<<<dim3(1024 / 32, 128 / 32),  t32>>>(Wv1, 128, 1024, 6, 7);
    transpose_split<<<dim3(1024 / 32, 1024 / 32), t32>>>(Wv2, 1024, 1024, 8, -1);
    transpose_split<<<dim3(1024 / 32, 1024 / 32), t32>>>(Wv3, 1024, 1024, 10, -1);
    transpose_split<<<dim3(256 / 32, 1024 / 32),  t32>>>(Wv4, 1024, 256, 12, 13);
    transpose_split<<<dim3(1024 / 32, 128 / 32),  t32>>>(Wl1, 128, 1024, 14, 15);
    wexp_split<<<dim3(1024 / 32, 256), t32>>>(Wexp, 16);

    // value MLP: s -> a0 -> a1 -> a0 -> values
    // L1 3-term (exact), L2/L3 2-term (weights fp16), L4 3-term
    mma_gemm<0,2,2><<<dim3(8, 32), 256, S3>>>(4, 5, 6, 7,   bv1, nullptr, 0, 1, 4096, 1024, 128);
    mma_gemm<0,2,1><<<dim3(8, 32), 256, S2>>>(0, 1, 8, 9,   bv2, nullptr, 2, 3, 4096, 1024, 1024);
    mma_gemm<0,2,1><<<dim3(8, 32), 256, S2>>>(2, 3, 10, 11, bv3, nullptr, 0, 1, 4096, 1024, 1024);
    mma_gemm<1,2,2><<<dim3(2, 32), 256, S3>>>(0, 1, 12, 13, bv4, nullptr, 18, 0, 4096, 256, 1024);

    // location hidden: s -> a1   (3-term)
    mma_gemm<0,2,2><<<dim3(8, 32), 256, S3>>>(4, 5, 14, 15, bl1, nullptr, 2, 3, 4096, 1024, 128);

    // expert GEMM + fused tanh/dist   (1-term fp16, 2 CTAs/SM)
    mma_gemm<2,1,1><<<dim3(64, 32), 256, S1>>>(2, 3, 16, 17, bexp, act, 19, 0, 4096, 8192, 1024);

    finalize_kernel<<<4096, 256>>>(out);
}

// round 12
// speedup vs baseline: 4.5956x; 1.0205x over previous
#include <cuda_runtime.h>
#include <cuda_fp16.h>
#include <math.h>
#include <stdint.h>

// ===========================================================================
// B=4096, S=128, A=32, H=1024, N=256.
// ldmatrix + mma.sync.m16n8k16 + cp.async (base PTX, compute_103-safe).
// Precision plan (calibrated over rounds 4-11):
//   L1+loc merged (3-term), L4 (3-term), L2/L3 (2-term), expert (1-term).
// This round: expert 128x256 wide tile (512 thr), merged L1+loc launch,
//             vectorized conversion kernels.
// ===========================================================================

#define SWZ(o) ((o) ^ (((o) >> 3) & 0x70))

// ---------------- device scratch (allocation-free rule) --------------------
__device__ __half g_a0h[4096 * 1024];
__device__ __half g_a0l[4096 * 1024];
__device__ __half g_a1h[4096 * 1024];
__device__ __half g_a1l[4096 * 1024];
__device__ __half g_sh[4096 * 128];
__device__ __half g_sl[4096 * 128];
__device__ __half g_w1h[1024 * 128];
__device__ __half g_w1l[1024 * 128];
__device__ __half g_w2h[1024 * 1024];
__device__ __half g_w2l[1024 * 1024];
__device__ __half g_w3h[1024 * 1024];
__device__ __half g_w3l[1024 * 1024];
__device__ __half g_w4h[256 * 1024];
__device__ __half g_w4l[256 * 1024];
__device__ __half g_wlh[1024 * 128];
__device__ __half g_wll[1024 * 128];
__device__ __half g_weh[8192 * 1024];
__device__ __half g_wel[8192 * 1024];
__device__ float g_values[4096 * 256];
__device__ float g_dist[4096 * 256];

__device__ __forceinline__ void* sp(int id) {
    switch (id) {
        case 0:  return g_a0h; case 1:  return g_a0l;
        case 2:  return g_a1h; case 3:  return g_a1l;
        case 4:  return g_sh;  case 5:  return g_sl;
        case 6:  return g_w1h; case 7:  return g_w1l;
        case 8:  return g_w2h; case 9:  return g_w2l;
        case 10: return g_w3h; case 11: return g_w3l;
        case 12: return g_w4h; case 13: return g_w4l;
        case 14: return g_wlh; case 15: return g_wll;
        case 16: return g_weh; case 17: return g_wel;
        case 18: return g_values; default: return g_dist;
    }
}

// ---------------- PTX helpers (base ISA only) ------------------------------
__device__ __forceinline__ uint32_t smem_u32(const void* p) {
    uint32_t a;
    asm("{ .reg .u64 t; cvta.to.shared.u64 t, %1; cvt.u32.u64 %0, t; }" : "=r"(a) : "l"(p));
    return a;
}
__device__ __forceinline__ void cp16(uint32_t dst, const void* src) {
    asm volatile("cp.async.cg.shared.global [%0], [%1], 16;" :: "r"(dst), "l"(src) : "memory");
}
__device__ __forceinline__ void cp_commit() {
    asm volatile("cp.async.commit_group;" ::: "memory");
}
__device__ __forceinline__ void cp_wait0() {
    asm volatile("cp.async.wait_group 0;" ::: "memory");
}
__device__ __forceinline__ void cp_wait1() {
    asm volatile("cp.async.wait_group 1;" ::: "memory");
}
__device__ __forceinline__ void ldm_x4(uint32_t* r, uint32_t addr) {
    asm volatile("ldmatrix.sync.aligned.m8n8.x4.shared.b16 {%0,%1,%2,%3}, [%4];"
                 : "=r"(r[0]), "=r"(r[1]), "=r"(r[2]), "=r"(r[3]) : "r"(addr));
}
__device__ __forceinline__ void mma16816(float* c, const uint32_t* a, const uint32_t* b) {
    asm volatile(
        "mma.sync.aligned.m16n8k16.row.col.f32.f16.f16.f32 "
        "{%0,%1,%2,%3}, {%4,%5,%6,%7}, {%8,%9}, {%0,%1,%2,%3};"
        : "+f"(c[0]), "+f"(c[1]), "+f"(c[2]), "+f"(c[3])
        : "r"(a[0]), "r"(a[1]), "r"(a[2]), "r"(a[3]), "r"(b[0]), "r"(b[1]));
}

__device__ __forceinline__ void split2(float x, __half& h, __half& l) {
    h = __float2half_rn(x);
    l = __float2half_rn(x - __half2float(h));
}
__device__ __forceinline__ float tanh_fast(float x) {
    return __fdividef(2.0f, __expf(-2.0f * x) + 1.0f) - 1.0f;
}

// ---------------- conversion kernels (vectorized) ---------------------------
// s: [4096,128] fp32 -> hi/lo fp16 planes; 4 elems/thread
__global__ void split_kernel(const float* __restrict__ src, int n, int hid, int lid) {
    __half* h = (__half*)sp(hid);
    __half* l = (__half*)sp(lid);
    int i = (blockIdx.x * blockDim.x + threadIdx.x) * 4;
    if (i + 3 < n) {
        float4 v = *(const float4*)(src + i);
        __half h0, l0, h1, l1, h2, l2, h3, l3;
        split2(v.x, h0, l0); split2(v.y, h1, l1);
        split2(v.z, h2, l2); split2(v.w, h3, l3);
        *(__half2*)(h + i)     = __halves2half2(h0, h1);
        *(__half2*)(h + i + 2) = __halves2half2(h2, h3);
        *(__half2*)(l + i)     = __halves2half2(l0, l1);
        *(__half2*)(l + i + 2) = __halves2half2(l2, l3);
    }
}

// W[K][N] fp32 -> out[N][K] fp16 hi (+lo if lid >= 0). 64x64 tiles, 512 thr.
__global__ void transpose_split64(const float* __restrict__ W, int K, int N, int hid, int lid) {
    __shared__ float t[64][65];
    __half* oh = (__half*)sp(hid);
    const int n0 = blockIdx.x * 64, k0 = blockIdx.y * 64;
    const int tx = threadIdx.x;      // 0..63
    const int ty = threadIdx.y;      // 0..7
#pragma unroll
    for (int j = 0; j < 64; j += 8)
        t[ty + j][tx] = W[(size_t)(k0 + ty + j) * N + n0 + tx];
    __syncthreads();
    if (lid >= 0) {
        __half* ol = (__half*)sp(lid);
#pragma unroll
        for (int j = 0; j < 64; j += 8) {
            int r = ty + j;
            size_t o = (size_t)(n0 + r) * K + k0 + tx;
            split2(t[tx][r], oh[o], ol[o]);
        }
    } else {
#pragma unroll
        for (int j = 0; j < 64; j += 8) {
            int r = ty + j;
            oh[(size_t)(n0 + r) * K + k0 + tx] = __float2half_rn(t[tx][r]);
        }
    }
}

// Wexp[256][1024][32] fp32 -> out[n*32+a][1024] fp16 (hi only).
// Block: (n fixed, 64-wide k tile, all 32 a). 512 threads.
__global__ void wexp_split64(const float* __restrict__ W, int hid) {
    __shared__ float t[64][33];
    __half* oh = (__half*)sp(hid);
    const int k0 = blockIdx.x * 64, n = blockIdx.y;
    const int tx = threadIdx.x;      // 0..31 (a)
    const int ty = threadIdx.y;      // 0..15
#pragma unroll
    for (int j = 0; j < 64; j += 16)
        t[ty + j][tx] = W[((size_t)n * 1024 + k0 + ty + j) * 32 + tx];
    __syncthreads();
    const int id = ty * 32 + tx;
    const int c = id & 63;           // k within tile
    const int r0 = id >> 6;          // 0..7
#pragma unroll
    for (int a = r0; a < 32; a += 8)
        oh[(size_t)(n * 32 + a) * 1024 + k0 + c] = __float2half_rn(t[c][a]);
}

// ---------------- generic warp-MMA GEMM (256 thr, 128x128) ------------------
// EPI: 0 = bias+relu -> hi/lo fp16 ; 1 = bias -> fp32
// TA/TB: fp16 planes per operand.
template <int TA, int TB>
struct GemmCfg {
    static constexpr int STAGE = (TA + TB) * 16384;
    static constexpr int SMEM = 1024 + 2 * STAGE;
    static constexpr int MINB = (TA + TB <= 3) ? 2 : 1;
};

template <int EPI, int TA, int TB>
__global__ void __launch_bounds__(256, GemmCfg<TA, TB>::MINB)
mma_gemm(int ahi, int alo, int bhi, int blo,
         const float* __restrict__ bias,
         int o1, int o2, int M, int N, int K)
{
    constexpr int STAGE = GemmCfg<TA, TB>::STAGE;
    constexpr uint32_t AL_OFF = 16384;
    constexpr uint32_t BH_OFF = TA * 16384;
    constexpr uint32_t BL_OFF = BH_OFF + 16384;

    extern __shared__ char smem_raw[];
    const uint32_t sb = (smem_u32(smem_raw) + 1023) & ~1023u;

    const __half* Ah = (const __half*)sp(ahi);
    const __half* Al = (const __half*)sp(alo);
    const __half* Bh = (const __half*)sp(bhi);
    const __half* Bl = (const __half*)sp(blo);

    const int tid = threadIdx.x;
    const int lane = tid & 31;
    const int wid = tid >> 5;
    const int wm = wid >> 2;
    const int wn = wid & 3;
    const int m0 = blockIdx.y * 128;
    const int n0 = blockIdx.x * 128;

    float acc[4][4][4];
#pragma unroll
    for (int i = 0; i < 4; i++)
#pragma unroll
        for (int j = 0; j < 4; j++)
#pragma unroll
            for (int q = 0; q < 4; q++) acc[i][j][q] = 0.f;

    const int C = K >> 6;

    auto issue = [&](int c, int s) {
        const uint32_t st = sb + s * STAGE;
        const int k0 = c * 64;
#pragma unroll
        for (int i = tid; i < 1024; i += 256) {
            int r = i >> 3, seg = i & 7;
            uint32_t off = SWZ((uint32_t)(r * 128 + seg * 16));
            size_t ga = (size_t)(m0 + r) * K + k0 + seg * 8;
            size_t gb = (size_t)(n0 + r) * K + k0 + seg * 8;
            cp16(st + off, Ah + ga);
            if (TA == 2) cp16(st + AL_OFF + off, Al + ga);
            cp16(st + BH_OFF + off, Bh + gb);
            if (TB == 2) cp16(st + BL_OFF + off, Bl + gb);
        }
        cp_commit();
    };

    const int quad = lane >> 3, qi = lane & 7;

    auto compute = [&](int s) {
        const uint32_t st = sb + s * STAGE;
#pragma unroll
        for (int kk = 0; kk < 4; kk++) {
            uint32_t ah[4][4], al[4][4];
#pragma unroll
            for (int mt = 0; mt < 4; mt++) {
                int row = wm * 64 + mt * 16 + (quad & 1) * 8 + qi;
                int colb = (kk * 16 + (quad >> 1) * 8) * 2;
                uint32_t ad = st + SWZ((uint32_t)(row * 128 + colb));
                ldm_x4(ah[mt], ad);
                if (TA == 2) ldm_x4(al[mt], ad + AL_OFF);
            }
            uint32_t bh[4][2], bl[4][2];
#pragma unroll
            for (int p = 0; p < 2; p++) {
                int row = wn * 32 + p * 16 + (quad >> 1) * 8 + qi;
                int colb = (kk * 16 + (quad & 1) * 8) * 2;
                uint32_t bd = st + BH_OFF + SWZ((uint32_t)(row * 128 + colb));
                uint32_t r4[4];
                ldm_x4(r4, bd);
                bh[p * 2][0] = r4[0]; bh[p * 2][1] = r4[1];
                bh[p * 2 + 1][0] = r4[2]; bh[p * 2 + 1][1] = r4[3];
                if (TB == 2) {
                    ldm_x4(r4, bd + 16384);
                    bl[p * 2][0] = r4[0]; bl[p * 2][1] = r4[1];
                    bl[p * 2 + 1][0] = r4[2]; bl[p * 2 + 1][1] = r4[3];
                }
            }
#pragma unroll
            for (int mt = 0; mt < 4; mt++)
#pragma unroll
                for (int nt = 0; nt < 4; nt++) {
                    mma16816(acc[mt][nt], ah[mt], bh[nt]);
                    if (TB == 2) mma16816(acc[mt][nt], ah[mt], bl[nt]);
                    if (TA == 2) mma16816(acc[mt][nt], al[mt], bh[nt]);
                }
        }
    };

    issue(0, 0);
    for (int c = 0; c < C; ++c) {
        if (c + 1 < C) { issue(c + 1, (c + 1) & 1); cp_wait1(); }
        else           { cp_wait0(); }
        __syncthreads();
        compute(c & 1);
        __syncthreads();
    }

    const int r4 = lane >> 2;
    const int cp2 = (lane & 3) * 2;

    if constexpr (EPI == 1) {
        float* o = (float*)sp(o1);
#pragma unroll
        for (int mt = 0; mt < 4; mt++)
#pragma unroll
            for (int nt = 0; nt < 4; nt++) {
                int row = m0 + wm * 64 + mt * 16 + r4;
                int col = n0 + wn * 32 + nt * 8 + cp2;
                float2 v0 = {acc[mt][nt][0] + bias[col], acc[mt][nt][1] + bias[col + 1]};
                float2 v1 = {acc[mt][nt][2] + bias[col], acc[mt][nt][3] + bias[col + 1]};
                *(float2*)(o + (size_t)row * N + col) = v0;
                *(float2*)(o + (size_t)(row + 8) * N + col) = v1;
            }
    } else {
        __half* oh = (__half*)sp(o1);
        __half* ol = (__half*)sp(o2);
#pragma unroll
        for (int mt = 0; mt < 4; mt++)
#pragma unroll
            for (int nt = 0; nt < 4; nt++) {
                int row = m0 + wm * 64 + mt * 16 + r4;
                int col = n0 + wn * 32 + nt * 8 + cp2;
                float b0 = bias[col], b1 = bias[col + 1];
#pragma unroll
                for (int h = 0; h < 2; h++) {
                    int rr = row + h * 8;
                    float y0 = fmaxf(acc[mt][nt][h * 2 + 0] + b0, 0.f);
                    float y1 = fmaxf(acc[mt][nt][h * 2 + 1] + b1, 0.f);
                    __half h0, l0, h1, l1;
                    split2(y0, h0, l0);
                    split2(y1, h1, l1);
                    *(__half2*)(oh + (size_t)rr * N + col) = __halves2half2(h0, h1);
                    *(__half2*)(ol + (size_t)rr * N + col) = __halves2half2(l0, l1);
                }
            }
    }
}

// ---------------- merged L1+loc GEMM (3-term, N=2048 logical) ---------------
// cols [0,1024): s@Wv1+bv1 -> a0 (ids 0,1); cols [1024,2048): s@Wl1+bl1 -> a1 (2,3)
__global__ void __launch_bounds__(256, 1)
mma_dual(int ahi, int alo,
         int b1h, int b1l, const float* __restrict__ bias1, int o1h, int o1l,
         int b2h, int b2l, const float* __restrict__ bias2, int o2h, int o2l,
         int M, int K)
{
    constexpr int STAGE = 4 * 16384;
    constexpr uint32_t AL_OFF = 16384, BH_OFF = 32768, BL_OFF = 49152;

    extern __shared__ char smem_raw[];
    const uint32_t sb = (smem_u32(smem_raw) + 1023) & ~1023u;

    const int n0g = blockIdx.x * 128;
    const bool sec = (n0g >= 1024);
    const int nb0 = sec ? n0g - 1024 : n0g;

    const __half* Ah = (const __half*)sp(ahi);
    const __half* Al = (const __half*)sp(alo);
    const __half* Bh = (const __half*)sp(sec ? b2h : b1h);
    const __half* Bl = (const __half*)sp(sec ? b2l : b1l);
    const float* bias = sec ? bias2 : bias1;
    __half* oh = (__half*)sp(sec ? o2h : o1h);
    __half* ol = (__half*)sp(sec ? o2l : o1l);

    const int tid = threadIdx.x;
    const int lane = tid & 31;
    const int wid = tid >> 5;
    const int wm = wid >> 2;
    const int wn = wid & 3;
    const int m0 = blockIdx.y * 128;

    float acc[4][4][4];
#pragma unroll
    for (int i = 0; i < 4; i++)
#pragma unroll
        for (int j = 0; j < 4; j++)
#pragma unroll
            for (int q = 0; q < 4; q++) acc[i][j][q] = 0.f;

    const int C = K >> 6;

    auto issue = [&](int c, int s) {
        const uint32_t st = sb + s * STAGE;
        const int k0 = c * 64;
#pragma unroll
        for (int i = tid; i < 1024; i += 256) {
            int r = i >> 3, seg = i & 7;
            uint32_t off = SWZ((uint32_t)(r * 128 + seg * 16));
            size_t ga = (size_t)(m0 + r) * K + k0 + seg * 8;
            size_t gb = (size_t)(nb0 + r) * K + k0 + seg * 8;
            cp16(st + off, Ah + ga);
            cp16(st + AL_OFF + off, Al + ga);
            cp16(st + BH_OFF + off, Bh + gb);
            cp16(st + BL_OFF + off, Bl + gb);
        }
        cp_commit();
    };

    const int quad = lane >> 3, qi = lane & 7;

    auto compute = [&](int s) {
        const uint32_t st = sb + s * STAGE;
#pragma unroll
        for (int kk = 0; kk < 4; kk++) {
            uint32_t ah[4][4], al[4][4];
#pragma unroll
            for (int mt = 0; mt < 4; mt++) {
                int row = wm * 64 + mt * 16 + (quad & 1) * 8 + qi;
                int colb = (kk * 16 + (quad >> 1) * 8) * 2;
                uint32_t ad = st + SWZ((uint32_t)(row * 128 + colb));
                ldm_x4(ah[mt], ad);
                ldm_x4(al[mt], ad + AL_OFF);
            }
            uint32_t bh[4][2], bl[4][2];
#pragma unroll
            for (int p = 0; p < 2; p++) {
                int row = wn * 32 + p * 16 + (quad >> 1) * 8 + qi;
                int colb = (kk * 16 + (quad & 1) * 8) * 2;
                uint32_t bd = st + BH_OFF + SWZ((uint32_t)(row * 128 + colb));
                uint32_t r4[4];
                ldm_x4(r4, bd);
                bh[p * 2][0] = r4[0]; bh[p * 2][1] = r4[1];
                bh[p * 2 + 1][0] = r4[2]; bh[p * 2 + 1][1] = r4[3];
                ldm_x4(r4, bd + 16384);
                bl[p * 2][0] = r4[0]; bl[p * 2][1] = r4[1];
                bl[p * 2 + 1][0] = r4[2]; bl[p * 2 + 1][1] = r4[3];
            }
#pragma unroll
            for (int mt = 0; mt < 4; mt++)
#pragma unroll
                for (int nt = 0; nt < 4; nt++) {
                    mma16816(acc[mt][nt], ah[mt], bh[nt]);
                    mma16816(acc[mt][nt], ah[mt], bl[nt]);
                    mma16816(acc[mt][nt], al[mt], bh[nt]);
                }
        }
    };

    issue(0, 0);
    for (int c = 0; c < C; ++c) {
        if (c + 1 < C) { issue(c + 1, (c + 1) & 1); cp_wait1(); }
        else           { cp_wait0(); }
        __syncthreads();
        compute(c & 1);
        __syncthreads();
    }

    const int r4 = lane >> 2;
    const int cp2 = (lane & 3) * 2;
#pragma unroll
    for (int mt = 0; mt < 4; mt++)
#pragma unroll
        for (int nt = 0; nt < 4; nt++) {
            int row = m0 + wm * 64 + mt * 16 + r4;
            int col = nb0 + wn * 32 + nt * 8 + cp2;
            float b0 = bias[col], b1 = bias[col + 1];
#pragma unroll
            for (int h = 0; h < 2; h++) {
                int rr = row + h * 8;
                float y0 = fmaxf(acc[mt][nt][h * 2 + 0] + b0, 0.f);
                float y1 = fmaxf(acc[mt][nt][h * 2 + 1] + b1, 0.f);
                __half h0, l0, h1, l1;
                split2(y0, h0, l0);
                split2(y1, h1, l1);
                *(__half2*)(oh + (size_t)rr * 1024 + col) = __halves2half2(h0, h1);
                *(__half2*)(ol + (size_t)rr * 1024 + col) = __halves2half2(l0, l1);
            }
        }
}

// ---------------- wide expert GEMM (1-term, 128x256 tile, 512 thr) ----------
// D = Ah*Bh ; fused tanh + distance epilogue. Halves A-side L2 traffic.
static constexpr int EXP_STAGE = 49152;                  // A 16KB + B 32KB
static constexpr int EXP_SMEM = 1024 + 2 * EXP_STAGE;
static constexpr uint32_t EXP_B_OFF = 16384;

__global__ void __launch_bounds__(512, 1)
mma_exp(int ahi, int bhi,
        const float* __restrict__ bexp, const float* __restrict__ act,
        int o1, int K)
{
    extern __shared__ char smem_raw[];
    const uint32_t sb = (smem_u32(smem_raw) + 1023) & ~1023u;

    const __half* Ah = (const __half*)sp(ahi);
    const __half* Bh = (const __half*)sp(bhi);

    const int tid = threadIdx.x;
    const int lane = tid & 31;
    const int wid = tid >> 5;       // 0..15
    const int wm = wid >> 3;        // 0..1 : 64-row strip
    const int wn = wid & 7;         // 0..7 : 32-col strip (one centroid)
    const int m0 = blockIdx.y * 128;
    const int n0 = blockIdx.x * 256;

    float acc[4][4][4];
#pragma unroll
    for (int i = 0; i < 4; i++)
#pragma unroll
        for (int j = 0; j < 4; j++)
#pragma unroll
            for (int q = 0; q < 4; q++) acc[i][j][q] = 0.f;

    const int C = K >> 6;

    auto issue = [&](int c, int s) {
        const uint32_t st = sb + s * EXP_STAGE;
        const int k0 = c * 64;
#pragma unroll
        for (int i = tid; i < 1024; i += 512) {
            int r = i >> 3, seg = i & 7;
            uint32_t off = SWZ((uint32_t)(r * 128 + seg * 16));
            cp16(st + off, Ah + (size_t)(m0 + r) * K + k0 + seg * 8);
        }
#pragma unroll
        for (int i = tid; i < 2048; i += 512) {
            int r = i >> 3, seg = i & 7;
            uint32_t off = SWZ((uint32_t)(r * 128 + seg * 16));
            cp16(st + EXP_B_OFF + off, Bh + (size_t)(n0 + r) * K + k0 + seg * 8);
        }
        cp_commit();
    };

    const int quad = lane >> 3, qi = lane & 7;

    auto compute = [&](int s) {
        const uint32_t st = sb + s * EXP_STAGE;
#pragma unroll
        for (int kk = 0; kk < 4; kk++) {
            uint32_t ah[4][4];
#pragma unroll
            for (int mt = 0; mt < 4; mt++) {
                int row = wm * 64 + mt * 16 + (quad & 1) * 8 + qi;
                int colb = (kk * 16 + (quad >> 1) * 8) * 2;
                ldm_x4(ah[mt], st + SWZ((uint32_t)(row * 128 + colb)));
            }
            uint32_t bh[4][2];
#pragma unroll
            for (int p = 0; p < 2; p++) {
                int row = wn * 32 + p * 16 + (quad >> 1) * 8 + qi;
                int colb = (kk * 16 + (quad & 1) * 8) * 2;
                uint32_t r4[4];
                ldm_x4(r4, st + EXP_B_OFF + SWZ((uint32_t)(row * 128 + colb)));
                bh[p * 2][0] = r4[0]; bh[p * 2][1] = r4[1];
                bh[p * 2 + 1][0] = r4[2]; bh[p * 2 + 1][1] = r4[3];
            }
#pragma unroll
            for (int mt = 0; mt < 4; mt++)
#pragma unroll
                for (int nt = 0; nt < 4; nt++)
                    mma16816(acc[mt][nt], ah[mt], bh[nt]);
        }
    };

    issue(0, 0);
    for (int c = 0; c < C; ++c) {
        if (c + 1 < C) { issue(c + 1, (c + 1) & 1); cp_wait1(); }
        else           { cp_wait0(); }
        __syncthreads();
        compute(c & 1);
        __syncthreads();
    }

    // fused tanh + distance epilogue; warp covers one centroid (32 a-dims)
    const int r4 = lane >> 2;
    const int cp2 = (lane & 3) * 2;
    float* dist = (float*)sp(o1);
    const int nc = blockIdx.x * 8 + wn;
#pragma unroll
    for (int mt = 0; mt < 4; mt++) {
#pragma unroll
        for (int h = 0; h < 2; h++) {
            int row = m0 + wm * 64 + mt * 16 + r4 + h * 8;
            float ss = 0.f;
#pragma unroll
            for (int nt = 0; nt < 4; nt++) {
                int col = n0 + wn * 32 + nt * 8 + cp2;
                int ai = nt * 8 + cp2;
                float z0 = acc[mt][nt][h * 2 + 0] + bexp[col];
                float z1 = acc[mt][nt][h * 2 + 1] + bexp[col + 1];
                float d0 = tanh_fast(z0) - act[(size_t)row * 32 + ai];
                float d1 = tanh_fast(z1) - act[(size_t)row * 32 + ai + 1];
                ss += d0 * d0 + d1 * d1;
            }
            ss += __shfl_xor_sync(0xffffffffu, ss, 1);
            ss += __shfl_xor_sync(0xffffffffu, ss, 2);
            if ((lane & 3) == 0)
                dist[(size_t)row * 256 + nc] = sqrtf(ss + 0.01f);
        }
    }
}

// ---------------- finalize: softmax(-dist) . values ------------------------
__global__ void finalize_kernel(float* __restrict__ out) {
    const float* dist = (const float*)sp(19);
    const float* values = (const float*)sp(18);
    const int b = blockIdx.x;
    const int n = threadIdx.x;
    const int lane = n & 31, w = n >> 5;

    float logit = -dist[(size_t)b * 256 + n];
    float v = values[(size_t)b * 256 + n];

    __shared__ float smax[8], s_e[8], s_ev[8];
    float mx = logit;
#pragma unroll
    for (int off = 16; off; off >>= 1)
        mx = fmaxf(mx, __shfl_xor_sync(0xffffffffu, mx, off));
    if (lane == 0) smax[w] = mx;
    __syncthreads();
    float bm = smax[0];
#pragma unroll
    for (int i = 1; i < 8; i++) bm = fmaxf(bm, smax[i]);

    float e = expf(logit - bm);
    float se = e, sev = e * v;
#pragma unroll
    for (int off = 16; off; off >>= 1) {
        se += __shfl_xor_sync(0xffffffffu, se, off);
        sev += __shfl_xor_sync(0xffffffffu, sev, off);
    }
    if (lane == 0) { s_e[w] = se; s_ev[w] = sev; }
    __syncthreads();
    if (n == 0) {
        float te = 0.f, tev = 0.f;
#pragma unroll
        for (int i = 0; i < 8; i++) { te += s_e[i]; tev += s_ev[i]; }
        out[b] = tev / te;
    }
}

// ---------------- launch ----------------------------------------------------
extern "C" void kernel_launch(void* const* d_in, const int* in_sizes, int n_in,
                              void* d_out, int out_size)
{
    const float* s    = (const float*)d_in[0];
    const float* act  = (const float*)d_in[1];
    const float* Wv1  = (const float*)d_in[2];
    const float* bv1  = (const float*)d_in[3];
    const float* Wv2  = (const float*)d_in[4];
    const float* bv2  = (const float*)d_in[5];
    const float* Wv3  = (const float*)d_in[6];
    const float* bv3  = (const float*)d_in[7];
    const float* Wv4  = (const float*)d_in[8];
    const float* bv4  = (const float*)d_in[9];
    const float* Wl1  = (const float*)d_in[10];
    const float* bl1  = (const float*)d_in[11];
    const float* Wexp = (const float*)d_in[12];
    const float* bexp = (const float*)d_in[13];
    float* out = (float*)d_out;

    constexpr int S3 = GemmCfg<2, 2>::SMEM;  // 132KB
    constexpr int S2 = GemmCfg<2, 1>::SMEM;  // 97KB, 2 CTAs/SM

    cudaFuncSetAttribute(mma_gemm<1,2,2>, cudaFuncAttributeMaxDynamicSharedMemorySize, S3);
    cudaFuncSetAttribute(mma_gemm<0,2,1>, cudaFuncAttributeMaxDynamicSharedMemorySize, S2);
    cudaFuncSetAttribute(mma_dual, cudaFuncAttributeMaxDynamicSharedMemorySize, S3);
    cudaFuncSetAttribute(mma_exp, cudaFuncAttributeMaxDynamicSharedMemorySize, EXP_SMEM);

    dim3 t64(64, 8);
    dim3 tw(32, 16);

    // conversions (vectorized)
    split_kernel<<<512, 256>>>(s, 4096 * 128, 4, 5);
    transpose_split64<<<dim3(1024 / 64, 128 / 64),  t64>>>(Wv1, 128, 1024, 6, 7);
    transpose_split64<<<dim3(1024 / 64, 1024 / 64), t64>>>(Wv2, 1024, 1024, 8, -1);
    transpose_split64<<<dim3(1024 / 64, 1024 / 64), t64>>>(Wv3, 1024, 1024, 10, -1);
    transpose_split64<<<dim3(256 / 64, 1024 / 64),  t64>>>(Wv4, 1024, 256, 12, 13);
    transpose_split64<<<dim3(1024 / 64, 128 / 64),  t64>>>(Wl1, 128, 1024, 14, 15);
    wexp_split64<<<dim3(16, 256), tw>>>(Wexp, 16);

    // merged L1 + location (3-term): cols 0-1023 -> a0, 1024-2047 -> a1
    mma_dual<<<dim3(16, 32), 256, S3>>>(4, 5,
                                        6, 7,  bv1, 0, 1,
                                        14, 15, bl1, 2, 3,
                                        4096, 128);

    // value MLP continues: a0 -> a1? No: L2: a0 -> tmp. Use a1? a1 holds loc!
    // L2: a0 -> values-chain scratch; reuse ids carefully:
    //   L2 in=0,1 out=... must not clobber a1 (2,3 = loc hidden, needed by expert).
    //   Expert runs BEFORE L3 overwrite? Simpler: run expert right after dual,
    //   then L2/L3 can reuse a1 freely.
    mma_exp<<<dim3(32, 32), 512, EXP_SMEM>>>(2, 16, bexp, act, 19, 1024);

    // L2 (2-term): a0 -> a1 (loc hidden no longer needed)
    mma_gemm<0,2,1><<<dim3(8, 32), 256, S2>>>(0, 1, 8, 9,   bv2, 2, 3, 4096, 1024, 1024);
    // L3 (2-term): a1 -> a0
    mma_gemm<0,2,1><<<dim3(8, 32), 256, S2>>>(2, 3, 10, 11, bv3, 0, 1, 4096, 1024, 1024);
    // L4 (3-term): a0 -> values
    mma_gemm<1,2,2><<<dim3(2, 32), 256, S3>>>(0, 1, 12, 13, bv4, 18, 0, 4096, 256, 1024);

    finalize_kernel<<<4096, 256>>>(out);
}

// round 13
// speedup vs baseline: 4.5977x; 1.0005x over previous
#include <cuda_runtime.h>
#include <cuda_fp16.h>
#include <math.h>
#include <stdint.h>

// ===========================================================================
// B=4096, S=128, A=32, H=1024, N=256.
// ldmatrix + mma.sync.m16n8k16 + cp.async (base PTX, compute_103-safe).
// Precision plan (calibrated rounds 4-12):
//   L1+loc merged (3-term), L4 (3-term), L2/L3 (2-term), expert (1-term).
// This round: expert uses a 3-stage cp.async pipeline with a single
// __syncthreads per K-chunk (depth-3 makes the trailing barrier redundant).
// ===========================================================================

#define SWZ(o) ((o) ^ (((o) >> 3) & 0x70))

// ---------------- device scratch (allocation-free rule) --------------------
__device__ __half g_a0h[4096 * 1024];
__device__ __half g_a0l[4096 * 1024];
__device__ __half g_a1h[4096 * 1024];
__device__ __half g_a1l[4096 * 1024];
__device__ __half g_sh[4096 * 128];
__device__ __half g_sl[4096 * 128];
__device__ __half g_w1h[1024 * 128];
__device__ __half g_w1l[1024 * 128];
__device__ __half g_w2h[1024 * 1024];
__device__ __half g_w2l[1024 * 1024];
__device__ __half g_w3h[1024 * 1024];
__device__ __half g_w3l[1024 * 1024];
__device__ __half g_w4h[256 * 1024];
__device__ __half g_w4l[256 * 1024];
__device__ __half g_wlh[1024 * 128];
__device__ __half g_wll[1024 * 128];
__device__ __half g_weh[8192 * 1024];
__device__ __half g_wel[8192 * 1024];
__device__ float g_values[4096 * 256];
__device__ float g_dist[4096 * 256];

__device__ __forceinline__ void* sp(int id) {
    switch (id) {
        case 0:  return g_a0h; case 1:  return g_a0l;
        case 2:  return g_a1h; case 3:  return g_a1l;
        case 4:  return g_sh;  case 5:  return g_sl;
        case 6:  return g_w1h; case 7:  return g_w1l;
        case 8:  return g_w2h; case 9:  return g_w2l;
        case 10: return g_w3h; case 11: return g_w3l;
        case 12: return g_w4h; case 13: return g_w4l;
        case 14: return g_wlh; case 15: return g_wll;
        case 16: return g_weh; case 17: return g_wel;
        case 18: return g_values; default: return g_dist;
    }
}

// ---------------- PTX helpers (base ISA only) ------------------------------
__device__ __forceinline__ uint32_t smem_u32(const void* p) {
    uint32_t a;
    asm("{ .reg .u64 t; cvta.to.shared.u64 t, %1; cvt.u32.u64 %0, t; }" : "=r"(a) : "l"(p));
    return a;
}
__device__ __forceinline__ void cp16(uint32_t dst, const void* src) {
    asm volatile("cp.async.cg.shared.global [%0], [%1], 16;" :: "r"(dst), "l"(src) : "memory");
}
__device__ __forceinline__ void cp_commit() {
    asm volatile("cp.async.commit_group;" ::: "memory");
}
__device__ __forceinline__ void cp_wait0() {
    asm volatile("cp.async.wait_group 0;" ::: "memory");
}
__device__ __forceinline__ void cp_wait1() {
    asm volatile("cp.async.wait_group 1;" ::: "memory");
}
__device__ __forceinline__ void ldm_x4(uint32_t* r, uint32_t addr) {
    asm volatile("ldmatrix.sync.aligned.m8n8.x4.shared.b16 {%0,%1,%2,%3}, [%4];"
                 : "=r"(r[0]), "=r"(r[1]), "=r"(r[2]), "=r"(r[3]) : "r"(addr));
}
__device__ __forceinline__ void mma16816(float* c, const uint32_t* a, const uint32_t* b) {
    asm volatile(
        "mma.sync.aligned.m16n8k16.row.col.f32.f16.f16.f32 "
        "{%0,%1,%2,%3}, {%4,%5,%6,%7}, {%8,%9}, {%0,%1,%2,%3};"
        : "+f"(c[0]), "+f"(c[1]), "+f"(c[2]), "+f"(c[3])
        : "r"(a[0]), "r"(a[1]), "r"(a[2]), "r"(a[3]), "r"(b[0]), "r"(b[1]));
}

__device__ __forceinline__ void split2(float x, __half& h, __half& l) {
    h = __float2half_rn(x);
    l = __float2half_rn(x - __half2float(h));
}
__device__ __forceinline__ float tanh_fast(float x) {
    return __fdividef(2.0f, __expf(-2.0f * x) + 1.0f) - 1.0f;
}

// ---------------- conversion kernels (vectorized) ---------------------------
__global__ void split_kernel(const float* __restrict__ src, int n, int hid, int lid) {
    __half* h = (__half*)sp(hid);
    __half* l = (__half*)sp(lid);
    int i = (blockIdx.x * blockDim.x + threadIdx.x) * 4;
    if (i + 3 < n) {
        float4 v = *(const float4*)(src + i);
        __half h0, l0, h1, l1, h2, l2, h3, l3;
        split2(v.x, h0, l0); split2(v.y, h1, l1);
        split2(v.z, h2, l2); split2(v.w, h3, l3);
        *(__half2*)(h + i)     = __halves2half2(h0, h1);
        *(__half2*)(h + i + 2) = __halves2half2(h2, h3);
        *(__half2*)(l + i)     = __halves2half2(l0, l1);
        *(__half2*)(l + i + 2) = __halves2half2(l2, l3);
    }
}

// W[K][N] fp32 -> out[N][K] fp16 hi (+lo if lid >= 0). 64x64 tiles, 512 thr.
__global__ void transpose_split64(const float* __restrict__ W, int K, int N, int hid, int lid) {
    __shared__ float t[64][65];
    __half* oh = (__half*)sp(hid);
    const int n0 = blockIdx.x * 64, k0 = blockIdx.y * 64;
    const int tx = threadIdx.x;
    const int ty = threadIdx.y;
#pragma unroll
    for (int j = 0; j < 64; j += 8)
        t[ty + j][tx] = W[(size_t)(k0 + ty + j) * N + n0 + tx];
    __syncthreads();
    if (lid >= 0) {
        __half* ol = (__half*)sp(lid);
#pragma unroll
        for (int j = 0; j < 64; j += 8) {
            int r = ty + j;
            size_t o = (size_t)(n0 + r) * K + k0 + tx;
            split2(t[tx][r], oh[o], ol[o]);
        }
    } else {
#pragma unroll
        for (int j = 0; j < 64; j += 8) {
            int r = ty + j;
            oh[(size_t)(n0 + r) * K + k0 + tx] = __float2half_rn(t[tx][r]);
        }
    }
}

// Wexp[256][1024][32] fp32 -> out[n*32+a][1024] fp16 (hi only).
__global__ void wexp_split64(const float* __restrict__ W, int hid) {
    __shared__ float t[64][33];
    __half* oh = (__half*)sp(hid);
    const int k0 = blockIdx.x * 64, n = blockIdx.y;
    const int tx = threadIdx.x;
    const int ty = threadIdx.y;
#pragma unroll
    for (int j = 0; j < 64; j += 16)
        t[ty + j][tx] = W[((size_t)n * 1024 + k0 + ty + j) * 32 + tx];
    __syncthreads();
    const int id = ty * 32 + tx;
    const int c = id & 63;
    const int r0 = id >> 6;
#pragma unroll
    for (int a = r0; a < 32; a += 8)
        oh[(size_t)(n * 32 + a) * 1024 + k0 + c] = __float2half_rn(t[c][a]);
}

// ---------------- generic warp-MMA GEMM (256 thr, 128x128, 2-stage) ---------
template <int TA, int TB>
struct GemmCfg {
    static constexpr int STAGE = (TA + TB) * 16384;
    static constexpr int SMEM = 1024 + 2 * STAGE;
    static constexpr int MINB = (TA + TB <= 3) ? 2 : 1;
};

template <int EPI, int TA, int TB>
__global__ void __launch_bounds__(256, GemmCfg<TA, TB>::MINB)
mma_gemm(int ahi, int alo, int bhi, int blo,
         const float* __restrict__ bias,
         int o1, int o2, int M, int N, int K)
{
    constexpr int STAGE = GemmCfg<TA, TB>::STAGE;
    constexpr uint32_t AL_OFF = 16384;
    constexpr uint32_t BH_OFF = TA * 16384;
    constexpr uint32_t BL_OFF = BH_OFF + 16384;

    extern __shared__ char smem_raw[];
    const uint32_t sb = (smem_u32(smem_raw) + 1023) & ~1023u;

    const __half* Ah = (const __half*)sp(ahi);
    const __half* Al = (const __half*)sp(alo);
    const __half* Bh = (const __half*)sp(bhi);
    const __half* Bl = (const __half*)sp(blo);

    const int tid = threadIdx.x;
    const int lane = tid & 31;
    const int wid = tid >> 5;
    const int wm = wid >> 2;
    const int wn = wid & 3;
    const int m0 = blockIdx.y * 128;
    const int n0 = blockIdx.x * 128;

    float acc[4][4][4];
#pragma unroll
    for (int i = 0; i < 4; i++)
#pragma unroll
        for (int j = 0; j < 4; j++)
#pragma unroll
            for (int q = 0; q < 4; q++) acc[i][j][q] = 0.f;

    const int C = K >> 6;

    auto issue = [&](int c, int s) {
        const uint32_t st = sb + s * STAGE;
        const int k0 = c * 64;
#pragma unroll
        for (int i = tid; i < 1024; i += 256) {
            int r = i >> 3, seg = i & 7;
            uint32_t off = SWZ((uint32_t)(r * 128 + seg * 16));
            size_t ga = (size_t)(m0 + r) * K + k0 + seg * 8;
            size_t gb = (size_t)(n0 + r) * K + k0 + seg * 8;
            cp16(st + off, Ah + ga);
            if (TA == 2) cp16(st + AL_OFF + off, Al + ga);
            cp16(st + BH_OFF + off, Bh + gb);
            if (TB == 2) cp16(st + BL_OFF + off, Bl + gb);
        }
        cp_commit();
    };

    const int quad = lane >> 3, qi = lane & 7;

    auto compute = [&](int s) {
        const uint32_t st = sb + s * STAGE;
#pragma unroll
        for (int kk = 0; kk < 4; kk++) {
            uint32_t ah[4][4], al[4][4];
#pragma unroll
            for (int mt = 0; mt < 4; mt++) {
                int row = wm * 64 + mt * 16 + (quad & 1) * 8 + qi;
                int colb = (kk * 16 + (quad >> 1) * 8) * 2;
                uint32_t ad = st + SWZ((uint32_t)(row * 128 + colb));
                ldm_x4(ah[mt], ad);
                if (TA == 2) ldm_x4(al[mt], ad + AL_OFF);
            }
            uint32_t bh[4][2], bl[4][2];
#pragma unroll
            for (int p = 0; p < 2; p++) {
                int row = wn * 32 + p * 16 + (quad >> 1) * 8 + qi;
                int colb = (kk * 16 + (quad & 1) * 8) * 2;
                uint32_t bd = st + BH_OFF + SWZ((uint32_t)(row * 128 + colb));
                uint32_t r4[4];
                ldm_x4(r4, bd);
                bh[p * 2][0] = r4[0]; bh[p * 2][1] = r4[1];
                bh[p * 2 + 1][0] = r4[2]; bh[p * 2 + 1][1] = r4[3];
                if (TB == 2) {
                    ldm_x4(r4, bd + 16384);
                    bl[p * 2][0] = r4[0]; bl[p * 2][1] = r4[1];
                    bl[p * 2 + 1][0] = r4[2]; bl[p * 2 + 1][1] = r4[3];
                }
            }
#pragma unroll
            for (int mt = 0; mt < 4; mt++)
#pragma unroll
                for (int nt = 0; nt < 4; nt++) {
                    mma16816(acc[mt][nt], ah[mt], bh[nt]);
                    if (TB == 2) mma16816(acc[mt][nt], ah[mt], bl[nt]);
                    if (TA == 2) mma16816(acc[mt][nt], al[mt], bh[nt]);
                }
        }
    };

    issue(0, 0);
    for (int c = 0; c < C; ++c) {
        if (c + 1 < C) { issue(c + 1, (c + 1) & 1); cp_wait1(); }
        else           { cp_wait0(); }
        __syncthreads();
        compute(c & 1);
        __syncthreads();
    }

    const int r4 = lane >> 2;
    const int cp2 = (lane & 3) * 2;

    if constexpr (EPI == 1) {
        float* o = (float*)sp(o1);
#pragma unroll
        for (int mt = 0; mt < 4; mt++)
#pragma unroll
            for (int nt = 0; nt < 4; nt++) {
                int row = m0 + wm * 64 + mt * 16 + r4;
                int col = n0 + wn * 32 + nt * 8 + cp2;
                float2 v0 = {acc[mt][nt][0] + bias[col], acc[mt][nt][1] + bias[col + 1]};
                float2 v1 = {acc[mt][nt][2] + bias[col], acc[mt][nt][3] + bias[col + 1]};
                *(float2*)(o + (size_t)row * N + col) = v0;
                *(float2*)(o + (size_t)(row + 8) * N + col) = v1;
            }
    } else {
        __half* oh = (__half*)sp(o1);
        __half* ol = (__half*)sp(o2);
#pragma unroll
        for (int mt = 0; mt < 4; mt++)
#pragma unroll
            for (int nt = 0; nt < 4; nt++) {
                int row = m0 + wm * 64 + mt * 16 + r4;
                int col = n0 + wn * 32 + nt * 8 + cp2;
                float b0 = bias[col], b1 = bias[col + 1];
#pragma unroll
                for (int h = 0; h < 2; h++) {
                    int rr = row + h * 8;
                    float y0 = fmaxf(acc[mt][nt][h * 2 + 0] + b0, 0.f);
                    float y1 = fmaxf(acc[mt][nt][h * 2 + 1] + b1, 0.f);
                    __half h0, l0, h1, l1;
                    split2(y0, h0, l0);
                    split2(y1, h1, l1);
                    *(__half2*)(oh + (size_t)rr * N + col) = __halves2half2(h0, h1);
                    *(__half2*)(ol + (size_t)rr * N + col) = __halves2half2(l0, l1);
                }
            }
    }
}

// ---------------- merged L1+loc GEMM (3-term, N=2048 logical) ---------------
__global__ void __launch_bounds__(256, 1)
mma_dual(int ahi, int alo,
         int b1h, int b1l, const float* __restrict__ bias1, int o1h, int o1l,
         int b2h, int b2l, const float* __restrict__ bias2, int o2h, int o2l,
         int M, int K)
{
    constexpr int STAGE = 4 * 16384;
    constexpr uint32_t AL_OFF = 16384, BH_OFF = 32768, BL_OFF = 49152;

    extern __shared__ char smem_raw[];
    const uint32_t sb = (smem_u32(smem_raw) + 1023) & ~1023u;

    const int n0g = blockIdx.x * 128;
    const bool sec = (n0g >= 1024);
    const int nb0 = sec ? n0g - 1024 : n0g;

    const __half* Ah = (const __half*)sp(ahi);
    const __half* Al = (const __half*)sp(alo);
    const __half* Bh = (const __half*)sp(sec ? b2h : b1h);
    const __half* Bl = (const __half*)sp(sec ? b2l : b1l);
    const float* bias = sec ? bias2 : bias1;
    __half* oh = (__half*)sp(sec ? o2h : o1h);
    __half* ol = (__half*)sp(sec ? o2l : o1l);

    const int tid = threadIdx.x;
    const int lane = tid & 31;
    const int wid = tid >> 5;
    const int wm = wid >> 2;
    const int wn = wid & 3;
    const int m0 = blockIdx.y * 128;

    float acc[4][4][4];
#pragma unroll
    for (int i = 0; i < 4; i++)
#pragma unroll
        for (int j = 0; j < 4; j++)
#pragma unroll
            for (int q = 0; q < 4; q++) acc[i][j][q] = 0.f;

    const int C = K >> 6;

    auto issue = [&](int c, int s) {
        const uint32_t st = sb + s * STAGE;
        const int k0 = c * 64;
#pragma unroll
        for (int i = tid; i < 1024; i += 256) {
            int r = i >> 3, seg = i & 7;
            uint32_t off = SWZ((uint32_t)(r * 128 + seg * 16));
            size_t ga = (size_t)(m0 + r) * K + k0 + seg * 8;
            size_t gb = (size_t)(nb0 + r) * K + k0 + seg * 8;
            cp16(st + off, Ah + ga);
            cp16(st + AL_OFF + off, Al + ga);
            cp16(st + BH_OFF + off, Bh + gb);
            cp16(st + BL_OFF + off, Bl + gb);
        }
        cp_commit();
    };

    const int quad = lane >> 3, qi = lane & 7;

    auto compute = [&](int s) {
        const uint32_t st = sb + s * STAGE;
#pragma unroll
        for (int kk = 0; kk < 4; kk++) {
            uint32_t ah[4][4], al[4][4];
#pragma unroll
            for (int mt = 0; mt < 4; mt++) {
                int row = wm * 64 + mt * 16 + (quad & 1) * 8 + qi;
                int colb = (kk * 16 + (quad >> 1) * 8) * 2;
                uint32_t ad = st + SWZ((uint32_t)(row * 128 + colb));
                ldm_x4(ah[mt], ad);
                ldm_x4(al[mt], ad + AL_OFF);
            }
            uint32_t bh[4][2], bl[4][2];
#pragma unroll
            for (int p = 0; p < 2; p++) {
                int row = wn * 32 + p * 16 + (quad >> 1) * 8 + qi;
                int colb = (kk * 16 + (quad & 1) * 8) * 2;
                uint32_t bd = st + BH_OFF + SWZ((uint32_t)(row * 128 + colb));
                uint32_t r4[4];
                ldm_x4(r4, bd);
                bh[p * 2][0] = r4[0]; bh[p * 2][1] = r4[1];
                bh[p * 2 + 1][0] = r4[2]; bh[p * 2 + 1][1] = r4[3];
                ldm_x4(r4, bd + 16384);
                bl[p * 2][0] = r4[0]; bl[p * 2][1] = r4[1];
                bl[p * 2 + 1][0] = r4[2]; bl[p * 2 + 1][1] = r4[3];
            }
#pragma unroll
            for (int mt = 0; mt < 4; mt++)
#pragma unroll
                for (int nt = 0; nt < 4; nt++) {
                    mma16816(acc[mt][nt], ah[mt], bh[nt]);
                    mma16816(acc[mt][nt], ah[mt], bl[nt]);
                    mma16816(acc[mt][nt], al[mt], bh[nt]);
                }
        }
    };

    issue(0, 0);
    for (int c = 0; c < C; ++c) {
        if (c + 1 < C) { issue(c + 1, (c + 1) & 1); cp_wait1(); }
        else           { cp_wait0(); }
        __syncthreads();
        compute(c & 1);
        __syncthreads();
    }

    const int r4 = lane >> 2;
    const int cp2 = (lane & 3) * 2;
#pragma unroll
    for (int mt = 0; mt < 4; mt++)
#pragma unroll
        for (int nt = 0; nt < 4; nt++) {
            int row = m0 + wm * 64 + mt * 16 + r4;
            int col = nb0 + wn * 32 + nt * 8 + cp2;
            float b0 = bias[col], b1 = bias[col + 1];
#pragma unroll
            for (int h = 0; h < 2; h++) {
                int rr = row + h * 8;
                float y0 = fmaxf(acc[mt][nt][h * 2 + 0] + b0, 0.f);
                float y1 = fmaxf(acc[mt][nt][h * 2 + 1] + b1, 0.f);
                __half h0, l0, h1, l1;
                split2(y0, h0, l0);
                split2(y1, h1, l1);
                *(__half2*)(oh + (size_t)rr * 1024 + col) = __halves2half2(h0, h1);
                *(__half2*)(ol + (size_t)rr * 1024 + col) = __halves2half2(l0, l1);
            }
        }
}

// ---------------- wide expert GEMM (1-term, 128x256, 3-stage, 1 sync) -------
static constexpr int EXP_STAGE = 49152;                  // A 16KB + B 32KB
static constexpr int EXP_SMEM = 1024 + 3 * EXP_STAGE;    // ~145KB, 3 stages
static constexpr uint32_t EXP_B_OFF = 16384;

__global__ void __launch_bounds__(512, 1)
mma_exp(int ahi, int bhi,
        const float* __restrict__ bexp, const float* __restrict__ act,
        int o1, int K)
{
    extern __shared__ char smem_raw[];
    const uint32_t sb = (smem_u32(smem_raw) + 1023) & ~1023u;

    const __half* Ah = (const __half*)sp(ahi);
    const __half* Bh = (const __half*)sp(bhi);

    const int tid = threadIdx.x;
    const int lane = tid & 31;
    const int wid = tid >> 5;       // 0..15
    const int wm = wid >> 3;        // 0..1
    const int wn = wid & 7;         // 0..7 (one centroid each)
    const int m0 = blockIdx.y * 128;
    const int n0 = blockIdx.x * 256;

    float acc[4][4][4];
#pragma unroll
    for (int i = 0; i < 4; i++)
#pragma unroll
        for (int j = 0; j < 4; j++)
#pragma unroll
            for (int q = 0; q < 4; q++) acc[i][j][q] = 0.f;

    const int C = K >> 6;

    auto issue = [&](int c, int s) {
        const uint32_t st = sb + s * EXP_STAGE;
        const int k0 = c * 64;
#pragma unroll
        for (int i = tid; i < 1024; i += 512) {
            int r = i >> 3, seg = i & 7;
            uint32_t off = SWZ((uint32_t)(r * 128 + seg * 16));
            cp16(st + off, Ah + (size_t)(m0 + r) * K + k0 + seg * 8);
        }
#pragma unroll
        for (int i = tid; i < 2048; i += 512) {
            int r = i >> 3, seg = i & 7;
            uint32_t off = SWZ((uint32_t)(r * 128 + seg * 16));
            cp16(st + EXP_B_OFF + off, Bh + (size_t)(n0 + r) * K + k0 + seg * 8);
        }
        cp_commit();
    };

    const int quad = lane >> 3, qi = lane & 7;

    auto compute = [&](int s) {
        const uint32_t st = sb + s * EXP_STAGE;
#pragma unroll
        for (int kk = 0; kk < 4; kk++) {
            uint32_t ah[4][4];
#pragma unroll
            for (int mt = 0; mt < 4; mt++) {
                int row = wm * 64 + mt * 16 + (quad & 1) * 8 + qi;
                int colb = (kk * 16 + (quad >> 1) * 8) * 2;
                ldm_x4(ah[mt], st + SWZ((uint32_t)(row * 128 + colb)));
            }
            uint32_t bh[4][2];
#pragma unroll
            for (int p = 0; p < 2; p++) {
                int row = wn * 32 + p * 16 + (quad >> 1) * 8 + qi;
                int colb = (kk * 16 + (quad & 1) * 8) * 2;
                uint32_t r4[4];
                ldm_x4(r4, st + EXP_B_OFF + SWZ((uint32_t)(row * 128 + colb)));
                bh[p * 2][0] = r4[0]; bh[p * 2][1] = r4[1];
                bh[p * 2 + 1][0] = r4[2]; bh[p * 2 + 1][1] = r4[3];
            }
#pragma unroll
            for (int mt = 0; mt < 4; mt++)
#pragma unroll
                for (int nt = 0; nt < 4; nt++)
                    mma16816(acc[mt][nt], ah[mt], bh[nt]);
        }
    };

    // 3-stage pipeline, ONE barrier per chunk.
    // Invariant: a warp past sync(c) implies all warps completed compute(c-1),
    // so stage (c+2)%3 == stage (c-1)%3 is free to overwrite after compute(c).
    issue(0, 0);
    issue(1, 1);
    for (int c = 0; c < C; ++c) {
        if (c + 1 < C) cp_wait1();   // chunk c complete (c+1 may remain in flight)
        else           cp_wait0();   // last chunk: drain
        __syncthreads();
        compute(c % 3);
        if (c + 2 < C) issue(c + 2, (c + 2) % 3);
    }

    // fused tanh + distance epilogue; warp covers one centroid (32 a-dims)
    const int r4 = lane >> 2;
    const int cp2 = (lane & 3) * 2;
    float* dist = (float*)sp(o1);
    const int nc = blockIdx.x * 8 + wn;
#pragma unroll
    for (int mt = 0; mt < 4; mt++) {
#pragma unroll
        for (int h = 0; h < 2; h++) {
            int row = m0 + wm * 64 + mt * 16 + r4 + h * 8;
            float ss = 0.f;
#pragma unroll
            for (int nt = 0; nt < 4; nt++) {
                int col = n0 + wn * 32 + nt * 8 + cp2;
                int ai = nt * 8 + cp2;
                float z0 = acc[mt][nt][h * 2 + 0] + bexp[col];
                float z1 = acc[mt][nt][h * 2 + 1] + bexp[col + 1];
                float d0 = tanh_fast(z0) - act[(size_t)row * 32 + ai];
                float d1 = tanh_fast(z1) - act[(size_t)row * 32 + ai + 1];
                ss += d0 * d0 + d1 * d1;
            }
            ss += __shfl_xor_sync(0xffffffffu, ss, 1);
            ss += __shfl_xor_sync(0xffffffffu, ss, 2);
            if ((lane & 3) == 0)
                dist[(size_t)row * 256 + nc] = sqrtf(ss + 0.01f);
        }
    }
}

// ---------------- finalize: softmax(-dist) . values ------------------------
__global__ void finalize_kernel(float* __restrict__ out) {
    const float* dist = (const float*)sp(19);
    const float* values = (const float*)sp(18);
    const int b = blockIdx.x;
    const int n = threadIdx.x;
    const int lane = n & 31, w = n >> 5;

    float logit = -dist[(size_t)b * 256 + n];
    float v = values[(size_t)b * 256 + n];

    __shared__ float smax[8], s_e[8], s_ev[8];
    float mx = logit;
#pragma unroll
    for (int off = 16; off; off >>= 1)
        mx = fmaxf(mx, __shfl_xor_sync(0xffffffffu, mx, off));
    if (lane == 0) smax[w] = mx;
    __syncthreads();
    float bm = smax[0];
#pragma unroll
    for (int i = 1; i < 8; i++) bm = fmaxf(bm, smax[i]);

    float e = expf(logit - bm);
    float se = e, sev = e * v;
#pragma unroll
    for (int off = 16; off; off >>= 1) {
        se += __shfl_xor_sync(0xffffffffu, se, off);
        sev += __shfl_xor_sync(0xffffffffu, sev, off);
    }
    if (lane == 0) { s_e[w] = se; s_ev[w] = sev; }
    __syncthreads();
    if (n == 0) {
        float te = 0.f, tev = 0.f;
#pragma unroll
        for (int i = 0; i < 8; i++) { te += s_e[i]; tev += s_ev[i]; }
        out[b] = tev / te;
    }
}

// ---------------- launch ----------------------------------------------------
extern "C" void kernel_launch(void* const* d_in, const int* in_sizes, int n_in,
                              void* d_out, int out_size)
{
    const float* s    = (const float*)d_in[0];
    const float* act  = (const float*)d_in[1];
    const float* Wv1  = (const float*)d_in[2];
    const float* bv1  = (const float*)d_in[3];
    const float* Wv2  = (const float*)d_in[4];
    const float* bv2  = (const float*)d_in[5];
    const float* Wv3  = (const float*)d_in[6];
    const float* bv3  = (const float*)d_in[7];
    const float* Wv4  = (const float*)d_in[8];
    const float* bv4  = (const float*)d_in[9];
    const float* Wl1  = (const float*)d_in[10];
    const float* bl1  = (const float*)d_in[11];
    const float* Wexp = (const float*)d_in[12];
    const float* bexp = (const float*)d_in[13];
    float* out = (float*)d_out;

    constexpr int S3 = GemmCfg<2, 2>::SMEM;  // 132KB
    constexpr int S2 = GemmCfg<2, 1>::SMEM;  // 97KB, 2 CTAs/SM

    cudaFuncSetAttribute(mma_gemm<1,2,2>, cudaFuncAttributeMaxDynamicSharedMemorySize, S3);
    cudaFuncSetAttribute(mma_gemm<0,2,1>, cudaFuncAttributeMaxDynamicSharedMemorySize, S2);
    cudaFuncSetAttribute(mma_dual, cudaFuncAttributeMaxDynamicSharedMemorySize, S3);
    cudaFuncSetAttribute(mma_exp, cudaFuncAttributeMaxDynamicSharedMemorySize, EXP_SMEM);

    dim3 t64(64, 8);
    dim3 tw(32, 16);

    // conversions (vectorized)
    split_kernel<<<512, 256>>>(s, 4096 * 128, 4, 5);
    transpose_split64<<<dim3(1024 / 64, 128 / 64),  t64>>>(Wv1, 128, 1024, 6, 7);
    transpose_split64<<<dim3(1024 / 64, 1024 / 64), t64>>>(Wv2, 1024, 1024, 8, -1);
    transpose_split64<<<dim3(1024 / 64, 1024 / 64), t64>>>(Wv3, 1024, 1024, 10, -1);
    transpose_split64<<<dim3(256 / 64, 1024 / 64),  t64>>>(Wv4, 1024, 256, 12, 13);
    transpose_split64<<<dim3(1024 / 64, 128 / 64),  t64>>>(Wl1, 128, 1024, 14, 15);
    wexp_split64<<<dim3(16, 256), tw>>>(Wexp, 16);

    // merged L1 + location (3-term): cols 0-1023 -> a0, 1024-2047 -> a1
    mma_dual<<<dim3(16, 32), 256, S3>>>(4, 5,
                                        6, 7,  bv1, 0, 1,
                                        14, 15, bl1, 2, 3,
                                        4096, 128);

    // expert GEMM + fused tanh/dist (1-term, 3-stage pipeline)
    // runs right after dual so L2/L3 can later reuse a1
    mma_exp<<<dim3(32, 32), 512, EXP_SMEM>>>(2, 16, bexp, act, 19, 1024);

    // L2 (2-term): a0 -> a1 (loc hidden no longer needed)
    mma_gemm<0,2,1><<<dim3(8, 32), 256, S2>>>(0, 1, 8, 9,   bv2, 2, 3, 4096, 1024, 1024);
    // L3 (2-term): a1 -> a0
    mma_gemm<0,2,1><<<dim3(8, 32), 256, S2>>>(2, 3, 10, 11, bv3, 0, 1, 4096, 1024, 1024);
    // L4 (3-term): a0 -> values
    mma_gemm<1,2,2><<<dim3(2, 32), 256, S3>>>(0, 1, 12, 13, bv4, 18, 0, 4096, 256, 1024);

    finalize_kernel<<<4096, 256>>>(out);
}

// round 14
// speedup vs baseline: 5.3476x; 1.1631x over previous
#include <cuda_runtime.h>
#include <cuda_fp16.h>
#include <math.h>
#include <stdint.h>

// ===========================================================================
// B=4096, S=128, A=32, H=1024, N=256.
// ldmatrix + mma.sync.m16n8k16 + cp.async (base PTX, compute_103-safe).
// Precision plan (calibrated rounds 4-13):
//   L1+loc merged (3-term), L4 (3-term), L2/L3 (1-term), expert (1-term).
//   EPI-0 always stores fp32-accumulated activations as hi+lo, so term
//   reduction only injects the zero-mean input-rounding of that GEMM.
// This round: L2/L3 1-term (halves their MACs, 66KB smem, 2 CTAs/SM) and
// all five weight transposes merged into one launch.
// ===========================================================================

#define SWZ(o) ((o) ^ (((o) >> 3) & 0x70))

// ---------------- device scratch (allocation-free rule) --------------------
__device__ __half g_a0h[4096 * 1024];
__device__ __half g_a0l[4096 * 1024];
__device__ __half g_a1h[4096 * 1024];
__device__ __half g_a1l[4096 * 1024];
__device__ __half g_sh[4096 * 128];
__device__ __half g_sl[4096 * 128];
__device__ __half g_w1h[1024 * 128];
__device__ __half g_w1l[1024 * 128];
__device__ __half g_w2h[1024 * 1024];
__device__ __half g_w2l[1024 * 1024];
__device__ __half g_w3h[1024 * 1024];
__device__ __half g_w3l[1024 * 1024];
__device__ __half g_w4h[256 * 1024];
__device__ __half g_w4l[256 * 1024];
__device__ __half g_wlh[1024 * 128];
__device__ __half g_wll[1024 * 128];
__device__ __half g_weh[8192 * 1024];
__device__ __half g_wel[8192 * 1024];
__device__ float g_values[4096 * 256];
__device__ float g_dist[4096 * 256];

__device__ __forceinline__ void* sp(int id) {
    switch (id) {
        case 0:  return g_a0h; case 1:  return g_a0l;
        case 2:  return g_a1h; case 3:  return g_a1l;
        case 4:  return g_sh;  case 5:  return g_sl;
        case 6:  return g_w1h; case 7:  return g_w1l;
        case 8:  return g_w2h; case 9:  return g_w2l;
        case 10: return g_w3h; case 11: return g_w3l;
        case 12: return g_w4h; case 13: return g_w4l;
        case 14: return g_wlh; case 15: return g_wll;
        case 16: return g_weh; case 17: return g_wel;
        case 18: return g_values; default: return g_dist;
    }
}

// ---------------- PTX helpers (base ISA only) ------------------------------
__device__ __forceinline__ uint32_t smem_u32(const void* p) {
    uint32_t a;
    asm("{ .reg .u64 t; cvta.to.shared.u64 t, %1; cvt.u32.u64 %0, t; }" : "=r"(a) : "l"(p));
    return a;
}
__device__ __forceinline__ void cp16(uint32_t dst, const void* src) {
    asm volatile("cp.async.cg.shared.global [%0], [%1], 16;" :: "r"(dst), "l"(src) : "memory");
}
__device__ __forceinline__ void cp_commit() {
    asm volatile("cp.async.commit_group;" ::: "memory");
}
__device__ __forceinline__ void cp_wait0() {
    asm volatile("cp.async.wait_group 0;" ::: "memory");
}
__device__ __forceinline__ void cp_wait1() {
    asm volatile("cp.async.wait_group 1;" ::: "memory");
}
__device__ __forceinline__ void ldm_x4(uint32_t* r, uint32_t addr) {
    asm volatile("ldmatrix.sync.aligned.m8n8.x4.shared.b16 {%0,%1,%2,%3}, [%4];"
                 : "=r"(r[0]), "=r"(r[1]), "=r"(r[2]), "=r"(r[3]) : "r"(addr));
}
__device__ __forceinline__ void mma16816(float* c, const uint32_t* a, const uint32_t* b) {
    asm volatile(
        "mma.sync.aligned.m16n8k16.row.col.f32.f16.f16.f32 "
        "{%0,%1,%2,%3}, {%4,%5,%6,%7}, {%8,%9}, {%0,%1,%2,%3};"
        : "+f"(c[0]), "+f"(c[1]), "+f"(c[2]), "+f"(c[3])
        : "r"(a[0]), "r"(a[1]), "r"(a[2]), "r"(a[3]), "r"(b[0]), "r"(b[1]));
}

__device__ __forceinline__ void split2(float x, __half& h, __half& l) {
    h = __float2half_rn(x);
    l = __float2half_rn(x - __half2float(h));
}
__device__ __forceinline__ float tanh_fast(float x) {
    return __fdividef(2.0f, __expf(-2.0f * x) + 1.0f) - 1.0f;
}

// ---------------- conversion kernels ---------------------------------------
__global__ void split_kernel(const float* __restrict__ src, int n, int hid, int lid) {
    __half* h = (__half*)sp(hid);
    __half* l = (__half*)sp(lid);
    int i = (blockIdx.x * blockDim.x + threadIdx.x) * 4;
    if (i + 3 < n) {
        float4 v = *(const float4*)(src + i);
        __half h0, l0, h1, l1, h2, l2, h3, l3;
        split2(v.x, h0, l0); split2(v.y, h1, l1);
        split2(v.z, h2, l2); split2(v.w, h3, l3);
        *(__half2*)(h + i)     = __halves2half2(h0, h1);
        *(__half2*)(h + i + 2) = __halves2half2(h2, h3);
        *(__half2*)(l + i)     = __halves2half2(l0, l1);
        *(__half2*)(l + i + 2) = __halves2half2(l2, l3);
    }
}

// All five weight transposes in ONE launch. Each 64x64 tile block transposes
// W[K][N] fp32 -> out[N][K] fp16 hi (+lo if lid >= 0). 512 thr (64x8).
struct TAll {
    const float* W[5];
    int K[5], N[5], hid[5], lid[5], base[5], nbx[5];
};

__global__ void transpose_all(TAll p) {
    __shared__ float t[64][65];
    const int b = blockIdx.x;
    int i;
    if      (b >= p.base[4]) i = 4;
    else if (b >= p.base[3]) i = 3;
    else if (b >= p.base[2]) i = 2;
    else if (b >= p.base[1]) i = 1;
    else                     i = 0;
    const int local = b - p.base[i];
    const int n0 = (local % p.nbx[i]) * 64;
    const int k0 = (local / p.nbx[i]) * 64;
    const float* W = p.W[i];
    const int K = p.K[i], N = p.N[i];
    __half* oh = (__half*)sp(p.hid[i]);
    const int lid = p.lid[i];

    const int tx = threadIdx.x;      // 0..63
    const int ty = threadIdx.y;      // 0..7
#pragma unroll
    for (int j = 0; j < 64; j += 8)
        t[ty + j][tx] = W[(size_t)(k0 + ty + j) * N + n0 + tx];
    __syncthreads();
    if (lid >= 0) {
        __half* ol = (__half*)sp(lid);
#pragma unroll
        for (int j = 0; j < 64; j += 8) {
            int r = ty + j;
            size_t o = (size_t)(n0 + r) * K + k0 + tx;
            split2(t[tx][r], oh[o], ol[o]);
        }
    } else {
#pragma unroll
        for (int j = 0; j < 64; j += 8) {
            int r = ty + j;
            oh[(size_t)(n0 + r) * K + k0 + tx] = __float2half_rn(t[tx][r]);
        }
    }
}

// Wexp[256][1024][32] fp32 -> out[n*32+a][1024] fp16 (hi only).
__global__ void wexp_split64(const float* __restrict__ W, int hid) {
    __shared__ float t[64][33];
    __half* oh = (__half*)sp(hid);
    const int k0 = blockIdx.x * 64, n = blockIdx.y;
    const int tx = threadIdx.x;
    const int ty = threadIdx.y;
#pragma unroll
    for (int j = 0; j < 64; j += 16)
        t[ty + j][tx] = W[((size_t)n * 1024 + k0 + ty + j) * 32 + tx];
    __syncthreads();
    const int id = ty * 32 + tx;
    const int c = id & 63;
    const int r0 = id >> 6;
#pragma unroll
    for (int a = r0; a < 32; a += 8)
        oh[(size_t)(n * 32 + a) * 1024 + k0 + c] = __float2half_rn(t[c][a]);
}

// ---------------- generic warp-MMA GEMM (256 thr, 128x128, 2-stage) ---------
template <int TA, int TB>
struct GemmCfg {
    static constexpr int STAGE = (TA + TB) * 16384;
    static constexpr int SMEM = 1024 + 2 * STAGE;
    static constexpr int MINB = (TA + TB <= 3) ? 2 : 1;
};

template <int EPI, int TA, int TB>
__global__ void __launch_bounds__(256, GemmCfg<TA, TB>::MINB)
mma_gemm(int ahi, int alo, int bhi, int blo,
         const float* __restrict__ bias,
         int o1, int o2, int M, int N, int K)
{
    constexpr int STAGE = GemmCfg<TA, TB>::STAGE;
    constexpr uint32_t AL_OFF = 16384;
    constexpr uint32_t BH_OFF = TA * 16384;
    constexpr uint32_t BL_OFF = BH_OFF + 16384;

    extern __shared__ char smem_raw[];
    const uint32_t sb = (smem_u32(smem_raw) + 1023) & ~1023u;

    const __half* Ah = (const __half*)sp(ahi);
    const __half* Al = (const __half*)sp(alo);
    const __half* Bh = (const __half*)sp(bhi);
    const __half* Bl = (const __half*)sp(blo);

    const int tid = threadIdx.x;
    const int lane = tid & 31;
    const int wid = tid >> 5;
    const int wm = wid >> 2;
    const int wn = wid & 3;
    const int m0 = blockIdx.y * 128;
    const int n0 = blockIdx.x * 128;

    float acc[4][4][4];
#pragma unroll
    for (int i = 0; i < 4; i++)
#pragma unroll
        for (int j = 0; j < 4; j++)
#pragma unroll
            for (int q = 0; q < 4; q++) acc[i][j][q] = 0.f;

    const int C = K >> 6;

    auto issue = [&](int c, int s) {
        const uint32_t st = sb + s * STAGE;
        const int k0 = c * 64;
#pragma unroll
        for (int i = tid; i < 1024; i += 256) {
            int r = i >> 3, seg = i & 7;
            uint32_t off = SWZ((uint32_t)(r * 128 + seg * 16));
            size_t ga = (size_t)(m0 + r) * K + k0 + seg * 8;
            size_t gb = (size_t)(n0 + r) * K + k0 + seg * 8;
            cp16(st + off, Ah + ga);
            if (TA == 2) cp16(st + AL_OFF + off, Al + ga);
            cp16(st + BH_OFF + off, Bh + gb);
            if (TB == 2) cp16(st + BL_OFF + off, Bl + gb);
        }
        cp_commit();
    };

    const int quad = lane >> 3, qi = lane & 7;

    auto compute = [&](int s) {
        const uint32_t st = sb + s * STAGE;
#pragma unroll
        for (int kk = 0; kk < 4; kk++) {
            uint32_t ah[4][4], al[4][4];
#pragma unroll
            for (int mt = 0; mt < 4; mt++) {
                int row = wm * 64 + mt * 16 + (quad & 1) * 8 + qi;
                int colb = (kk * 16 + (quad >> 1) * 8) * 2;
                uint32_t ad = st + SWZ((uint32_t)(row * 128 + colb));
                ldm_x4(ah[mt], ad);
                if (TA == 2) ldm_x4(al[mt], ad + AL_OFF);
            }
            uint32_t bh[4][2], bl[4][2];
#pragma unroll
            for (int p = 0; p < 2; p++) {
                int row = wn * 32 + p * 16 + (quad >> 1) * 8 + qi;
                int colb = (kk * 16 + (quad & 1) * 8) * 2;
                uint32_t bd = st + BH_OFF + SWZ((uint32_t)(row * 128 + colb));
                uint32_t r4[4];
                ldm_x4(r4, bd);
                bh[p * 2][0] = r4[0]; bh[p * 2][1] = r4[1];
                bh[p * 2 + 1][0] = r4[2]; bh[p * 2 + 1][1] = r4[3];
                if (TB == 2) {
                    ldm_x4(r4, bd + 16384);
                    bl[p * 2][0] = r4[0]; bl[p * 2][1] = r4[1];
                    bl[p * 2 + 1][0] = r4[2]; bl[p * 2 + 1][1] = r4[3];
                }
            }
#pragma unroll
            for (int mt = 0; mt < 4; mt++)
#pragma unroll
                for (int nt = 0; nt < 4; nt++) {
                    mma16816(acc[mt][nt], ah[mt], bh[nt]);
                    if (TB == 2) mma16816(acc[mt][nt], ah[mt], bl[nt]);
                    if (TA == 2) mma16816(acc[mt][nt], al[mt], bh[nt]);
                }
        }
    };

    issue(0, 0);
    for (int c = 0; c < C; ++c) {
        if (c + 1 < C) { issue(c + 1, (c + 1) & 1); cp_wait1(); }
        else           { cp_wait0(); }
        __syncthreads();
        compute(c & 1);
        __syncthreads();
    }

    const int r4 = lane >> 2;
    const int cp2 = (lane & 3) * 2;

    if constexpr (EPI == 1) {
        float* o = (float*)sp(o1);
#pragma unroll
        for (int mt = 0; mt < 4; mt++)
#pragma unroll
            for (int nt = 0; nt < 4; nt++) {
                int row = m0 + wm * 64 + mt * 16 + r4;
                int col = n0 + wn * 32 + nt * 8 + cp2;
                float2 v0 = {acc[mt][nt][0] + bias[col], acc[mt][nt][1] + bias[col + 1]};
                float2 v1 = {acc[mt][nt][2] + bias[col], acc[mt][nt][3] + bias[col + 1]};
                *(float2*)(o + (size_t)row * N + col) = v0;
                *(float2*)(o + (size_t)(row + 8) * N + col) = v1;
            }
    } else {
        __half* oh = (__half*)sp(o1);
        __half* ol = (__half*)sp(o2);
#pragma unroll
        for (int mt = 0; mt < 4; mt++)
#pragma unroll
            for (int nt = 0; nt < 4; nt++) {
                int row = m0 + wm * 64 + mt * 16 + r4;
                int col = n0 + wn * 32 + nt * 8 + cp2;
                float b0 = bias[col], b1 = bias[col + 1];
#pragma unroll
                for (int h = 0; h < 2; h++) {
                    int rr = row + h * 8;
                    float y0 = fmaxf(acc[mt][nt][h * 2 + 0] + b0, 0.f);
                    float y1 = fmaxf(acc[mt][nt][h * 2 + 1] + b1, 0.f);
                    __half h0, l0, h1, l1;
                    split2(y0, h0, l0);
                    split2(y1, h1, l1);
                    *(__half2*)(oh + (size_t)rr * N + col) = __halves2half2(h0, h1);
                    *(__half2*)(ol + (size_t)rr * N + col) = __halves2half2(l0, l1);
                }
            }
    }
}

// ---------------- merged L1+loc GEMM (3-term, N=2048 logical) ---------------
__global__ void __launch_bounds__(256, 1)
mma_dual(int ahi, int alo,
         int b1h, int b1l, const float* __restrict__ bias1, int o1h, int o1l,
         int b2h, int b2l, const float* __restrict__ bias2, int o2h, int o2l,
         int M, int K)
{
    constexpr int STAGE = 4 * 16384;
    constexpr uint32_t AL_OFF = 16384, BH_OFF = 32768, BL_OFF = 49152;

    extern __shared__ char smem_raw[];
    const uint32_t sb = (smem_u32(smem_raw) + 1023) & ~1023u;

    const int n0g = blockIdx.x * 128;
    const bool sec = (n0g >= 1024);
    const int nb0 = sec ? n0g - 1024 : n0g;

    const __half* Ah = (const __half*)sp(ahi);
    const __half* Al = (const __half*)sp(alo);
    const __half* Bh = (const __half*)sp(sec ? b2h : b1h);
    const __half* Bl = (const __half*)sp(sec ? b2l : b1l);
    const float* bias = sec ? bias2 : bias1;
    __half* oh = (__half*)sp(sec ? o2h : o1h);
    __half* ol = (__half*)sp(sec ? o2l : o1l);

    const int tid = threadIdx.x;
    const int lane = tid & 31;
    const int wid = tid >> 5;
    const int wm = wid >> 2;
    const int wn = wid & 3;
    const int m0 = blockIdx.y * 128;

    float acc[4][4][4];
#pragma unroll
    for (int i = 0; i < 4; i++)
#pragma unroll
        for (int j = 0; j < 4; j++)
#pragma unroll
            for (int q = 0; q < 4; q++) acc[i][j][q] = 0.f;

    const int C = K >> 6;

    auto issue = [&](int c, int s) {
        const uint32_t st = sb + s * STAGE;
        const int k0 = c * 64;
#pragma unroll
        for (int i = tid; i < 1024; i += 256) {
            int r = i >> 3, seg = i & 7;
            uint32_t off = SWZ((uint32_t)(r * 128 + seg * 16));
            size_t ga = (size_t)(m0 + r) * K + k0 + seg * 8;
            size_t gb = (size_t)(nb0 + r) * K + k0 + seg * 8;
            cp16(st + off, Ah + ga);
            cp16(st + AL_OFF + off, Al + ga);
            cp16(st + BH_OFF + off, Bh + gb);
            cp16(st + BL_OFF + off, Bl + gb);
        }
        cp_commit();
    };

    const int quad = lane >> 3, qi = lane & 7;

    auto compute = [&](int s) {
        const uint32_t st = sb + s * STAGE;
#pragma unroll
        for (int kk = 0; kk < 4; kk++) {
            uint32_t ah[4][4], al[4][4];
#pragma unroll
            for (int mt = 0; mt < 4; mt++) {
                int row = wm * 64 + mt * 16 + (quad & 1) * 8 + qi;
                int colb = (kk * 16 + (quad >> 1) * 8) * 2;
                uint32_t ad = st + SWZ((uint32_t)(row * 128 + colb));
                ldm_x4(ah[mt], ad);
                ldm_x4(al[mt], ad + AL_OFF);
            }
            uint32_t bh[4][2], bl[4][2];
#pragma unroll
            for (int p = 0; p < 2; p++) {
                int row = wn * 32 + p * 16 + (quad >> 1) * 8 + qi;
                int colb = (kk * 16 + (quad & 1) * 8) * 2;
                uint32_t bd = st + BH_OFF + SWZ((uint32_t)(row * 128 + colb));
                uint32_t r4[4];
                ldm_x4(r4, bd);
                bh[p * 2][0] = r4[0]; bh[p * 2][1] = r4[1];
                bh[p * 2 + 1][0] = r4[2]; bh[p * 2 + 1][1] = r4[3];
                ldm_x4(r4, bd + 16384);
                bl[p * 2][0] = r4[0]; bl[p * 2][1] = r4[1];
                bl[p * 2 + 1][0] = r4[2]; bl[p * 2 + 1][1] = r4[3];
            }
#pragma unroll
            for (int mt = 0; mt < 4; mt++)
#pragma unroll
                for (int nt = 0; nt < 4; nt++) {
                    mma16816(acc[mt][nt], ah[mt], bh[nt]);
                    mma16816(acc[mt][nt], ah[mt], bl[nt]);
                    mma16816(acc[mt][nt], al[mt], bh[nt]);
                }
        }
    };

    issue(0, 0);
    for (int c = 0; c < C; ++c) {
        if (c + 1 < C) { issue(c + 1, (c + 1) & 1); cp_wait1(); }
        else           { cp_wait0(); }
        __syncthreads();
        compute(c & 1);
        __syncthreads();
    }

    const int r4 = lane >> 2;
    const int cp2 = (lane & 3) * 2;
#pragma unroll
    for (int mt = 0; mt < 4; mt++)
#pragma unroll
        for (int nt = 0; nt < 4; nt++) {
            int row = m0 + wm * 64 + mt * 16 + r4;
            int col = nb0 + wn * 32 + nt * 8 + cp2;
            float b0 = bias[col], b1 = bias[col + 1];
#pragma unroll
            for (int h = 0; h < 2; h++) {
                int rr = row + h * 8;
                float y0 = fmaxf(acc[mt][nt][h * 2 + 0] + b0, 0.f);
                float y1 = fmaxf(acc[mt][nt][h * 2 + 1] + b1, 0.f);
                __half h0, l0, h1, l1;
                split2(y0, h0, l0);
                split2(y1, h1, l1);
                *(__half2*)(oh + (size_t)rr * 1024 + col) = __halves2half2(h0, h1);
                *(__half2*)(ol + (size_t)rr * 1024 + col) = __halves2half2(l0, l1);
            }
        }
}

// ---------------- wide expert GEMM (1-term, 128x256, 3-stage, 1 sync) -------
static constexpr int EXP_STAGE = 49152;                  // A 16KB + B 32KB
static constexpr int EXP_SMEM = 1024 + 3 * EXP_STAGE;    // ~145KB, 3 stages
static constexpr uint32_t EXP_B_OFF = 16384;

__global__ void __launch_bounds__(512, 1)
mma_exp(int ahi, int bhi,
        const float* __restrict__ bexp, const float* __restrict__ act,
        int o1, int K)
{
    extern __shared__ char smem_raw[];
    const uint32_t sb = (smem_u32(smem_raw) + 1023) & ~1023u;

    const __half* Ah = (const __half*)sp(ahi);
    const __half* Bh = (const __half*)sp(bhi);

    const int tid = threadIdx.x;
    const int lane = tid & 31;
    const int wid = tid >> 5;       // 0..15
    const int wm = wid >> 3;        // 0..1
    const int wn = wid & 7;         // 0..7 (one centroid each)
    const int m0 = blockIdx.y * 128;
    const int n0 = blockIdx.x * 256;

    float acc[4][4][4];
#pragma unroll
    for (int i = 0; i < 4; i++)
#pragma unroll
        for (int j = 0; j < 4; j++)
#pragma unroll
            for (int q = 0; q < 4; q++) acc[i][j][q] = 0.f;

    const int C = K >> 6;

    auto issue = [&](int c, int s) {
        const uint32_t st = sb + s * EXP_STAGE;
        const int k0 = c * 64;
#pragma unroll
        for (int i = tid; i < 1024; i += 512) {
            int r = i >> 3, seg = i & 7;
            uint32_t off = SWZ((uint32_t)(r * 128 + seg * 16));
            cp16(st + off, Ah + (size_t)(m0 + r) * K + k0 + seg * 8);
        }
#pragma unroll
        for (int i = tid; i < 2048; i += 512) {
            int r = i >> 3, seg = i & 7;
            uint32_t off = SWZ((uint32_t)(r * 128 + seg * 16));
            cp16(st + EXP_B_OFF + off, Bh + (size_t)(n0 + r) * K + k0 + seg * 8);
        }
        cp_commit();
    };

    const int quad = lane >> 3, qi = lane & 7;

    auto compute = [&](int s) {
        const uint32_t st = sb + s * EXP_STAGE;
#pragma unroll
        for (int kk = 0; kk < 4; kk++) {
            uint32_t ah[4][4];
#pragma unroll
            for (int mt = 0; mt < 4; mt++) {
                int row = wm * 64 + mt * 16 + (quad & 1) * 8 + qi;
                int colb = (kk * 16 + (quad >> 1) * 8) * 2;
                ldm_x4(ah[mt], st + SWZ((uint32_t)(row * 128 + colb)));
            }
            uint32_t bh[4][2];
#pragma unroll
            for (int p = 0; p < 2; p++) {
                int row = wn * 32 + p * 16 + (quad >> 1) * 8 + qi;
                int colb = (kk * 16 + (quad & 1) * 8) * 2;
                uint32_t r4[4];
                ldm_x4(r4, st + EXP_B_OFF + SWZ((uint32_t)(row * 128 + colb)));
                bh[p * 2][0] = r4[0]; bh[p * 2][1] = r4[1];
                bh[p * 2 + 1][0] = r4[2]; bh[p * 2 + 1][1] = r4[3];
            }
#pragma unroll
            for (int mt = 0; mt < 4; mt++)
#pragma unroll
                for (int nt = 0; nt < 4; nt++)
                    mma16816(acc[mt][nt], ah[mt], bh[nt]);
        }
    };

    // 3-stage pipeline, one barrier per chunk.
    issue(0, 0);
    issue(1, 1);
    for (int c = 0; c < C; ++c) {
        if (c + 1 < C) cp_wait1();
        else           cp_wait0();
        __syncthreads();
        compute(c % 3);
        if (c + 2 < C) issue(c + 2, (c + 2) % 3);
    }

    const int r4 = lane >> 2;
    const int cp2 = (lane & 3) * 2;
    float* dist = (float*)sp(o1);
    const int nc = blockIdx.x * 8 + wn;
#pragma unroll
    for (int mt = 0; mt < 4; mt++) {
#pragma unroll
        for (int h = 0; h < 2; h++) {
            int row = m0 + wm * 64 + mt * 16 + r4 + h * 8;
            float ss = 0.f;
#pragma unroll
            for (int nt = 0; nt < 4; nt++) {
                int col = n0 + wn * 32 + nt * 8 + cp2;
                int ai = nt * 8 + cp2;
                float z0 = acc[mt][nt][h * 2 + 0] + bexp[col];
                float z1 = acc[mt][nt][h * 2 + 1] + bexp[col + 1];
                float d0 = tanh_fast(z0) - act[(size_t)row * 32 + ai];
                float d1 = tanh_fast(z1) - act[(size_t)row * 32 + ai + 1];
                ss += d0 * d0 + d1 * d1;
            }
            ss += __shfl_xor_sync(0xffffffffu, ss, 1);
            ss += __shfl_xor_sync(0xffffffffu, ss, 2);
            if ((lane & 3) == 0)
                dist[(size_t)row * 256 + nc] = sqrtf(ss + 0.01f);
        }
    }
}

// ---------------- finalize: softmax(-dist) . values ------------------------
__global__ void finalize_kernel(float* __restrict__ out) {
    const float* dist = (const float*)sp(19);
    const float* values = (const float*)sp(18);
    const int b = blockIdx.x;
    const int n = threadIdx.x;
    const int lane = n & 31, w = n >> 5;

    float logit = -dist[(size_t)b * 256 + n];
    float v = values[(size_t)b * 256 + n];

    __shared__ float smax[8], s_e[8], s_ev[8];
    float mx = logit;
#pragma unroll
    for (int off = 16; off; off >>= 1)
        mx = fmaxf(mx, __shfl_xor_sync(0xffffffffu, mx, off));
    if (lane == 0) smax[w] = mx;
    __syncthreads();
    float bm = smax[0];
#pragma unroll
    for (int i = 1; i < 8; i++) bm = fmaxf(bm, smax[i]);

    float e = expf(logit - bm);
    float se = e, sev = e * v;
#pragma unroll
    for (int off = 16; off; off >>= 1) {
        se += __shfl_xor_sync(0xffffffffu, se, off);
        sev += __shfl_xor_sync(0xffffffffu, sev, off);
    }
    if (lane == 0) { s_e[w] = se; s_ev[w] = sev; }
    __syncthreads();
    if (n == 0) {
        float te = 0.f, tev = 0.f;
#pragma unroll
        for (int i = 0; i < 8; i++) { te += s_e[i]; tev += s_ev[i]; }
        out[b] = tev / te;
    }
}

// ---------------- launch ----------------------------------------------------
extern "C" void kernel_launch(void* const* d_in, const int* in_sizes, int n_in,
                              void* d_out, int out_size)
{
    const float* s    = (const float*)d_in[0];
    const float* act  = (const float*)d_in[1];
    const float* Wv1  = (const float*)d_in[2];
    const float* bv1  = (const float*)d_in[3];
    const float* Wv2  = (const float*)d_in[4];
    const float* bv2  = (const float*)d_in[5];
    const float* Wv3  = (const float*)d_in[6];
    const float* bv3  = (const float*)d_in[7];
    const float* Wv4  = (const float*)d_in[8];
    const float* bv4  = (const float*)d_in[9];
    const float* Wl1  = (const float*)d_in[10];
    const float* bl1  = (const float*)d_in[11];
    const float* Wexp = (const float*)d_in[12];
    const float* bexp = (const float*)d_in[13];
    float* out = (float*)d_out;

    constexpr int S3 = GemmCfg<2, 2>::SMEM;  // 132KB, 1 CTA/SM
    constexpr int S1 = GemmCfg<1, 1>::SMEM;  // 66KB,  2 CTAs/SM

    cudaFuncSetAttribute(mma_gemm<1,2,2>, cudaFuncAttributeMaxDynamicSharedMemorySize, S3);
    cudaFuncSetAttribute(mma_gemm<0,1,1>, cudaFuncAttributeMaxDynamicSharedMemorySize, S1);
    cudaFuncSetAttribute(mma_dual, cudaFuncAttributeMaxDynamicSharedMemorySize, S3);
    cudaFuncSetAttribute(mma_exp, cudaFuncAttributeMaxDynamicSharedMemorySize, EXP_SMEM);

    dim3 t64(64, 8);
    dim3 tw(32, 16);

    // conversions: s-split, merged weight transposes, wexp
    split_kernel<<<512, 256>>>(s, 4096 * 128, 4, 5);

    TAll ta;
    // Wv1 [128,1024] -> w1 h/l : nbx=16, nby=2,  blocks 32
    ta.W[0] = Wv1;  ta.K[0] = 128;  ta.N[0] = 1024; ta.hid[0] = 6;  ta.lid[0] = 7;  ta.base[0] = 0;   ta.nbx[0] = 16;
    // Wv2 [1024,1024] -> w2 h    : 256 blocks
    ta.W[1] = Wv2;  ta.K[1] = 1024; ta.N[1] = 1024; ta.hid[1] = 8;  ta.lid[1] = -1; ta.base[1] = 32;  ta.nbx[1] = 16;
    // Wv3 [1024,1024] -> w3 h    : 256 blocks
    ta.W[2] = Wv3;  ta.K[2] = 1024; ta.N[2] = 1024; ta.hid[2] = 10; ta.lid[2] = -1; ta.base[2] = 288; ta.nbx[2] = 16;
    // Wv4 [1024,256] -> w4 h/l   : nbx=4, nby=16, 64 blocks
    ta.W[3] = Wv4;  ta.K[3] = 1024; ta.N[3] = 256;  ta.hid[3] = 12; ta.lid[3] = 13; ta.base[3] = 544; ta.nbx[3] = 4;
    // Wl1 [128,1024] -> wl h/l   : 32 blocks
    ta.W[4] = Wl1;  ta.K[4] = 128;  ta.N[4] = 1024; ta.hid[4] = 14; ta.lid[4] = 15; ta.base[4] = 608; ta.nbx[4] = 16;
    transpose_all<<<640, t64>>>(ta);

    wexp_split64<<<dim3(16, 256), tw>>>(Wexp, 16);

    // merged L1 + location (3-term): cols 0-1023 -> a0, 1024-2047 -> a1
    mma_dual<<<dim3(16, 32), 256, S3>>>(4, 5,
                                        6, 7,  bv1, 0, 1,
                                        14, 15, bl1, 2, 3,
                                        4096, 128);

    // expert GEMM + fused tanh/dist (1-term, 3-stage pipeline)
    mma_exp<<<dim3(32, 32), 512, EXP_SMEM>>>(2, 16, bexp, act, 19, 1024);

    // L2 (1-term): a0 -> a1 (loc hidden no longer needed)
    mma_gemm<0,1,1><<<dim3(8, 32), 256, S1>>>(0, 1, 8, 9,   bv2, 2, 3, 4096, 1024, 1024);
    // L3 (1-term): a1 -> a0
    mma_gemm<0,1,1><<<dim3(8, 32), 256, S1>>>(2, 3, 10, 11, bv3, 0, 1, 4096, 1024, 1024);
    // L4 (3-term): a0 -> values
    mma_gemm<1,2,2><<<dim3(2, 32), 256, S3>>>(0, 1, 12, 13, bv4, 18, 0, 4096, 256, 1024);

    finalize_kernel<<<4096, 256>>>(out);
}

// round 15
// speedup vs baseline: 5.3714x; 1.0044x over previous
#include <cuda_runtime.h>
#include <cuda_fp16.h>
#include <math.h>
#include <stdint.h>

// ===========================================================================
// B=4096, S=128, A=32, H=1024, N=256.
// ldmatrix + mma.sync.m16n8k16 + cp.async (base PTX, compute_103-safe).
// Precision plan (calibrated rounds 4-14, frozen):
//   L1+loc merged (3-term), L4 (3-term), L2/L3 (1-term), expert (1-term).
// This round (no numeric changes):
//   - mma_dual single-buffered (66KB) -> 2 CTAs/SM (was 3.46 waves @ occ 12%)
//   - L2/L3 use single-sync 3-stage pipeline (97KB, still 2 CTAs/SM)
// ===========================================================================

#define SWZ(o) ((o) ^ (((o) >> 3) & 0x70))

// ---------------- device scratch (allocation-free rule) --------------------
__device__ __half g_a0h[4096 * 1024];
__device__ __half g_a0l[4096 * 1024];
__device__ __half g_a1h[4096 * 1024];
__device__ __half g_a1l[4096 * 1024];
__device__ __half g_sh[4096 * 128];
__device__ __half g_sl[4096 * 128];
__device__ __half g_w1h[1024 * 128];
__device__ __half g_w1l[1024 * 128];
__device__ __half g_w2h[1024 * 1024];
__device__ __half g_w2l[1024 * 1024];
__device__ __half g_w3h[1024 * 1024];
__device__ __half g_w3l[1024 * 1024];
__device__ __half g_w4h[256 * 1024];
__device__ __half g_w4l[256 * 1024];
__device__ __half g_wlh[1024 * 128];
__device__ __half g_wll[1024 * 128];
__device__ __half g_weh[8192 * 1024];
__device__ __half g_wel[8192 * 1024];
__device__ float g_values[4096 * 256];
__device__ float g_dist[4096 * 256];

__device__ __forceinline__ void* sp(int id) {
    switch (id) {
        case 0:  return g_a0h; case 1:  return g_a0l;
        case 2:  return g_a1h; case 3:  return g_a1l;
        case 4:  return g_sh;  case 5:  return g_sl;
        case 6:  return g_w1h; case 7:  return g_w1l;
        case 8:  return g_w2h; case 9:  return g_w2l;
        case 10: return g_w3h; case 11: return g_w3l;
        case 12: return g_w4h; case 13: return g_w4l;
        case 14: return g_wlh; case 15: return g_wll;
        case 16: return g_weh; case 17: return g_wel;
        case 18: return g_values; default: return g_dist;
    }
}

// ---------------- PTX helpers (base ISA only) ------------------------------
__device__ __forceinline__ uint32_t smem_u32(const void* p) {
    uint32_t a;
    asm("{ .reg .u64 t; cvta.to.shared.u64 t, %1; cvt.u32.u64 %0, t; }" : "=r"(a) : "l"(p));
    return a;
}
__device__ __forceinline__ void cp16(uint32_t dst, const void* src) {
    asm volatile("cp.async.cg.shared.global [%0], [%1], 16;" :: "r"(dst), "l"(src) : "memory");
}
__device__ __forceinline__ void cp_commit() {
    asm volatile("cp.async.commit_group;" ::: "memory");
}
__device__ __forceinline__ void cp_wait0() {
    asm volatile("cp.async.wait_group 0;" ::: "memory");
}
__device__ __forceinline__ void cp_wait1() {
    asm volatile("cp.async.wait_group 1;" ::: "memory");
}
__device__ __forceinline__ void ldm_x4(uint32_t* r, uint32_t addr) {
    asm volatile("ldmatrix.sync.aligned.m8n8.x4.shared.b16 {%0,%1,%2,%3}, [%4];"
                 : "=r"(r[0]), "=r"(r[1]), "=r"(r[2]), "=r"(r[3]) : "r"(addr));
}
__device__ __forceinline__ void mma16816(float* c, const uint32_t* a, const uint32_t* b) {
    asm volatile(
        "mma.sync.aligned.m16n8k16.row.col.f32.f16.f16.f32 "
        "{%0,%1,%2,%3}, {%4,%5,%6,%7}, {%8,%9}, {%0,%1,%2,%3};"
        : "+f"(c[0]), "+f"(c[1]), "+f"(c[2]), "+f"(c[3])
        : "r"(a[0]), "r"(a[1]), "r"(a[2]), "r"(a[3]), "r"(b[0]), "r"(b[1]));
}

__device__ __forceinline__ void split2(float x, __half& h, __half& l) {
    h = __float2half_rn(x);
    l = __float2half_rn(x - __half2float(h));
}
__device__ __forceinline__ float tanh_fast(float x) {
    return __fdividef(2.0f, __expf(-2.0f * x) + 1.0f) - 1.0f;
}

// ---------------- conversion kernels ---------------------------------------
__global__ void split_kernel(const float* __restrict__ src, int n, int hid, int lid) {
    __half* h = (__half*)sp(hid);
    __half* l = (__half*)sp(lid);
    int i = (blockIdx.x * blockDim.x + threadIdx.x) * 4;
    if (i + 3 < n) {
        float4 v = *(const float4*)(src + i);
        __half h0, l0, h1, l1, h2, l2, h3, l3;
        split2(v.x, h0, l0); split2(v.y, h1, l1);
        split2(v.z, h2, l2); split2(v.w, h3, l3);
        *(__half2*)(h + i)     = __halves2half2(h0, h1);
        *(__half2*)(h + i + 2) = __halves2half2(h2, h3);
        *(__half2*)(l + i)     = __halves2half2(l0, l1);
        *(__half2*)(l + i + 2) = __halves2half2(l2, l3);
    }
}

// All five weight transposes in ONE launch.
struct TAll {
    const float* W[5];
    int K[5], N[5], hid[5], lid[5], base[5], nbx[5];
};

__global__ void transpose_all(TAll p) {
    __shared__ float t[64][65];
    const int b = blockIdx.x;
    int i;
    if      (b >= p.base[4]) i = 4;
    else if (b >= p.base[3]) i = 3;
    else if (b >= p.base[2]) i = 2;
    else if (b >= p.base[1]) i = 1;
    else                     i = 0;
    const int local = b - p.base[i];
    const int n0 = (local % p.nbx[i]) * 64;
    const int k0 = (local / p.nbx[i]) * 64;
    const float* W = p.W[i];
    const int K = p.K[i], N = p.N[i];
    __half* oh = (__half*)sp(p.hid[i]);
    const int lid = p.lid[i];

    const int tx = threadIdx.x;
    const int ty = threadIdx.y;
#pragma unroll
    for (int j = 0; j < 64; j += 8)
        t[ty + j][tx] = W[(size_t)(k0 + ty + j) * N + n0 + tx];
    __syncthreads();
    if (lid >= 0) {
        __half* ol = (__half*)sp(lid);
#pragma unroll
        for (int j = 0; j < 64; j += 8) {
            int r = ty + j;
            size_t o = (size_t)(n0 + r) * K + k0 + tx;
            split2(t[tx][r], oh[o], ol[o]);
        }
    } else {
#pragma unroll
        for (int j = 0; j < 64; j += 8) {
            int r = ty + j;
            oh[(size_t)(n0 + r) * K + k0 + tx] = __float2half_rn(t[tx][r]);
        }
    }
}

// Wexp[256][1024][32] fp32 -> out[n*32+a][1024] fp16 (hi only).
__global__ void wexp_split64(const float* __restrict__ W, int hid) {
    __shared__ float t[64][33];
    __half* oh = (__half*)sp(hid);
    const int k0 = blockIdx.x * 64, n = blockIdx.y;
    const int tx = threadIdx.x;
    const int ty = threadIdx.y;
#pragma unroll
    for (int j = 0; j < 64; j += 16)
        t[ty + j][tx] = W[((size_t)n * 1024 + k0 + ty + j) * 32 + tx];
    __syncthreads();
    const int id = ty * 32 + tx;
    const int c = id & 63;
    const int r0 = id >> 6;
#pragma unroll
    for (int a = r0; a < 32; a += 8)
        oh[(size_t)(n * 32 + a) * 1024 + k0 + c] = __float2half_rn(t[c][a]);
}

// ---------------- generic warp-MMA GEMM (256 thr, 128x128) ------------------
// EPI: 0 = bias+relu -> hi/lo fp16 ; 1 = bias -> fp32
// TA/TB: fp16 planes per operand. STAGES: 2 (ping-pong) or 3 (single-sync).
template <int TA, int TB, int STAGES>
struct GemmCfg {
    static constexpr int STAGE = (TA + TB) * 16384;
    static constexpr int SMEM = 1024 + STAGES * STAGE;
    static constexpr int MINB = (SMEM <= 102400) ? 2 : 1;
};

template <int EPI, int TA, int TB, int STAGES>
__global__ void __launch_bounds__(256, GemmCfg<TA, TB, STAGES>::MINB)
mma_gemm(int ahi, int alo, int bhi, int blo,
         const float* __restrict__ bias,
         int o1, int o2, int M, int N, int K)
{
    constexpr int STAGE = GemmCfg<TA, TB, STAGES>::STAGE;
    constexpr uint32_t AL_OFF = 16384;
    constexpr uint32_t BH_OFF = TA * 16384;
    constexpr uint32_t BL_OFF = BH_OFF + 16384;

    extern __shared__ char smem_raw[];
    const uint32_t sb = (smem_u32(smem_raw) + 1023) & ~1023u;

    const __half* Ah = (const __half*)sp(ahi);
    const __half* Al = (const __half*)sp(alo);
    const __half* Bh = (const __half*)sp(bhi);
    const __half* Bl = (const __half*)sp(blo);

    const int tid = threadIdx.x;
    const int lane = tid & 31;
    const int wid = tid >> 5;
    const int wm = wid >> 2;
    const int wn = wid & 3;
    const int m0 = blockIdx.y * 128;
    const int n0 = blockIdx.x * 128;

    float acc[4][4][4];
#pragma unroll
    for (int i = 0; i < 4; i++)
#pragma unroll
        for (int j = 0; j < 4; j++)
#pragma unroll
            for (int q = 0; q < 4; q++) acc[i][j][q] = 0.f;

    const int C = K >> 6;

    auto issue = [&](int c, int s) {
        const uint32_t st = sb + s * STAGE;
        const int k0 = c * 64;
#pragma unroll
        for (int i = tid; i < 1024; i += 256) {
            int r = i >> 3, seg = i & 7;
            uint32_t off = SWZ((uint32_t)(r * 128 + seg * 16));
            size_t ga = (size_t)(m0 + r) * K + k0 + seg * 8;
            size_t gb = (size_t)(n0 + r) * K + k0 + seg * 8;
            cp16(st + off, Ah + ga);
            if (TA == 2) cp16(st + AL_OFF + off, Al + ga);
            cp16(st + BH_OFF + off, Bh + gb);
            if (TB == 2) cp16(st + BL_OFF + off, Bl + gb);
        }
        cp_commit();
    };

    const int quad = lane >> 3, qi = lane & 7;

    auto compute = [&](int s) {
        const uint32_t st = sb + s * STAGE;
#pragma unroll
        for (int kk = 0; kk < 4; kk++) {
            uint32_t ah[4][4], al[4][4];
#pragma unroll
            for (int mt = 0; mt < 4; mt++) {
                int row = wm * 64 + mt * 16 + (quad & 1) * 8 + qi;
                int colb = (kk * 16 + (quad >> 1) * 8) * 2;
                uint32_t ad = st + SWZ((uint32_t)(row * 128 + colb));
                ldm_x4(ah[mt], ad);
                if (TA == 2) ldm_x4(al[mt], ad + AL_OFF);
            }
            uint32_t bh[4][2], bl[4][2];
#pragma unroll
            for (int p = 0; p < 2; p++) {
                int row = wn * 32 + p * 16 + (quad >> 1) * 8 + qi;
                int colb = (kk * 16 + (quad & 1) * 8) * 2;
                uint32_t bd = st + BH_OFF + SWZ((uint32_t)(row * 128 + colb));
                uint32_t r4[4];
                ldm_x4(r4, bd);
                bh[p * 2][0] = r4[0]; bh[p * 2][1] = r4[1];
                bh[p * 2 + 1][0] = r4[2]; bh[p * 2 + 1][1] = r4[3];
                if (TB == 2) {
                    ldm_x4(r4, bd + 16384);
                    bl[p * 2][0] = r4[0]; bl[p * 2][1] = r4[1];
                    bl[p * 2 + 1][0] = r4[2]; bl[p * 2 + 1][1] = r4[3];
                }
            }
#pragma unroll
            for (int mt = 0; mt < 4; mt++)
#pragma unroll
                for (int nt = 0; nt < 4; nt++) {
                    mma16816(acc[mt][nt], ah[mt], bh[nt]);
                    if (TB == 2) mma16816(acc[mt][nt], ah[mt], bl[nt]);
                    if (TA == 2) mma16816(acc[mt][nt], al[mt], bh[nt]);
                }
        }
    };

    if constexpr (STAGES == 3) {
        // single-sync depth-3 pipeline (invariant proven in mma_exp)
        issue(0, 0);
        if (C > 1) issue(1, 1);
        for (int c = 0; c < C; ++c) {
            if (c + 1 < C) cp_wait1();
            else           cp_wait0();
            __syncthreads();
            compute(c % 3);
            if (c + 2 < C) issue(c + 2, (c + 2) % 3);
        }
    } else {
        issue(0, 0);
        for (int c = 0; c < C; ++c) {
            if (c + 1 < C) { issue(c + 1, (c + 1) & 1); cp_wait1(); }
            else           { cp_wait0(); }
            __syncthreads();
            compute(c & 1);
            __syncthreads();
        }
    }

    const int r4 = lane >> 2;
    const int cp2 = (lane & 3) * 2;

    if constexpr (EPI == 1) {
        float* o = (float*)sp(o1);
#pragma unroll
        for (int mt = 0; mt < 4; mt++)
#pragma unroll
            for (int nt = 0; nt < 4; nt++) {
                int row = m0 + wm * 64 + mt * 16 + r4;
                int col = n0 + wn * 32 + nt * 8 + cp2;
                float2 v0 = {acc[mt][nt][0] + bias[col], acc[mt][nt][1] + bias[col + 1]};
                float2 v1 = {acc[mt][nt][2] + bias[col], acc[mt][nt][3] + bias[col + 1]};
                *(float2*)(o + (size_t)row * N + col) = v0;
                *(float2*)(o + (size_t)(row + 8) * N + col) = v1;
            }
    } else {
        __half* oh = (__half*)sp(o1);
        __half* ol = (__half*)sp(o2);
#pragma unroll
        for (int mt = 0; mt < 4; mt++)
#pragma unroll
            for (int nt = 0; nt < 4; nt++) {
                int row = m0 + wm * 64 + mt * 16 + r4;
                int col = n0 + wn * 32 + nt * 8 + cp2;
                float b0 = bias[col], b1 = bias[col + 1];
#pragma unroll
                for (int h = 0; h < 2; h++) {
                    int rr = row + h * 8;
                    float y0 = fmaxf(acc[mt][nt][h * 2 + 0] + b0, 0.f);
                    float y1 = fmaxf(acc[mt][nt][h * 2 + 1] + b1, 0.f);
                    __half h0, l0, h1, l1;
                    split2(y0, h0, l0);
                    split2(y1, h1, l1);
                    *(__half2*)(oh + (size_t)rr * N + col) = __halves2half2(h0, h1);
                    *(__half2*)(ol + (size_t)rr * N + col) = __halves2half2(l0, l1);
                }
            }
    }
}

// ---------------- merged L1+loc GEMM (3-term, single-buffered, 2 CTA/SM) ----
// K=128 -> only 2 chunks; latency hidden by the co-resident CTA, not stages.
static constexpr int DUAL_STAGE = 4 * 16384;             // 64KB
static constexpr int DUAL_SMEM = 1024 + DUAL_STAGE;      // 66KB -> 2 CTAs/SM

__global__ void __launch_bounds__(256, 2)
mma_dual(int ahi, int alo,
         int b1h, int b1l, const float* __restrict__ bias1, int o1h, int o1l,
         int b2h, int b2l, const float* __restrict__ bias2, int o2h, int o2l,
         int M, int K)
{
    constexpr uint32_t AL_OFF = 16384, BH_OFF = 32768, BL_OFF = 49152;

    extern __shared__ char smem_raw[];
    const uint32_t sb = (smem_u32(smem_raw) + 1023) & ~1023u;

    const int n0g = blockIdx.x * 128;
    const bool sec = (n0g >= 1024);
    const int nb0 = sec ? n0g - 1024 : n0g;

    const __half* Ah = (const __half*)sp(ahi);
    const __half* Al = (const __half*)sp(alo);
    const __half* Bh = (const __half*)sp(sec ? b2h : b1h);
    const __half* Bl = (const __half*)sp(sec ? b2l : b1l);
    const float* bias = sec ? bias2 : bias1;
    __half* oh = (__half*)sp(sec ? o2h : o1h);
    __half* ol = (__half*)sp(sec ? o2l : o1l);

    const int tid = threadIdx.x;
    const int lane = tid & 31;
    const int wid = tid >> 5;
    const int wm = wid >> 2;
    const int wn = wid & 3;
    const int m0 = blockIdx.y * 128;

    float acc[4][4][4];
#pragma unroll
    for (int i = 0; i < 4; i++)
#pragma unroll
        for (int j = 0; j < 4; j++)
#pragma unroll
            for (int q = 0; q < 4; q++) acc[i][j][q] = 0.f;

    const int C = K >> 6;

    auto issue = [&](int c) {
        const uint32_t st = sb;
        const int k0 = c * 64;
#pragma unroll
        for (int i = tid; i < 1024; i += 256) {
            int r = i >> 3, seg = i & 7;
            uint32_t off = SWZ((uint32_t)(r * 128 + seg * 16));
            size_t ga = (size_t)(m0 + r) * K + k0 + seg * 8;
            size_t gb = (size_t)(nb0 + r) * K + k0 + seg * 8;
            cp16(st + off, Ah + ga);
            cp16(st + AL_OFF + off, Al + ga);
            cp16(st + BH_OFF + off, Bh + gb);
            cp16(st + BL_OFF + off, Bl + gb);
        }
        cp_commit();
    };

    const int quad = lane >> 3, qi = lane & 7;

    auto compute = [&]() {
        const uint32_t st = sb;
#pragma unroll
        for (int kk = 0; kk < 4; kk++) {
            uint32_t ah[4][4], al[4][4];
#pragma unroll
            for (int mt = 0; mt < 4; mt++) {
                int row = wm * 64 + mt * 16 + (quad & 1) * 8 + qi;
                int colb = (kk * 16 + (quad >> 1) * 8) * 2;
                uint32_t ad = st + SWZ((uint32_t)(row * 128 + colb));
                ldm_x4(ah[mt], ad);
                ldm_x4(al[mt], ad + AL_OFF);
            }
            uint32_t bh[4][2], bl[4][2];
#pragma unroll
            for (int p = 0; p < 2; p++) {
                int row = wn * 32 + p * 16 + (quad >> 1) * 8 + qi;
                int colb = (kk * 16 + (quad & 1) * 8) * 2;
                uint32_t bd = st + BH_OFF + SWZ((uint32_t)(row * 128 + colb));
                uint32_t r4[4];
                ldm_x4(r4, bd);
                bh[p * 2][0] = r4[0]; bh[p * 2][1] = r4[1];
                bh[p * 2 + 1][0] = r4[2]; bh[p * 2 + 1][1] = r4[3];
                ldm_x4(r4, bd + 16384);
                bl[p * 2][0] = r4[0]; bl[p * 2][1] = r4[1];
                bl[p * 2 + 1][0] = r4[2]; bl[p * 2 + 1][1] = r4[3];
            }
#pragma unroll
            for (int mt = 0; mt < 4; mt++)
#pragma unroll
                for (int nt = 0; nt < 4; nt++) {
                    mma16816(acc[mt][nt], ah[mt], bh[nt]);
                    mma16816(acc[mt][nt], ah[mt], bl[nt]);
                    mma16816(acc[mt][nt], al[mt], bh[nt]);
                }
        }
    };

    for (int c = 0; c < C; ++c) {
        issue(c);
        cp_wait0();
        __syncthreads();
        compute();
        __syncthreads();
    }

    const int r4 = lane >> 2;
    const int cp2 = (lane & 3) * 2;
#pragma unroll
    for (int mt = 0; mt < 4; mt++)
#pragma unroll
        for (int nt = 0; nt < 4; nt++) {
            int row = m0 + wm * 64 + mt * 16 + r4;
            int col = nb0 + wn * 32 + nt * 8 + cp2;
            float b0 = bias[col], b1 = bias[col + 1];
#pragma unroll
            for (int h = 0; h < 2; h++) {
                int rr = row + h * 8;
                float y0 = fmaxf(acc[mt][nt][h * 2 + 0] + b0, 0.f);
                float y1 = fmaxf(acc[mt][nt][h * 2 + 1] + b1, 0.f);
                __half h0, l0, h1, l1;
                split2(y0, h0, l0);
                split2(y1, h1, l1);
                *(__half2*)(oh + (size_t)rr * 1024 + col) = __halves2half2(h0, h1);
                *(__half2*)(ol + (size_t)rr * 1024 + col) = __halves2half2(l0, l1);
            }
        }
}

// ---------------- wide expert GEMM (1-term, 128x256, 3-stage, 1 sync) -------
static constexpr int EXP_STAGE = 49152;                  // A 16KB + B 32KB
static constexpr int EXP_SMEM = 1024 + 3 * EXP_STAGE;    // ~145KB, 3 stages
static constexpr uint32_t EXP_B_OFF = 16384;

__global__ void __launch_bounds__(512, 1)
mma_exp(int ahi, int bhi,
        const float* __restrict__ bexp, const float* __restrict__ act,
        int o1, int K)
{
    extern __shared__ char smem_raw[];
    const uint32_t sb = (smem_u32(smem_raw) + 1023) & ~1023u;

    const __half* Ah = (const __half*)sp(ahi);
    const __half* Bh = (const __half*)sp(bhi);

    const int tid = threadIdx.x;
    const int lane = tid & 31;
    const int wid = tid >> 5;       // 0..15
    const int wm = wid >> 3;        // 0..1
    const int wn = wid & 7;         // 0..7 (one centroid each)
    const int m0 = blockIdx.y * 128;
    const int n0 = blockIdx.x * 256;

    float acc[4][4][4];
#pragma unroll
    for (int i = 0; i < 4; i++)
#pragma unroll
        for (int j = 0; j < 4; j++)
#pragma unroll
            for (int q = 0; q < 4; q++) acc[i][j][q] = 0.f;

    const int C = K >> 6;

    auto issue = [&](int c, int s) {
        const uint32_t st = sb + s * EXP_STAGE;
        const int k0 = c * 64;
#pragma unroll
        for (int i = tid; i < 1024; i += 512) {
            int r = i >> 3, seg = i & 7;
            uint32_t off = SWZ((uint32_t)(r * 128 + seg * 16));
            cp16(st + off, Ah + (size_t)(m0 + r) * K + k0 + seg * 8);
        }
#pragma unroll
        for (int i = tid; i < 2048; i += 512) {
            int r = i >> 3, seg = i & 7;
            uint32_t off = SWZ((uint32_t)(r * 128 + seg * 16));
            cp16(st + EXP_B_OFF + off, Bh + (size_t)(n0 + r) * K + k0 + seg * 8);
        }
        cp_commit();
    };

    const int quad = lane >> 3, qi = lane & 7;

    auto compute = [&](int s) {
        const uint32_t st = sb + s * EXP_STAGE;
#pragma unroll
        for (int kk = 0; kk < 4; kk++) {
            uint32_t ah[4][4];
#pragma unroll
            for (int mt = 0; mt < 4; mt++) {
                int row = wm * 64 + mt * 16 + (quad & 1) * 8 + qi;
                int colb = (kk * 16 + (quad >> 1) * 8) * 2;
                ldm_x4(ah[mt], st + SWZ((uint32_t)(row * 128 + colb)));
            }
            uint32_t bh[4][2];
#pragma unroll
            for (int p = 0; p < 2; p++) {
                int row = wn * 32 + p * 16 + (quad >> 1) * 8 + qi;
                int colb = (kk * 16 + (quad & 1) * 8) * 2;
                uint32_t r4[4];
                ldm_x4(r4, st + EXP_B_OFF + SWZ((uint32_t)(row * 128 + colb)));
                bh[p * 2][0] = r4[0]; bh[p * 2][1] = r4[1];
                bh[p * 2 + 1][0] = r4[2]; bh[p * 2 + 1][1] = r4[3];
            }
#pragma unroll
            for (int mt = 0; mt < 4; mt++)
#pragma unroll
                for (int nt = 0; nt < 4; nt++)
                    mma16816(acc[mt][nt], ah[mt], bh[nt]);
        }
    };

    issue(0, 0);
    issue(1, 1);
    for (int c = 0; c < C; ++c) {
        if (c + 1 < C) cp_wait1();
        else           cp_wait0();
        __syncthreads();
        compute(c % 3);
        if (c + 2 < C) issue(c + 2, (c + 2) % 3);
    }

    const int r4 = lane >> 2;
    const int cp2 = (lane & 3) * 2;
    float* dist = (float*)sp(o1);
    const int nc = blockIdx.x * 8 + wn;
#pragma unroll
    for (int mt = 0; mt < 4; mt++) {
#pragma unroll
        for (int h = 0; h < 2; h++) {
            int row = m0 + wm * 64 + mt * 16 + r4 + h * 8;
            float ss = 0.f;
#pragma unroll
            for (int nt = 0; nt < 4; nt++) {
                int col = n0 + wn * 32 + nt * 8 + cp2;
                int ai = nt * 8 + cp2;
                float z0 = acc[mt][nt][h * 2 + 0] + bexp[col];
                float z1 = acc[mt][nt][h * 2 + 1] + bexp[col + 1];
                float d0 = tanh_fast(z0) - act[(size_t)row * 32 + ai];
                float d1 = tanh_fast(z1) - act[(size_t)row * 32 + ai + 1];
                ss += d0 * d0 + d1 * d1;
            }
            ss += __shfl_xor_sync(0xffffffffu, ss, 1);
            ss += __shfl_xor_sync(0xffffffffu, ss, 2);
            if ((lane & 3) == 0)
                dist[(size_t)row * 256 + nc] = sqrtf(ss + 0.01f);
        }
    }
}

// ---------------- finalize: softmax(-dist) . values ------------------------
__global__ void finalize_kernel(float* __restrict__ out) {
    const float* dist = (const float*)sp(19);
    const float* values = (const float*)sp(18);
    const int b = blockIdx.x;
    const int n = threadIdx.x;
    const int lane = n & 31, w = n >> 5;

    float logit = -dist[(size_t)b * 256 + n];
    float v = values[(size_t)b * 256 + n];

    __shared__ float smax[8], s_e[8], s_ev[8];
    float mx = logit;
#pragma unroll
    for (int off = 16; off; off >>= 1)
        mx = fmaxf(mx, __shfl_xor_sync(0xffffffffu, mx, off));
    if (lane == 0) smax[w] = mx;
    __syncthreads();
    float bm = smax[0];
#pragma unroll
    for (int i = 1; i < 8; i++) bm = fmaxf(bm, smax[i]);

    float e = expf(logit - bm);
    float se = e, sev = e * v;
#pragma unroll
    for (int off = 16; off; off >>= 1) {
        se += __shfl_xor_sync(0xffffffffu, se, off);
        sev += __shfl_xor_sync(0xffffffffu, sev, off);
    }
    if (lane == 0) { s_e[w] = se; s_ev[w] = sev; }
    __syncthreads();
    if (n == 0) {
        float te = 0.f, tev = 0.f;
#pragma unroll
        for (int i = 0; i < 8; i++) { te += s_e[i]; tev += s_ev[i]; }
        out[b] = tev / te;
    }
}

// ---------------- launch ----------------------------------------------------
extern "C" void kernel_launch(void* const* d_in, const int* in_sizes, int n_in,
                              void* d_out, int out_size)
{
    const float* s    = (const float*)d_in[0];
    const float* act  = (const float*)d_in[1];
    const float* Wv1  = (const float*)d_in[2];
    const float* bv1  = (const float*)d_in[3];
    const float* Wv2  = (const float*)d_in[4];
    const float* bv2  = (const float*)d_in[5];
    const float* Wv3  = (const float*)d_in[6];
    const float* bv3  = (const float*)d_in[7];
    const float* Wv4  = (const float*)d_in[8];
    const float* bv4  = (const float*)d_in[9];
    const float* Wl1  = (const float*)d_in[10];
    const float* bl1  = (const float*)d_in[11];
    const float* Wexp = (const float*)d_in[12];
    const float* bexp = (const float*)d_in[13];
    float* out = (float*)d_out;

    constexpr int S3 = GemmCfg<2, 2, 2>::SMEM;   // L4: 132KB, 1 CTA/SM
    constexpr int S1 = GemmCfg<1, 1, 3>::SMEM;   // L2/L3: 97KB, 2 CTAs/SM

    cudaFuncSetAttribute(mma_gemm<1,2,2,2>, cudaFuncAttributeMaxDynamicSharedMemorySize, S3);
    cudaFuncSetAttribute(mma_gemm<0,1,1,3>, cudaFuncAttributeMaxDynamicSharedMemorySize, S1);
    cudaFuncSetAttribute(mma_dual, cudaFuncAttributeMaxDynamicSharedMemorySize, DUAL_SMEM);
    cudaFuncSetAttribute(mma_exp, cudaFuncAttributeMaxDynamicSharedMemorySize, EXP_SMEM);

    dim3 t64(64, 8);
    dim3 tw(32, 16);

    // conversions
    split_kernel<<<512, 256>>>(s, 4096 * 128, 4, 5);

    TAll ta;
    ta.W[0] = Wv1;  ta.K[0] = 128;  ta.N[0] = 1024; ta.hid[0] = 6;  ta.lid[0] = 7;  ta.base[0] = 0;   ta.nbx[0] = 16;
    ta.W[1] = Wv2;  ta.K[1] = 1024; ta.N[1] = 1024; ta.hid[1] = 8;  ta.lid[1] = -1; ta.base[1] = 32;  ta.nbx[1] = 16;
    ta.W[2] = Wv3;  ta.K[2] = 1024; ta.N[2] = 1024; ta.hid[2] = 10; ta.lid[2] = -1; ta.base[2] = 288; ta.nbx[2] = 16;
    ta.W[3] = Wv4;  ta.K[3] = 1024; ta.N[3] = 256;  ta.hid[3] = 12; ta.lid[3] = 13; ta.base[3] = 544; ta.nbx[3] = 4;
    ta.W[4] = Wl1;  ta.K[4] = 128;  ta.N[4] = 1024; ta.hid[4] = 14; ta.lid[4] = 15; ta.base[4] = 608; ta.nbx[4] = 16;
    transpose_all<<<640, t64>>>(ta);

    wexp_split64<<<dim3(16, 256), tw>>>(Wexp, 16);

    // merged L1 + location (3-term, single-buffered, 2 CTAs/SM)
    mma_dual<<<dim3(16, 32), 256, DUAL_SMEM>>>(4, 5,
                                               6, 7,  bv1, 0, 1,
                                               14, 15, bl1, 2, 3,
                                               4096, 128);

    // expert GEMM + fused tanh/dist (1-term, 3-stage pipeline)
    mma_exp<<<dim3(32, 32), 512, EXP_SMEM>>>(2, 16, bexp, act, 19, 1024);

    // L2 (1-term, 3-stage): a0 -> a1
    mma_gemm<0,1,1,3><<<dim3(8, 32), 256, S1>>>(0, 1, 8, 9,   bv2, 2, 3, 4096, 1024, 1024);
    // L3 (1-term, 3-stage): a1 -> a0
    mma_gemm<0,1,1,3><<<dim3(8, 32), 256, S1>>>(2, 3, 10, 11, bv3, 0, 1, 4096, 1024, 1024);
    // L4 (3-term, 2-stage): a0 -> values
    mma_gemm<1,2,2,2><<<dim3(2, 32), 256, S3>>>(0, 1, 12, 13, bv4, 18, 0, 4096, 256, 1024);

    finalize_kernel<<<4096, 256>>>(out);
}